// round 1
// baseline (speedup 1.0000x reference)
#include <cuda_runtime.h>
#include <cuda_bf16.h>
#include <math.h>

// ---------------- problem constants ----------------
#define BB   4
#define TT   512
#define DM   1024
#define HH   16
#define DH   64
#define FF   2048
#define EE   8
#define NTOK 2048      // BB*TT
#define EPSL 1e-5f

// ---------------- static scratch (no allocation allowed) ----------------
__device__ float g_q   [NTOK * DM];
__device__ float g_k   [NTOK * DM];
__device__ float g_v   [NTOK * DM];
__device__ float g_ctx [NTOK * DM];
__device__ float g_attn[NTOK * DM];
__device__ float g_t1  [NTOK * DM];
__device__ float g_t2  [NTOK * DM];
__device__ float g_moe [NTOK * DM];
__device__ float g_h   [(size_t)EE * NTOK * FF];   // expert hidden scratch (128 MB)
__device__ int   g_elist[EE * NTOK];
__device__ float g_egate[EE * NTOK];
__device__ int   g_ecnt [EE];
__device__ float g_imp  [EE];

// ---------------- utilities ----------------
__device__ __forceinline__ float block_reduce_sum(float v, float* red) {
    int lane = threadIdx.x & 31, w = threadIdx.x >> 5;
    #pragma unroll
    for (int o = 16; o; o >>= 1) v += __shfl_xor_sync(0xFFFFFFFFu, v, o);
    __syncthreads();            // protect red[] reuse across calls
    if (lane == 0) red[w] = v;
    __syncthreads();
    if (w == 0) {
        v = (lane < ((int)blockDim.x >> 5)) ? red[lane] : 0.0f;
        #pragma unroll
        for (int o = 16; o; o >>= 1) v += __shfl_xor_sync(0xFFFFFFFFu, v, o);
        if (lane == 0) red[0] = v;
    }
    __syncthreads();
    return red[0];
}

// ---------------- zero / init ----------------
__global__ void zero_kernel() {
    int i = blockIdx.x * blockDim.x + threadIdx.x;
    if (i < NTOK * DM) g_moe[i] = 0.0f;
    if (i < EE) { g_ecnt[i] = 0; g_imp[i] = 0.0f; }
}

// ---------------- SGEMM: C[M,Nn] = A[M,Kd] @ W[Kd,Nn] + bias ----------------
// tiles: 128x128x8, 256 threads, 8x8 per thread. M,Nn,Kd multiples of 128/8.
__global__ __launch_bounds__(256) void gemm_bias_kernel(
    const float* __restrict__ A, const float* __restrict__ W,
    const float* __restrict__ bias, float* __restrict__ C,
    int M, int Kd, int Nn)
{
    __shared__ float As[8][128];
    __shared__ float Bs[8][128];
    int tid  = threadIdx.x;
    int row0 = blockIdx.y * 128;
    int col0 = blockIdx.x * 128;
    int arow = tid >> 1,  acol = (tid & 1) * 4;
    int brow = tid >> 5,  bcol = (tid & 31) * 4;
    int tx = tid & 15, ty = tid >> 4;
    float acc[8][8] = {};

    for (int k0 = 0; k0 < Kd; k0 += 8) {
        float4 av = *(const float4*)&A[(size_t)(row0 + arow) * Kd + k0 + acol];
        As[acol + 0][arow] = av.x; As[acol + 1][arow] = av.y;
        As[acol + 2][arow] = av.z; As[acol + 3][arow] = av.w;
        *(float4*)&Bs[brow][bcol] = *(const float4*)&W[(size_t)(k0 + brow) * Nn + col0 + bcol];
        __syncthreads();
        #pragma unroll
        for (int kk = 0; kk < 8; kk++) {
            float ar[8], br[8];
            #pragma unroll
            for (int i = 0; i < 8; i++) ar[i] = As[kk][ty * 8 + i];
            #pragma unroll
            for (int j = 0; j < 8; j++) br[j] = Bs[kk][tx * 8 + j];
            #pragma unroll
            for (int i = 0; i < 8; i++)
                #pragma unroll
                for (int j = 0; j < 8; j++)
                    acc[i][j] = fmaf(ar[i], br[j], acc[i][j]);
        }
        __syncthreads();
    }
    #pragma unroll
    for (int i = 0; i < 8; i++) {
        int r = row0 + ty * 8 + i;
        #pragma unroll
        for (int j = 0; j < 8; j++) {
            int c = col0 + tx * 8 + j;
            C[(size_t)r * Nn + c] = acc[i][j] + bias[c];
        }
    }
}

// ---------------- attention: one block per (b, h, 8-query tile) ----------------
#define QT 8
__global__ __launch_bounds__(256) void attn_kernel(
    const float* __restrict__ Q, const float* __restrict__ Kk,
    const float* __restrict__ V, float* __restrict__ O)
{
    int q0 = blockIdx.x * QT;
    int h  = blockIdx.y;
    int b  = blockIdx.z;
    int tid = threadIdx.x;

    __shared__ float qs[QT][DH];
    __shared__ float s[QT][TT];
    __shared__ float red[4][QT][DH];

    for (int i = tid; i < QT * DH; i += 256) {
        int qq = i / DH, d = i % DH;
        qs[qq][d] = Q[((size_t)(b * TT + q0 + qq)) * DM + h * DH + d] * 0.125f;
    }
    __syncthreads();

    // scores
    for (int j = tid; j < TT; j += 256) {
        const float* kp = Kk + ((size_t)(b * TT + j)) * DM + h * DH;
        float acc[QT] = {};
        #pragma unroll 16
        for (int d = 0; d < DH; d++) {
            float kv = kp[d];
            #pragma unroll
            for (int qq = 0; qq < QT; qq++) acc[qq] += qs[qq][d] * kv;
        }
        #pragma unroll
        for (int qq = 0; qq < QT; qq++) s[qq][j] = acc[qq];
    }
    __syncthreads();

    // softmax: warp w owns row w
    {
        int lane = tid & 31, w = tid >> 5;
        float m = -1e30f;
        for (int j = lane; j < TT; j += 32) m = fmaxf(m, s[w][j]);
        #pragma unroll
        for (int o = 16; o; o >>= 1) m = fmaxf(m, __shfl_xor_sync(0xFFFFFFFFu, m, o));
        float sum = 0.0f;
        for (int j = lane; j < TT; j += 32) { float ev = __expf(s[w][j] - m); s[w][j] = ev; sum += ev; }
        #pragma unroll
        for (int o = 16; o; o >>= 1) sum += __shfl_xor_sync(0xFFFFFFFFu, sum, o);
        float inv = 1.0f / sum;
        for (int j = lane; j < TT; j += 32) s[w][j] *= inv;
    }
    __syncthreads();

    // output: 256 threads = 64 dims x 4 j-groups
    {
        int d = tid & 63, grp = tid >> 6;
        float acc[QT] = {};
        for (int j = grp; j < TT; j += 4) {
            float vv = V[((size_t)(b * TT + j)) * DM + h * DH + d];
            #pragma unroll
            for (int qq = 0; qq < QT; qq++) acc[qq] += s[qq][j] * vv;
        }
        #pragma unroll
        for (int qq = 0; qq < QT; qq++) red[grp][qq][d] = acc[qq];
        __syncthreads();
        if (grp == 0) {
            #pragma unroll
            for (int qq = 0; qq < QT; qq++)
                O[((size_t)(b * TT + q0 + qq)) * DM + h * DH + d] =
                    red[0][qq][d] + red[1][qq][d] + red[2][qq][d] + red[3][qq][d];
        }
    }
}

// ---------------- add + layernorm: out = LN(x + r) ----------------
__global__ __launch_bounds__(256) void add_ln_kernel(
    const float* __restrict__ x, const float* __restrict__ r,
    const float* __restrict__ g, const float* __restrict__ be,
    float* __restrict__ out)
{
    __shared__ float red[32];
    __shared__ float s_mean, s_rstd;
    int row = blockIdx.x, tid = threadIdx.x;
    const float* xp = x + (size_t)row * DM;
    const float* rp = r + (size_t)row * DM;
    float v[4]; float sum = 0.0f;
    #pragma unroll
    for (int i = 0; i < 4; i++) { int idx = tid + i * 256; v[i] = xp[idx] + rp[idx]; sum += v[i]; }
    sum = block_reduce_sum(sum, red);
    if (tid == 0) s_mean = sum * (1.0f / DM);
    __syncthreads();
    float mean = s_mean, vs = 0.0f;
    #pragma unroll
    for (int i = 0; i < 4; i++) { float dv = v[i] - mean; vs += dv * dv; }
    vs = block_reduce_sum(vs, red);
    if (tid == 0) s_rstd = rsqrtf(vs * (1.0f / DM) + EPSL);
    __syncthreads();
    float rs = s_rstd;
    #pragma unroll
    for (int i = 0; i < 4; i++) {
        int idx = tid + i * 256;
        out[(size_t)row * DM + idx] = (v[i] - mean) * rs * g[idx] + be[idx];
    }
}

// ---------------- router: softmax over E, top-2, gating, lists ----------------
__global__ __launch_bounds__(256) void router_kernel(
    const float* __restrict__ x, const float* __restrict__ rw,
    const float* __restrict__ rb)
{
    int t = blockIdx.x;
    int tid = threadIdx.x, lane = tid & 31, w = tid >> 5;
    __shared__ float logits[EE];
    const float* xp = x + (size_t)t * DM;
    float acc = 0.0f;
    for (int d = lane; d < DM; d += 32) acc += xp[d] * rw[d * EE + w];
    #pragma unroll
    for (int o = 16; o; o >>= 1) acc += __shfl_xor_sync(0xFFFFFFFFu, acc, o);
    if (lane == 0) logits[w] = acc + rb[w];
    __syncthreads();
    if (tid == 0) {
        float m = logits[0];
        #pragma unroll
        for (int e = 1; e < EE; e++) m = fmaxf(m, logits[e]);
        float p[EE], sum = 0.0f;
        #pragma unroll
        for (int e = 0; e < EE; e++) { p[e] = __expf(logits[e] - m); sum += p[e]; }
        float inv = 1.0f / sum;
        #pragma unroll
        for (int e = 0; e < EE; e++) { p[e] *= inv; atomicAdd(&g_imp[e], p[e]); }
        int i0 = 0;
        #pragma unroll
        for (int e = 1; e < EE; e++) if (p[e] > p[i0]) i0 = e;
        int i1 = (i0 == 0) ? 1 : 0;
        #pragma unroll
        for (int e = 0; e < EE; e++) if (e != i0 && p[e] > p[i1]) i1 = e;
        float g0 = p[i0], g1 = p[i1], gs = 1.0f / (g0 + g1);
        g0 *= gs; g1 *= gs;
        int pos = atomicAdd(&g_ecnt[i0], 1);
        g_elist[i0 * NTOK + pos] = t; g_egate[i0 * NTOK + pos] = g0;
        pos = atomicAdd(&g_ecnt[i1], 1);
        g_elist[i1 * NTOK + pos] = t; g_egate[i1 * NTOK + pos] = g1;
    }
}

// ---------------- MoE GEMM1: H = relu(gather(X) @ W1[e] + b1[e]) ----------------
__global__ __launch_bounds__(256) void moe_gemm1_kernel(
    const float* __restrict__ X, const float* __restrict__ w1,
    const float* __restrict__ b1)
{
    int e = blockIdx.z;
    int cnt = g_ecnt[e];
    int row0 = blockIdx.y * 128;
    if (row0 >= cnt) return;
    int col0 = blockIdx.x * 128;

    __shared__ float As[8][128];
    __shared__ float Bs[8][128];
    __shared__ int   toks[128];
    int tid = threadIdx.x;
    if (tid < 128) { int r = row0 + tid; toks[tid] = (r < cnt) ? g_elist[e * NTOK + r] : -1; }
    __syncthreads();

    const float* W = w1 + (size_t)e * DM * FF;
    int arow = tid >> 1,  acol = (tid & 1) * 4;
    int brow = tid >> 5,  bcol = (tid & 31) * 4;
    int tx = tid & 15, ty = tid >> 4;
    int atok = toks[arow];
    float acc[8][8] = {};

    for (int k0 = 0; k0 < DM; k0 += 8) {
        float4 av = make_float4(0.f, 0.f, 0.f, 0.f);
        if (atok >= 0) av = *(const float4*)&X[(size_t)atok * DM + k0 + acol];
        As[acol + 0][arow] = av.x; As[acol + 1][arow] = av.y;
        As[acol + 2][arow] = av.z; As[acol + 3][arow] = av.w;
        *(float4*)&Bs[brow][bcol] = *(const float4*)&W[(size_t)(k0 + brow) * FF + col0 + bcol];
        __syncthreads();
        #pragma unroll
        for (int kk = 0; kk < 8; kk++) {
            float ar[8], br[8];
            #pragma unroll
            for (int i = 0; i < 8; i++) ar[i] = As[kk][ty * 8 + i];
            #pragma unroll
            for (int j = 0; j < 8; j++) br[j] = Bs[kk][tx * 8 + j];
            #pragma unroll
            for (int i = 0; i < 8; i++)
                #pragma unroll
                for (int j = 0; j < 8; j++)
                    acc[i][j] = fmaf(ar[i], br[j], acc[i][j]);
        }
        __syncthreads();
    }
    #pragma unroll
    for (int i = 0; i < 8; i++) {
        int r = row0 + ty * 8 + i;
        if (r >= cnt) continue;
        float* hp = g_h + ((size_t)e * NTOK + r) * FF + col0;
        #pragma unroll
        for (int j = 0; j < 8; j++) {
            int c = tx * 8 + j;
            hp[c] = fmaxf(acc[i][j] + b1[e * FF + col0 + c], 0.0f);
        }
    }
}

// ---------------- MoE GEMM2: moe_out[tok] += gate * (H @ W2[e] + b2[e]) ----------------
__global__ __launch_bounds__(256) void moe_gemm2_kernel(
    const float* __restrict__ w2, const float* __restrict__ b2)
{
    int e = blockIdx.z;
    int cnt = g_ecnt[e];
    int row0 = blockIdx.y * 128;
    if (row0 >= cnt) return;
    int col0 = blockIdx.x * 128;

    __shared__ float As[8][128];
    __shared__ float Bs[8][128];
    int tid = threadIdx.x;
    const float* W = w2 + (size_t)e * FF * DM;
    const float* A = g_h + (size_t)e * NTOK * FF;
    int arow = tid >> 1,  acol = (tid & 1) * 4;
    int brow = tid >> 5,  bcol = (tid & 31) * 4;
    int tx = tid & 15, ty = tid >> 4;
    float acc[8][8] = {};

    for (int k0 = 0; k0 < FF; k0 += 8) {
        float4 av = make_float4(0.f, 0.f, 0.f, 0.f);
        if (row0 + arow < cnt) av = *(const float4*)&A[(size_t)(row0 + arow) * FF + k0 + acol];
        As[acol + 0][arow] = av.x; As[acol + 1][arow] = av.y;
        As[acol + 2][arow] = av.z; As[acol + 3][arow] = av.w;
        *(float4*)&Bs[brow][bcol] = *(const float4*)&W[(size_t)(k0 + brow) * DM + col0 + bcol];
        __syncthreads();
        #pragma unroll
        for (int kk = 0; kk < 8; kk++) {
            float ar[8], br[8];
            #pragma unroll
            for (int i = 0; i < 8; i++) ar[i] = As[kk][ty * 8 + i];
            #pragma unroll
            for (int j = 0; j < 8; j++) br[j] = Bs[kk][tx * 8 + j];
            #pragma unroll
            for (int i = 0; i < 8; i++)
                #pragma unroll
                for (int j = 0; j < 8; j++)
                    acc[i][j] = fmaf(ar[i], br[j], acc[i][j]);
        }
        __syncthreads();
    }
    #pragma unroll
    for (int i = 0; i < 8; i++) {
        int r = row0 + ty * 8 + i;
        if (r >= cnt) continue;
        int tok = g_elist[e * NTOK + r];
        float gate = g_egate[e * NTOK + r];
        #pragma unroll
        for (int j = 0; j < 8; j++) {
            int c = col0 + tx * 8 + j;
            atomicAdd(&g_moe[(size_t)tok * DM + c], gate * (acc[i][j] + b2[e * DM + c]));
        }
    }
}

// ---------------- load-balance loss ----------------
__global__ void lb_kernel(float* __restrict__ out) {
    float lb = 0.0f;
    #pragma unroll
    for (int e = 0; e < EE; e++)
        lb += ((float)g_ecnt[e] / (float)(NTOK * 2)) * (g_imp[e] / (float)NTOK);
    out[0] = (float)EE * lb;
}

// ---------------- host launcher ----------------
extern "C" void kernel_launch(void* const* d_in, const int* in_sizes, int n_in,
                              void* d_out, int out_size)
{
    const float* tgt = (const float*)d_in[0];
    const float* mem = (const float*)d_in[1];
    const float *sa_wq, *sa_wk, *sa_wv, *sa_wo, *ca_wq, *ca_wk, *ca_wv, *ca_wo;
    const float *sa_bq, *sa_bk, *sa_bv, *sa_bo, *ca_bq, *ca_bk, *ca_bv, *ca_bo;
    const float *ln1g, *ln1b, *ln2g, *ln2b, *ln3g, *ln3b, *rw, *rb, *w1, *b1, *w2, *b2;

    if (in_sizes[5] == DM * DM) {
        // dict insertion order: weights, then biases, then ln gammas, then ln betas
        sa_wq = (const float*)d_in[2];  sa_wk = (const float*)d_in[3];
        sa_wv = (const float*)d_in[4];  sa_wo = (const float*)d_in[5];
        ca_wq = (const float*)d_in[6];  ca_wk = (const float*)d_in[7];
        ca_wv = (const float*)d_in[8];  ca_wo = (const float*)d_in[9];
        sa_bq = (const float*)d_in[10]; sa_bk = (const float*)d_in[11];
        sa_bv = (const float*)d_in[12]; sa_bo = (const float*)d_in[13];
        ca_bq = (const float*)d_in[14]; ca_bk = (const float*)d_in[15];
        ca_bv = (const float*)d_in[16]; ca_bo = (const float*)d_in[17];
        ln1g = (const float*)d_in[18]; ln2g = (const float*)d_in[19]; ln3g = (const float*)d_in[20];
        ln1b = (const float*)d_in[21]; ln2b = (const float*)d_in[22]; ln3b = (const float*)d_in[23];
    } else {
        // reference signature order
        sa_wq = (const float*)d_in[2];  sa_wk = (const float*)d_in[3];
        sa_wv = (const float*)d_in[4];
        sa_bq = (const float*)d_in[5];  sa_bk = (const float*)d_in[6];
        sa_bv = (const float*)d_in[7];
        sa_wo = (const float*)d_in[8];  sa_bo = (const float*)d_in[9];
        ca_wq = (const float*)d_in[10]; ca_wk = (const float*)d_in[11];
        ca_wv = (const float*)d_in[12];
        ca_bq = (const float*)d_in[13]; ca_bk = (const float*)d_in[14];
        ca_bv = (const float*)d_in[15];
        ca_wo = (const float*)d_in[16]; ca_bo = (const float*)d_in[17];
        ln1g = (const float*)d_in[18]; ln1b = (const float*)d_in[19];
        ln2g = (const float*)d_in[20]; ln2b = (const float*)d_in[21];
        ln3g = (const float*)d_in[22]; ln3b = (const float*)d_in[23];
    }
    rw = (const float*)d_in[24]; rb = (const float*)d_in[25];
    w1 = (const float*)d_in[26]; b1 = (const float*)d_in[27];
    w2 = (const float*)d_in[28]; b2 = (const float*)d_in[29];

    float* q; float* k; float* v; float* ctx; float* attn;
    float* t1; float* t2; float* moe_o;
    cudaGetSymbolAddress((void**)&q,    g_q);
    cudaGetSymbolAddress((void**)&k,    g_k);
    cudaGetSymbolAddress((void**)&v,    g_v);
    cudaGetSymbolAddress((void**)&ctx,  g_ctx);
    cudaGetSymbolAddress((void**)&attn, g_attn);
    cudaGetSymbolAddress((void**)&t1,   g_t1);
    cudaGetSymbolAddress((void**)&t2,   g_t2);
    cudaGetSymbolAddress((void**)&moe_o, g_moe);

    float* out = (float*)d_out;

    dim3 gProj(DM / 128, NTOK / 128);     // (8, 16)
    dim3 gAttn(TT / QT, HH, BB);          // (64, 16, 4)
    dim3 gMoe1(FF / 128, NTOK / 128, EE); // (16, 16, 8)
    dim3 gMoe2(DM / 128, NTOK / 128, EE); // (8, 16, 8)

    zero_kernel<<<(NTOK * DM + 255) / 256, 256>>>();

    // ---- self attention ----
    gemm_bias_kernel<<<gProj, 256>>>(tgt, sa_wq, sa_bq, q, NTOK, DM, DM);
    gemm_bias_kernel<<<gProj, 256>>>(tgt, sa_wk, sa_bk, k, NTOK, DM, DM);
    gemm_bias_kernel<<<gProj, 256>>>(tgt, sa_wv, sa_bv, v, NTOK, DM, DM);
    attn_kernel<<<gAttn, 256>>>(q, k, v, ctx);
    gemm_bias_kernel<<<gProj, 256>>>(ctx, sa_wo, sa_bo, attn, NTOK, DM, DM);
    add_ln_kernel<<<NTOK, 256>>>(attn, tgt, ln1g, ln1b, t1);

    // ---- cross attention ----
    gemm_bias_kernel<<<gProj, 256>>>(t1,  ca_wq, ca_bq, q, NTOK, DM, DM);
    gemm_bias_kernel<<<gProj, 256>>>(mem, ca_wk, ca_bk, k, NTOK, DM, DM);
    gemm_bias_kernel<<<gProj, 256>>>(mem, ca_wv, ca_bv, v, NTOK, DM, DM);
    attn_kernel<<<gAttn, 256>>>(q, k, v, ctx);
    gemm_bias_kernel<<<gProj, 256>>>(ctx, ca_wo, ca_bo, attn, NTOK, DM, DM);
    add_ln_kernel<<<NTOK, 256>>>(attn, t1, ln2g, ln2b, t2);

    // ---- MoE (sparse top-2 evaluation) ----
    router_kernel<<<NTOK, 256>>>(t2, rw, rb);
    moe_gemm1_kernel<<<gMoe1, 256>>>(t2, w1, b1);
    moe_gemm2_kernel<<<gMoe2, 256>>>(w2, b2);
    add_ln_kernel<<<NTOK, 256>>>(moe_o, t2, ln3g, ln3b, out);

    if (out_size > NTOK * DM)
        lb_kernel<<<1, 1>>>(out + (size_t)NTOK * DM);
}

// round 2
// speedup vs baseline: 1.8087x; 1.8087x over previous
#include <cuda_runtime.h>
#include <cuda_bf16.h>
#include <math.h>
#include <stdint.h>

// ---------------- problem constants ----------------
#define BB   4
#define TT   512
#define DM   1024
#define HH   16
#define DH   64
#define FF   2048
#define EE   8
#define NTOK 2048      // BB*TT
#define EPSL 1e-5f

// GEMM tiling
#define BM 128
#define BN 128
#define BKT 16
#define AS_STRIDE 20     // 16 + 4 pad (conflict-free frag loads)
#define BS_STRIDE 136    // 128 + 8 pad

// ---------------- static scratch ----------------
__device__ float g_q   [NTOK * DM];
__device__ float g_k   [NTOK * DM];
__device__ float g_v   [NTOK * DM];
__device__ float g_ctx [NTOK * DM];
__device__ float g_attn[NTOK * DM];
__device__ float g_t1  [NTOK * DM];
__device__ float g_t2  [NTOK * DM];
__device__ float g_moe [NTOK * DM];
__device__ float g_h   [(size_t)EE * NTOK * FF];
__device__ int   g_elist[EE * NTOK];
__device__ float g_egate[EE * NTOK];
__device__ int   g_ecnt [EE];
__device__ float g_imp  [EE];

// ---------------- helpers ----------------
__device__ __forceinline__ uint32_t f2tf(float f) {
    uint32_t u;
    asm("cvt.rna.tf32.f32 %0, %1;" : "=r"(u) : "f"(f));
    return u;
}

__device__ __forceinline__ void mma8(float* c, const uint32_t* a, const uint32_t* b) {
    asm volatile(
        "mma.sync.aligned.m16n8k8.row.col.f32.tf32.tf32.f32 "
        "{%0,%1,%2,%3}, {%4,%5,%6,%7}, {%8,%9}, {%0,%1,%2,%3};\n"
        : "+f"(c[0]), "+f"(c[1]), "+f"(c[2]), "+f"(c[3])
        : "r"(a[0]), "r"(a[1]), "r"(a[2]), "r"(a[3]), "r"(b[0]), "r"(b[1]));
}

__device__ __forceinline__ float block_reduce_sum(float v, float* red) {
    int lane = threadIdx.x & 31, w = threadIdx.x >> 5;
    #pragma unroll
    for (int o = 16; o; o >>= 1) v += __shfl_xor_sync(0xFFFFFFFFu, v, o);
    __syncthreads();
    if (lane == 0) red[w] = v;
    __syncthreads();
    if (w == 0) {
        v = (lane < ((int)blockDim.x >> 5)) ? red[lane] : 0.0f;
        #pragma unroll
        for (int o = 16; o; o >>= 1) v += __shfl_xor_sync(0xFFFFFFFFu, v, o);
        if (lane == 0) red[0] = v;
    }
    __syncthreads();
    return red[0];
}

// ---------------- zero / init ----------------
__global__ void zero_kernel() {
    int i = blockIdx.x * blockDim.x + threadIdx.x;
    if (i < NTOK * DM) g_moe[i] = 0.0f;
    if (i < EE) { g_ecnt[i] = 0; g_imp[i] = 0.0f; }
}

// ================= tf32 MMA GEMM core =================
// MODE 0: C[atoks[lr]][c] = acc + bias[c]                 (proj)
// MODE 1: if atoks[lr]>=0: C[row0+lr][c] = relu(acc+b)    (moe gemm1, gather A via atoks)
// MODE 2: if otoks[lr]>=0: atomicAdd(C[otoks[lr]][c], gate*(acc+b))  (moe gemm2)
template<int MODE>
__device__ __forceinline__ void gemm_core(
    const float* __restrict__ A, const float* __restrict__ W,
    const float* __restrict__ bias, float* __restrict__ C,
    int K, int N, int row0, int col0,
    const int* atoks, const int* otoks, const float* gates)
{
    __shared__ uint32_t As[2][BM * AS_STRIDE];
    __shared__ uint32_t Bs[2][BKT * BS_STRIDE];

    const int tid = threadIdx.x;
    const int lane = tid & 31;
    const int wid  = tid >> 5;
    const int wm = wid >> 2;          // 0..1
    const int wn = wid & 3;           // 0..3
    const int g   = lane >> 2;        // 0..7
    const int tig = lane & 3;         // 0..3

    // A loader: rows lr0, lr0+64 ; 4 consecutive k per thread
    const int lr0 = tid >> 2;
    const int akq = (tid & 3) * 4;
    const int t0 = atoks[lr0];
    const int t1 = atoks[lr0 + 64];
    const float* a0p = (t0 >= 0) ? (A + (size_t)t0 * K + akq) : nullptr;
    const float* a1p = (t1 >= 0) ? (A + (size_t)t1 * K + akq) : nullptr;

    // B loader: row kr, 8 consecutive n per thread
    const int kr = tid >> 4;          // 0..15
    const int nq = (tid & 15) * 8;
    const float* bp = W + (size_t)kr * N + col0 + nq;

    const int nk = K / BKT;
    float4 ra0, ra1, rb0, rb1;
    const float4 z4 = make_float4(0.f, 0.f, 0.f, 0.f);

    // prologue: load tile 0
    ra0 = a0p ? *(const float4*)(a0p) : z4;
    ra1 = a1p ? *(const float4*)(a1p) : z4;
    rb0 = *(const float4*)(bp);
    rb1 = *(const float4*)(bp + 4);

    {
        uint4 u0 = make_uint4(f2tf(ra0.x), f2tf(ra0.y), f2tf(ra0.z), f2tf(ra0.w));
        uint4 u1 = make_uint4(f2tf(ra1.x), f2tf(ra1.y), f2tf(ra1.z), f2tf(ra1.w));
        *(uint4*)&As[0][lr0 * AS_STRIDE + akq]        = u0;
        *(uint4*)&As[0][(lr0 + 64) * AS_STRIDE + akq] = u1;
        uint4 v0 = make_uint4(f2tf(rb0.x), f2tf(rb0.y), f2tf(rb0.z), f2tf(rb0.w));
        uint4 v1 = make_uint4(f2tf(rb1.x), f2tf(rb1.y), f2tf(rb1.z), f2tf(rb1.w));
        *(uint4*)&Bs[0][kr * BS_STRIDE + nq]     = v0;
        *(uint4*)&Bs[0][kr * BS_STRIDE + nq + 4] = v1;
    }
    __syncthreads();

    float acc[4][4][4];
    #pragma unroll
    for (int i = 0; i < 4; i++)
        #pragma unroll
        for (int j = 0; j < 4; j++)
            #pragma unroll
            for (int r = 0; r < 4; r++) acc[i][j][r] = 0.0f;

    int buf = 0;
    for (int kt = 0; kt < nk; kt++) {
        const bool more = (kt + 1 < nk);
        if (more) {
            const int k0 = (kt + 1) * BKT;
            ra0 = a0p ? *(const float4*)(a0p + k0) : z4;
            ra1 = a1p ? *(const float4*)(a1p + k0) : z4;
            rb0 = *(const float4*)(bp + (size_t)k0 * N);
            rb1 = *(const float4*)(bp + (size_t)k0 * N + 4);
        }

        // compute current buffer
        #pragma unroll
        for (int k8 = 0; k8 < 2; k8++) {
            uint32_t af[4][4], bf[4][2];
            const uint32_t* abase = &As[buf][(wm * 64 + g) * AS_STRIDE + k8 * 8 + tig];
            #pragma unroll
            for (int mt = 0; mt < 4; mt++) {
                const uint32_t* p = abase + mt * 16 * AS_STRIDE;
                af[mt][0] = p[0];
                af[mt][1] = p[8 * AS_STRIDE];
                af[mt][2] = p[4];
                af[mt][3] = p[8 * AS_STRIDE + 4];
            }
            const uint32_t* bbase = &Bs[buf][(k8 * 8 + tig) * BS_STRIDE + wn * 32 + g];
            #pragma unroll
            for (int nt = 0; nt < 4; nt++) {
                bf[nt][0] = bbase[nt * 8];
                bf[nt][1] = bbase[4 * BS_STRIDE + nt * 8];
            }
            #pragma unroll
            for (int mt = 0; mt < 4; mt++)
                #pragma unroll
                for (int nt = 0; nt < 4; nt++)
                    mma8(acc[mt][nt], af[mt], bf[nt]);
        }

        if (more) {
            const int nb = buf ^ 1;
            uint4 u0 = make_uint4(f2tf(ra0.x), f2tf(ra0.y), f2tf(ra0.z), f2tf(ra0.w));
            uint4 u1 = make_uint4(f2tf(ra1.x), f2tf(ra1.y), f2tf(ra1.z), f2tf(ra1.w));
            *(uint4*)&As[nb][lr0 * AS_STRIDE + akq]        = u0;
            *(uint4*)&As[nb][(lr0 + 64) * AS_STRIDE + akq] = u1;
            uint4 v0 = make_uint4(f2tf(rb0.x), f2tf(rb0.y), f2tf(rb0.z), f2tf(rb0.w));
            uint4 v1 = make_uint4(f2tf(rb1.x), f2tf(rb1.y), f2tf(rb1.z), f2tf(rb1.w));
            *(uint4*)&Bs[nb][kr * BS_STRIDE + nq]     = v0;
            *(uint4*)&Bs[nb][kr * BS_STRIDE + nq + 4] = v1;
            __syncthreads();
            buf = nb;
        }
    }

    // epilogue
    #pragma unroll
    for (int mt = 0; mt < 4; mt++) {
        const int lr = wm * 64 + mt * 16 + g;   // local rows lr, lr+8
        #pragma unroll
        for (int nt = 0; nt < 4; nt++) {
            float* ac = acc[mt][nt];
            const int c = col0 + wn * 32 + nt * 8 + 2 * tig;
            const float bc0 = bias[c], bc1 = bias[c + 1];
            if (MODE == 0) {
                const int r0 = atoks[lr], r1 = atoks[lr + 8];
                *(float2*)&C[(size_t)r0 * N + c] = make_float2(ac[0] + bc0, ac[1] + bc1);
                *(float2*)&C[(size_t)r1 * N + c] = make_float2(ac[2] + bc0, ac[3] + bc1);
            } else if (MODE == 1) {
                if (atoks[lr] >= 0)
                    *(float2*)&C[(size_t)(row0 + lr) * N + c] =
                        make_float2(fmaxf(ac[0] + bc0, 0.f), fmaxf(ac[1] + bc1, 0.f));
                if (atoks[lr + 8] >= 0)
                    *(float2*)&C[(size_t)(row0 + lr + 8) * N + c] =
                        make_float2(fmaxf(ac[2] + bc0, 0.f), fmaxf(ac[3] + bc1, 0.f));
            } else {
                int tk = otoks[lr]; float gt = gates[lr];
                if (tk >= 0) {
                    atomicAdd(&C[(size_t)tk * N + c],     gt * (ac[0] + bc0));
                    atomicAdd(&C[(size_t)tk * N + c + 1], gt * (ac[1] + bc1));
                }
                tk = otoks[lr + 8]; gt = gates[lr + 8];
                if (tk >= 0) {
                    atomicAdd(&C[(size_t)tk * N + c],     gt * (ac[2] + bc0));
                    atomicAdd(&C[(size_t)tk * N + c + 1], gt * (ac[3] + bc1));
                }
            }
        }
    }
}

// ---------------- GEMM wrappers ----------------
__global__ __launch_bounds__(256) void proj_qkv_kernel(
    const float* A0, const float* A1, const float* A2,
    const float* W0, const float* W1, const float* W2,
    const float* b0, const float* b1, const float* b2,
    float* C0, float* C1, float* C2, int K, int N)
{
    __shared__ int toks[BM];
    const int z = blockIdx.z;
    const float* A = (z == 0) ? A0 : (z == 1) ? A1 : A2;
    const float* W = (z == 0) ? W0 : (z == 1) ? W1 : W2;
    const float* b = (z == 0) ? b0 : (z == 1) ? b1 : b2;
    float*       C = (z == 0) ? C0 : (z == 1) ? C1 : C2;
    const int row0 = blockIdx.y * BM, col0 = blockIdx.x * BN;
    if (threadIdx.x < BM) toks[threadIdx.x] = row0 + threadIdx.x;
    __syncthreads();
    gemm_core<0>(A, W, b, C, K, N, row0, col0, toks, nullptr, nullptr);
}

__global__ __launch_bounds__(256) void moe1_kernel(
    const float* __restrict__ X, const float* __restrict__ w1,
    const float* __restrict__ b1)
{
    const int e = blockIdx.z;
    const int cnt = g_ecnt[e];
    const int row0 = blockIdx.y * BM;
    if (row0 >= cnt) return;
    const int col0 = blockIdx.x * BN;
    __shared__ int toks[BM];
    if (threadIdx.x < BM) {
        int r = row0 + threadIdx.x;
        toks[threadIdx.x] = (r < cnt) ? g_elist[e * NTOK + r] : -1;
    }
    __syncthreads();
    gemm_core<1>(X, w1 + (size_t)e * DM * FF, b1 + e * FF,
                 g_h + (size_t)e * NTOK * FF,
                 DM, FF, row0, col0, toks, nullptr, nullptr);
}

__global__ __launch_bounds__(256) void moe2_kernel(
    const float* __restrict__ w2, const float* __restrict__ b2)
{
    const int e = blockIdx.z;
    const int cnt = g_ecnt[e];
    const int row0 = blockIdx.y * BM;
    if (row0 >= cnt) return;
    const int col0 = blockIdx.x * BN;
    __shared__ int atoks[BM];
    __shared__ int otoks[BM];
    __shared__ float gat[BM];
    if (threadIdx.x < BM) {
        int r = row0 + threadIdx.x;
        bool ok = (r < cnt);
        atoks[threadIdx.x] = ok ? r : -1;
        otoks[threadIdx.x] = ok ? g_elist[e * NTOK + r] : -1;
        gat[threadIdx.x]   = ok ? g_egate[e * NTOK + r] : 0.0f;
    }
    __syncthreads();
    gemm_core<2>(g_h + (size_t)e * NTOK * FF, w2 + (size_t)e * FF * DM,
                 b2 + e * DM, g_moe,
                 FF, DM, row0, col0, atoks, otoks, gat);
}

// ---------------- attention ----------------
#define QT 8
__global__ __launch_bounds__(256) void attn_kernel(
    const float* __restrict__ Q, const float* __restrict__ Kk,
    const float* __restrict__ V, float* __restrict__ O)
{
    int q0 = blockIdx.x * QT;
    int h  = blockIdx.y;
    int b  = blockIdx.z;
    int tid = threadIdx.x;

    __shared__ float qs[QT][DH];
    __shared__ float s[QT][TT];
    __shared__ float red[4][QT][DH];

    for (int i = tid; i < QT * DH; i += 256) {
        int qq = i / DH, d = i % DH;
        qs[qq][d] = Q[((size_t)(b * TT + q0 + qq)) * DM + h * DH + d] * 0.125f;
    }
    __syncthreads();

    for (int j = tid; j < TT; j += 256) {
        const float* kp = Kk + ((size_t)(b * TT + j)) * DM + h * DH;
        float acc[QT] = {};
        #pragma unroll 16
        for (int d = 0; d < DH; d++) {
            float kv = kp[d];
            #pragma unroll
            for (int qq = 0; qq < QT; qq++) acc[qq] += qs[qq][d] * kv;
        }
        #pragma unroll
        for (int qq = 0; qq < QT; qq++) s[qq][j] = acc[qq];
    }
    __syncthreads();

    {
        int lane = tid & 31, w = tid >> 5;
        float m = -1e30f;
        for (int j = lane; j < TT; j += 32) m = fmaxf(m, s[w][j]);
        #pragma unroll
        for (int o = 16; o; o >>= 1) m = fmaxf(m, __shfl_xor_sync(0xFFFFFFFFu, m, o));
        float sum = 0.0f;
        for (int j = lane; j < TT; j += 32) { float ev = __expf(s[w][j] - m); s[w][j] = ev; sum += ev; }
        #pragma unroll
        for (int o = 16; o; o >>= 1) sum += __shfl_xor_sync(0xFFFFFFFFu, sum, o);
        float inv = 1.0f / sum;
        for (int j = lane; j < TT; j += 32) s[w][j] *= inv;
    }
    __syncthreads();

    {
        int d = tid & 63, grp = tid >> 6;
        float acc[QT] = {};
        for (int j = grp; j < TT; j += 4) {
            float vv = V[((size_t)(b * TT + j)) * DM + h * DH + d];
            #pragma unroll
            for (int qq = 0; qq < QT; qq++) acc[qq] += s[qq][j] * vv;
        }
        #pragma unroll
        for (int qq = 0; qq < QT; qq++) red[grp][qq][d] = acc[qq];
        __syncthreads();
        if (grp == 0) {
            #pragma unroll
            for (int qq = 0; qq < QT; qq++)
                O[((size_t)(b * TT + q0 + qq)) * DM + h * DH + d] =
                    red[0][qq][d] + red[1][qq][d] + red[2][qq][d] + red[3][qq][d];
        }
    }
}

// ---------------- add + layernorm ----------------
__global__ __launch_bounds__(256) void add_ln_kernel(
    const float* __restrict__ x, const float* __restrict__ r,
    const float* __restrict__ g, const float* __restrict__ be,
    float* __restrict__ out)
{
    __shared__ float red[32];
    __shared__ float s_mean, s_rstd;
    int row = blockIdx.x, tid = threadIdx.x;
    const float* xp = x + (size_t)row * DM;
    const float* rp = r + (size_t)row * DM;
    float v[4]; float sum = 0.0f;
    #pragma unroll
    for (int i = 0; i < 4; i++) { int idx = tid + i * 256; v[i] = xp[idx] + rp[idx]; sum += v[i]; }
    sum = block_reduce_sum(sum, red);
    if (tid == 0) s_mean = sum * (1.0f / DM);
    __syncthreads();
    float mean = s_mean, vs = 0.0f;
    #pragma unroll
    for (int i = 0; i < 4; i++) { float dv = v[i] - mean; vs += dv * dv; }
    vs = block_reduce_sum(vs, red);
    if (tid == 0) s_rstd = rsqrtf(vs * (1.0f / DM) + EPSL);
    __syncthreads();
    float rs = s_rstd;
    #pragma unroll
    for (int i = 0; i < 4; i++) {
        int idx = tid + i * 256;
        out[(size_t)row * DM + idx] = (v[i] - mean) * rs * g[idx] + be[idx];
    }
}

// ---------------- router ----------------
__global__ __launch_bounds__(256) void router_kernel(
    const float* __restrict__ x, const float* __restrict__ rw,
    const float* __restrict__ rb)
{
    int t = blockIdx.x;
    int tid = threadIdx.x, lane = tid & 31, w = tid >> 5;
    __shared__ float logits[EE];
    const float* xp = x + (size_t)t * DM;
    float acc = 0.0f;
    for (int d = lane; d < DM; d += 32) acc += xp[d] * rw[d * EE + w];
    #pragma unroll
    for (int o = 16; o; o >>= 1) acc += __shfl_xor_sync(0xFFFFFFFFu, acc, o);
    if (lane == 0) logits[w] = acc + rb[w];
    __syncthreads();
    if (tid == 0) {
        float m = logits[0];
        #pragma unroll
        for (int e = 1; e < EE; e++) m = fmaxf(m, logits[e]);
        float p[EE], sum = 0.0f;
        #pragma unroll
        for (int e = 0; e < EE; e++) { p[e] = __expf(logits[e] - m); sum += p[e]; }
        float inv = 1.0f / sum;
        #pragma unroll
        for (int e = 0; e < EE; e++) { p[e] *= inv; atomicAdd(&g_imp[e], p[e]); }
        int i0 = 0;
        #pragma unroll
        for (int e = 1; e < EE; e++) if (p[e] > p[i0]) i0 = e;
        int i1 = (i0 == 0) ? 1 : 0;
        #pragma unroll
        for (int e = 0; e < EE; e++) if (e != i0 && p[e] > p[i1]) i1 = e;
        float g0 = p[i0], g1 = p[i1], gs = 1.0f / (g0 + g1);
        g0 *= gs; g1 *= gs;
        int pos = atomicAdd(&g_ecnt[i0], 1);
        g_elist[i0 * NTOK + pos] = t; g_egate[i0 * NTOK + pos] = g0;
        pos = atomicAdd(&g_ecnt[i1], 1);
        g_elist[i1 * NTOK + pos] = t; g_egate[i1 * NTOK + pos] = g1;
    }
}

// ---------------- load-balance loss ----------------
__global__ void lb_kernel(float* __restrict__ out) {
    float lb = 0.0f;
    #pragma unroll
    for (int e = 0; e < EE; e++)
        lb += ((float)g_ecnt[e] / (float)(NTOK * 2)) * (g_imp[e] / (float)NTOK);
    out[0] = (float)EE * lb;
}

// ---------------- host launcher ----------------
extern "C" void kernel_launch(void* const* d_in, const int* in_sizes, int n_in,
                              void* d_out, int out_size)
{
    const float* tgt = (const float*)d_in[0];
    const float* mem = (const float*)d_in[1];
    const float *sa_wq, *sa_wk, *sa_wv, *sa_wo, *ca_wq, *ca_wk, *ca_wv, *ca_wo;
    const float *sa_bq, *sa_bk, *sa_bv, *sa_bo, *ca_bq, *ca_bk, *ca_bv, *ca_bo;
    const float *ln1g, *ln1b, *ln2g, *ln2b, *ln3g, *ln3b, *rw, *rb, *w1, *b1, *w2, *b2;

    if (in_sizes[5] == DM * DM) {
        sa_wq = (const float*)d_in[2];  sa_wk = (const float*)d_in[3];
        sa_wv = (const float*)d_in[4];  sa_wo = (const float*)d_in[5];
        ca_wq = (const float*)d_in[6];  ca_wk = (const float*)d_in[7];
        ca_wv = (const float*)d_in[8];  ca_wo = (const float*)d_in[9];
        sa_bq = (const float*)d_in[10]; sa_bk = (const float*)d_in[11];
        sa_bv = (const float*)d_in[12]; sa_bo = (const float*)d_in[13];
        ca_bq = (const float*)d_in[14]; ca_bk = (const float*)d_in[15];
        ca_bv = (const float*)d_in[16]; ca_bo = (const float*)d_in[17];
        ln1g = (const float*)d_in[18]; ln2g = (const float*)d_in[19]; ln3g = (const float*)d_in[20];
        ln1b = (const float*)d_in[21]; ln2b = (const float*)d_in[22]; ln3b = (const float*)d_in[23];
    } else {
        sa_wq = (const float*)d_in[2];  sa_wk = (const float*)d_in[3];
        sa_wv = (const float*)d_in[4];
        sa_bq = (const float*)d_in[5];  sa_bk = (const float*)d_in[6];
        sa_bv = (const float*)d_in[7];
        sa_wo = (const float*)d_in[8];  sa_bo = (const float*)d_in[9];
        ca_wq = (const float*)d_in[10]; ca_wk = (const float*)d_in[11];
        ca_wv = (const float*)d_in[12];
        ca_bq = (const float*)d_in[13]; ca_bk = (const float*)d_in[14];
        ca_bv = (const float*)d_in[15];
        ca_wo = (const float*)d_in[16]; ca_bo = (const float*)d_in[17];
        ln1g = (const float*)d_in[18]; ln1b = (const float*)d_in[19];
        ln2g = (const float*)d_in[20]; ln2b = (const float*)d_in[21];
        ln3g = (const float*)d_in[22]; ln3b = (const float*)d_in[23];
    }
    rw = (const float*)d_in[24]; rb = (const float*)d_in[25];
    w1 = (const float*)d_in[26]; b1 = (const float*)d_in[27];
    w2 = (const float*)d_in[28]; b2 = (const float*)d_in[29];

    float *q, *k, *v, *ctx, *attn, *t1, *t2, *moe_o;
    cudaGetSymbolAddress((void**)&q,    g_q);
    cudaGetSymbolAddress((void**)&k,    g_k);
    cudaGetSymbolAddress((void**)&v,    g_v);
    cudaGetSymbolAddress((void**)&ctx,  g_ctx);
    cudaGetSymbolAddress((void**)&attn, g_attn);
    cudaGetSymbolAddress((void**)&t1,   g_t1);
    cudaGetSymbolAddress((void**)&t2,   g_t2);
    cudaGetSymbolAddress((void**)&moe_o, g_moe);

    float* out = (float*)d_out;

    dim3 gQKV(DM / BN, NTOK / BM, 3);      // (8, 16, 3)
    dim3 gO  (DM / BN, NTOK / BM, 1);      // (8, 16, 1)
    dim3 gAttn(TT / QT, HH, BB);           // (64, 16, 4)
    dim3 gMoe1(FF / BN, NTOK / BM, EE);    // (16, 16, 8)
    dim3 gMoe2(DM / BN, NTOK / BM, EE);    // (8, 16, 8)

    zero_kernel<<<(NTOK * DM + 255) / 256, 256>>>();

    // ---- self attention ----
    proj_qkv_kernel<<<gQKV, 256>>>(tgt, tgt, tgt, sa_wq, sa_wk, sa_wv,
                                   sa_bq, sa_bk, sa_bv, q, k, v, DM, DM);
    attn_kernel<<<gAttn, 256>>>(q, k, v, ctx);
    proj_qkv_kernel<<<gO, 256>>>(ctx, ctx, ctx, sa_wo, sa_wo, sa_wo,
                                 sa_bo, sa_bo, sa_bo, attn, attn, attn, DM, DM);
    add_ln_kernel<<<NTOK, 256>>>(attn, tgt, ln1g, ln1b, t1);

    // ---- cross attention ----
    proj_qkv_kernel<<<gQKV, 256>>>(t1, mem, mem, ca_wq, ca_wk, ca_wv,
                                   ca_bq, ca_bk, ca_bv, q, k, v, DM, DM);
    attn_kernel<<<gAttn, 256>>>(q, k, v, ctx);
    proj_qkv_kernel<<<gO, 256>>>(ctx, ctx, ctx, ca_wo, ca_wo, ca_wo,
                                 ca_bo, ca_bo, ca_bo, attn, attn, attn, DM, DM);
    add_ln_kernel<<<NTOK, 256>>>(attn, t1, ln2g, ln2b, t2);

    // ---- MoE (sparse top-2) ----
    router_kernel<<<NTOK, 256>>>(t2, rw, rb);
    moe1_kernel<<<gMoe1, 256>>>(t2, w1, b1);
    moe2_kernel<<<gMoe2, 256>>>(w2, b2);
    add_ln_kernel<<<NTOK, 256>>>(moe_o, t2, ln3g, ln3b, out);

    if (out_size > NTOK * DM)
        lb_kernel<<<1, 1>>>(out + (size_t)NTOK * DM);
}

// round 3
// speedup vs baseline: 2.4042x; 1.3293x over previous
#include <cuda_runtime.h>
#include <cuda_bf16.h>
#include <math.h>
#include <stdint.h>

// ---------------- problem constants ----------------
#define BB   4
#define TT   512
#define DM   1024
#define HH   16
#define DH   64
#define FF   2048
#define EE   8
#define NTOK 2048
#define EPSL 1e-5f

// GEMM tiling
#define BM 128
#define BN 128
#define BKT 16
#define AS_STRIDE 20     // conflict-free fragment loads (verified)
#define BS_STRIDE 136
#define NSTAGE 3
#define A_ELEMS (BM * AS_STRIDE)    // 2560
#define B_ELEMS (BKT * BS_STRIDE)   // 2176
#define GEMM_SMEM (NSTAGE * (A_ELEMS + B_ELEMS) * 4)   // 56832 B

// pre-converted (tf32-rounded) constant pool layout, units of floats
#define PQ 1048576ull
#define WT_TOTAL (44ull * PQ)

// ---------------- static scratch ----------------
__device__ float g_wt  [WT_TOTAL];          // rounded weights + tgt + mem
__device__ float g_q   [NTOK * DM];
__device__ float g_k   [NTOK * DM];
__device__ float g_v   [NTOK * DM];
__device__ float g_ctx [NTOK * DM];         // written tf32-rounded by attn
__device__ float g_attn[NTOK * DM];
__device__ float g_t1  [NTOK * DM];
__device__ float g_t1t [NTOK * DM];
__device__ float g_t2  [NTOK * DM];
__device__ float g_t2t [NTOK * DM];
__device__ float g_ys  [NTOK * 2 * DM];     // per-slot expert outputs
__device__ float g_h   [(size_t)EE * NTOK * FF];  // rounded by moe1 epilogue
__device__ int   g_elist[EE * NTOK];
__device__ int   g_slot [EE * NTOK];
__device__ float g_egate[EE * NTOK];
__device__ int   g_ecnt [EE];
__device__ float g_imp  [EE];

// ---------------- helpers ----------------
__device__ __forceinline__ uint32_t f2tf(float f) {
    uint32_t u;
    asm("cvt.rna.tf32.f32 %0, %1;" : "=r"(u) : "f"(f));
    return u;
}
__device__ __forceinline__ float tfr(float f) { return __uint_as_float(f2tf(f)); }

__device__ __forceinline__ void mma8(float* c, const uint32_t* a, const uint32_t* b) {
    asm volatile(
        "mma.sync.aligned.m16n8k8.row.col.f32.tf32.tf32.f32 "
        "{%0,%1,%2,%3}, {%4,%5,%6,%7}, {%8,%9}, {%0,%1,%2,%3};\n"
        : "+f"(c[0]), "+f"(c[1]), "+f"(c[2]), "+f"(c[3])
        : "r"(a[0]), "r"(a[1]), "r"(a[2]), "r"(a[3]), "r"(b[0]), "r"(b[1]));
}

__device__ __forceinline__ uint32_t smem_u32(const void* p) {
    return (uint32_t)__cvta_generic_to_shared(p);
}
__device__ __forceinline__ void cp16(uint32_t dst, const void* src, bool pred) {
    int sz = pred ? 16 : 0;
    asm volatile("cp.async.cg.shared.global [%0], [%1], 16, %2;\n"
                 :: "r"(dst), "l"(src), "r"(sz) : "memory");
}
#define CP_COMMIT  asm volatile("cp.async.commit_group;\n" ::: "memory")
#define CP_WAIT1   asm volatile("cp.async.wait_group 1;\n" ::: "memory")

__device__ __forceinline__ float block_reduce_sum(float v, float* red) {
    int lane = threadIdx.x & 31, w = threadIdx.x >> 5;
    #pragma unroll
    for (int o = 16; o; o >>= 1) v += __shfl_xor_sync(0xFFFFFFFFu, v, o);
    __syncthreads();
    if (lane == 0) red[w] = v;
    __syncthreads();
    if (w == 0) {
        v = (lane < ((int)blockDim.x >> 5)) ? red[lane] : 0.0f;
        #pragma unroll
        for (int o = 16; o; o >>= 1) v += __shfl_xor_sync(0xFFFFFFFFu, v, o);
        if (lane == 0) red[0] = v;
    }
    __syncthreads();
    return red[0];
}

// ---------------- tiny zero ----------------
__global__ void zero_small_kernel() {
    int i = threadIdx.x;
    if (i < EE) { g_ecnt[i] = 0; g_imp[i] = 0.0f; }
}

// ---------------- prep: tf32-round all static operands into g_wt ----------------
__global__ void prep_kernel(
    const float* s0, const float* s1, const float* s2, const float* s3,
    const float* s4, const float* s5, const float* s6, const float* s7,
    const float* s8, const float* s9, const float* s10, const float* s11)
{
    int r = blockIdx.y;
    const float* src; size_t off, cnt;
    switch (r) {
        case 0:  src = s0;  off = 0;       cnt = PQ;      break;
        case 1:  src = s1;  off = PQ;      cnt = PQ;      break;
        case 2:  src = s2;  off = 2 * PQ;  cnt = PQ;      break;
        case 3:  src = s3;  off = 3 * PQ;  cnt = PQ;      break;
        case 4:  src = s4;  off = 4 * PQ;  cnt = PQ;      break;
        case 5:  src = s5;  off = 5 * PQ;  cnt = PQ;      break;
        case 6:  src = s6;  off = 6 * PQ;  cnt = PQ;      break;
        case 7:  src = s7;  off = 7 * PQ;  cnt = PQ;      break;
        case 8:  src = s8;  off = 8 * PQ;  cnt = 16 * PQ; break;
        case 9:  src = s9;  off = 24 * PQ; cnt = 16 * PQ; break;
        case 10: src = s10; off = 40 * PQ; cnt = 2 * PQ;  break;
        default: src = s11; off = 42 * PQ; cnt = 2 * PQ;  break;
    }
    const float4* sp = (const float4*)src;
    float4* dp = (float4*)(g_wt + off);
    size_t n4 = cnt >> 2;
    for (size_t i = blockIdx.x * blockDim.x + threadIdx.x; i < n4;
         i += (size_t)gridDim.x * blockDim.x) {
        float4 v = sp[i];
        v.x = tfr(v.x); v.y = tfr(v.y); v.z = tfr(v.z); v.w = tfr(v.w);
        dp[i] = v;
    }
}

// ================= tf32 MMA GEMM core (cp.async pipelined) =================
// MODE 0: C[row0+lr][c] = acc + bias[c]
// MODE 1: gather A rows via atoks; C[row0+lr][c] = tf32(relu(acc+b)) if atoks[lr]>=0
// MODE 2: C[slots[lr]*DM + c] = gates[lr]*(acc+b) if slots[lr]>=0
template<int MODE>
__device__ __forceinline__ void gemm_core(
    const float* __restrict__ A, const float* __restrict__ W,
    const float* __restrict__ bias, float* __restrict__ C,
    int K, int N, int row0, int col0,
    const int* atoks, const int* slots, const float* gates)
{
    extern __shared__ uint32_t smp[];
    uint32_t* As = smp;                      // [NSTAGE][A_ELEMS]
    uint32_t* Bs = smp + NSTAGE * A_ELEMS;   // [NSTAGE][B_ELEMS]

    const int tid  = threadIdx.x;
    const int lane = tid & 31;
    const int wid  = tid >> 5;
    const int wm   = wid >> 2;
    const int wn   = wid & 3;
    const int g    = lane >> 2;
    const int tig  = lane & 3;

    // A loader coords
    const int lr0 = tid >> 2;
    const int akq = (tid & 3) * 4;
    bool p0 = true, p1 = true;
    const float *a0p, *a1p;
    if (MODE == 1) {
        int t0 = atoks[lr0], t1 = atoks[lr0 + 64];
        p0 = (t0 >= 0); p1 = (t1 >= 0);
        a0p = A + (size_t)(p0 ? t0 : 0) * K + akq;
        a1p = A + (size_t)(p1 ? t1 : 0) * K + akq;
    } else {
        a0p = A + (size_t)(row0 + lr0) * K + akq;
        a1p = A + (size_t)(row0 + lr0 + 64) * K + akq;
    }

    // B loader coords
    const int kr = tid >> 4;
    const int nq = (tid & 15) * 8;
    const float* bp = W + (size_t)kr * N + col0 + nq;

    uint32_t sA0 = smem_u32(As) + (lr0 * AS_STRIDE + akq) * 4;
    uint32_t sA1 = sA0 + 64 * AS_STRIDE * 4;
    uint32_t sB0 = smem_u32(Bs) + (kr * BS_STRIDE + nq) * 4;

    const int nk = K / BKT;

#define ISSUE(b, kti) do {                                     \
        uint32_t ao = (uint32_t)(b) * (A_ELEMS * 4);           \
        cp16(sA0 + ao, a0p + (kti) * BKT, p0);                 \
        cp16(sA1 + ao, a1p + (kti) * BKT, p1);                 \
        const float* bs_ = bp + (size_t)(kti) * BKT * N;       \
        uint32_t bo = (uint32_t)(b) * (B_ELEMS * 4);           \
        cp16(sB0 + bo, bs_, true);                             \
        cp16(sB0 + bo + 16, bs_ + 4, true);                    \
    } while (0)

    ISSUE(0, 0); CP_COMMIT;
    ISSUE(1, 1); CP_COMMIT;

    float acc[4][4][4];
    #pragma unroll
    for (int i = 0; i < 4; i++)
        #pragma unroll
        for (int j = 0; j < 4; j++)
            #pragma unroll
            for (int r = 0; r < 4; r++) acc[i][j][r] = 0.0f;

    int buf = 0;
    for (int kt = 0; kt < nk; kt++) {
        CP_WAIT1;
        __syncthreads();
        if (kt + 2 < nk) {
            int nb = buf + 2; if (nb >= NSTAGE) nb -= NSTAGE;
            ISSUE(nb, kt + 2);
        }
        CP_COMMIT;

        const uint32_t* Ab = As + buf * A_ELEMS;
        const uint32_t* Bb = Bs + buf * B_ELEMS;
        #pragma unroll
        for (int k8 = 0; k8 < 2; k8++) {
            uint32_t af[4][4], bf[4][2];
            const uint32_t* abase = Ab + (wm * 64 + g) * AS_STRIDE + k8 * 8 + tig;
            #pragma unroll
            for (int mt = 0; mt < 4; mt++) {
                const uint32_t* p = abase + mt * 16 * AS_STRIDE;
                af[mt][0] = p[0];
                af[mt][1] = p[8 * AS_STRIDE];
                af[mt][2] = p[4];
                af[mt][3] = p[8 * AS_STRIDE + 4];
            }
            const uint32_t* bbase = Bb + (k8 * 8 + tig) * BS_STRIDE + wn * 32 + g;
            #pragma unroll
            for (int nt = 0; nt < 4; nt++) {
                bf[nt][0] = bbase[nt * 8];
                bf[nt][1] = bbase[4 * BS_STRIDE + nt * 8];
            }
            #pragma unroll
            for (int mt = 0; mt < 4; mt++)
                #pragma unroll
                for (int nt = 0; nt < 4; nt++)
                    mma8(acc[mt][nt], af[mt], bf[nt]);
        }
        buf = (buf == NSTAGE - 1) ? 0 : buf + 1;
    }
#undef ISSUE

    // epilogue
    #pragma unroll
    for (int mt = 0; mt < 4; mt++) {
        const int lr = wm * 64 + mt * 16 + g;
        #pragma unroll
        for (int nt = 0; nt < 4; nt++) {
            float* ac = acc[mt][nt];
            const int c = col0 + wn * 32 + nt * 8 + 2 * tig;
            const float bc0 = bias[c], bc1 = bias[c + 1];
            if (MODE == 0) {
                *(float2*)&C[(size_t)(row0 + lr) * N + c]     = make_float2(ac[0] + bc0, ac[1] + bc1);
                *(float2*)&C[(size_t)(row0 + lr + 8) * N + c] = make_float2(ac[2] + bc0, ac[3] + bc1);
            } else if (MODE == 1) {
                if (atoks[lr] >= 0)
                    *(float2*)&C[(size_t)(row0 + lr) * N + c] = make_float2(
                        tfr(fmaxf(ac[0] + bc0, 0.f)), tfr(fmaxf(ac[1] + bc1, 0.f)));
                if (atoks[lr + 8] >= 0)
                    *(float2*)&C[(size_t)(row0 + lr + 8) * N + c] = make_float2(
                        tfr(fmaxf(ac[2] + bc0, 0.f)), tfr(fmaxf(ac[3] + bc1, 0.f)));
            } else {
                int sid = slots[lr]; float gt = gates[lr];
                if (sid >= 0)
                    *(float2*)&C[(size_t)sid * DM + c] =
                        make_float2(gt * (ac[0] + bc0), gt * (ac[1] + bc1));
                sid = slots[lr + 8]; gt = gates[lr + 8];
                if (sid >= 0)
                    *(float2*)&C[(size_t)sid * DM + c] =
                        make_float2(gt * (ac[2] + bc0), gt * (ac[3] + bc1));
            }
        }
    }
}

// ---------------- GEMM wrappers ----------------
__global__ __launch_bounds__(256, 2) void proj_qkv_kernel(
    const float* A0, const float* A1, const float* A2,
    const float* W0, const float* W1, const float* W2,
    const float* b0, const float* b1, const float* b2,
    float* C0, float* C1, float* C2, int K, int N)
{
    const int z = blockIdx.z;
    const float* A = (z == 0) ? A0 : (z == 1) ? A1 : A2;
    const float* W = (z == 0) ? W0 : (z == 1) ? W1 : W2;
    const float* b = (z == 0) ? b0 : (z == 1) ? b1 : b2;
    float*       C = (z == 0) ? C0 : (z == 1) ? C1 : C2;
    gemm_core<0>(A, W, b, C, K, N, blockIdx.y * BM, blockIdx.x * BN,
                 nullptr, nullptr, nullptr);
}

__global__ __launch_bounds__(256, 2) void moe1_kernel(
    const float* __restrict__ X, const float* __restrict__ w1,
    const float* __restrict__ b1)
{
    const int e = blockIdx.z;
    const int cnt = g_ecnt[e];
    const int row0 = blockIdx.y * BM;
    if (row0 >= cnt) return;
    __shared__ int toks[BM];
    if (threadIdx.x < BM) {
        int r = row0 + threadIdx.x;
        toks[threadIdx.x] = (r < cnt) ? g_elist[e * NTOK + r] : -1;
    }
    __syncthreads();
    gemm_core<1>(X, w1 + (size_t)e * DM * FF, b1 + e * FF,
                 g_h + (size_t)e * NTOK * FF,
                 DM, FF, row0, blockIdx.x * BN, toks, nullptr, nullptr);
}

__global__ __launch_bounds__(256, 2) void moe2_kernel(
    const float* __restrict__ w2, const float* __restrict__ b2)
{
    const int e = blockIdx.z;
    const int cnt = g_ecnt[e];
    const int row0 = blockIdx.y * BM;
    if (row0 >= cnt) return;
    __shared__ int slts[BM];
    __shared__ float gat[BM];
    if (threadIdx.x < BM) {
        int r = row0 + threadIdx.x;
        bool ok = (r < cnt);
        slts[threadIdx.x] = ok ? g_slot[e * NTOK + r] : -1;
        gat[threadIdx.x]  = ok ? g_egate[e * NTOK + r] : 0.0f;
    }
    __syncthreads();
    gemm_core<2>(g_h + (size_t)e * NTOK * FF, w2 + (size_t)e * FF * DM,
                 b2 + e * DM, g_ys,
                 FF, DM, row0, blockIdx.x * BN, nullptr, slts, gat);
}

// ---------------- attention (QT=16, dynamic smem) ----------------
#define QT 16
#define ATTN_SMEM ((QT * DH + QT * TT + 4 * QT * DH) * 4)
__global__ __launch_bounds__(256) void attn_kernel(
    const float* __restrict__ Q, const float* __restrict__ Kk,
    const float* __restrict__ V, float* __restrict__ O)
{
    extern __shared__ float am[];
    float* qs  = am;                        // [QT][DH]
    float* s   = am + QT * DH;              // [QT][TT]
    float* red = s + QT * TT;               // [4][QT][DH]

    int q0 = blockIdx.x * QT;
    int h  = blockIdx.y;
    int b  = blockIdx.z;
    int tid = threadIdx.x;

    for (int i = tid; i < QT * DH; i += 256) {
        int qq = i / DH, d = i % DH;
        qs[qq * DH + d] = Q[((size_t)(b * TT + q0 + qq)) * DM + h * DH + d] * 0.125f;
    }
    __syncthreads();

    for (int j = tid; j < TT; j += 256) {
        const float* kp = Kk + ((size_t)(b * TT + j)) * DM + h * DH;
        float acc[QT] = {};
        #pragma unroll 16
        for (int d = 0; d < DH; d++) {
            float kv = kp[d];
            #pragma unroll
            for (int qq = 0; qq < QT; qq++) acc[qq] += qs[qq * DH + d] * kv;
        }
        #pragma unroll
        for (int qq = 0; qq < QT; qq++) s[qq * TT + j] = acc[qq];
    }
    __syncthreads();

    {
        int lane = tid & 31, w = tid >> 5;
        #pragma unroll
        for (int rr = 0; rr < QT / 8; rr++) {
            int row = w * (QT / 8) + rr;
            float* sr = s + row * TT;
            float m = -1e30f;
            for (int j = lane; j < TT; j += 32) m = fmaxf(m, sr[j]);
            #pragma unroll
            for (int o = 16; o; o >>= 1) m = fmaxf(m, __shfl_xor_sync(0xFFFFFFFFu, m, o));
            float sum = 0.0f;
            for (int j = lane; j < TT; j += 32) { float ev = __expf(sr[j] - m); sr[j] = ev; sum += ev; }
            #pragma unroll
            for (int o = 16; o; o >>= 1) sum += __shfl_xor_sync(0xFFFFFFFFu, sum, o);
            float inv = 1.0f / sum;
            for (int j = lane; j < TT; j += 32) sr[j] *= inv;
        }
    }
    __syncthreads();

    {
        int d = tid & 63, grp = tid >> 6;
        float acc[QT] = {};
        for (int j = grp; j < TT; j += 4) {
            float vv = V[((size_t)(b * TT + j)) * DM + h * DH + d];
            #pragma unroll
            for (int qq = 0; qq < QT; qq++) acc[qq] += s[qq * TT + j] * vv;
        }
        #pragma unroll
        for (int qq = 0; qq < QT; qq++) red[(grp * QT + qq) * DH + d] = acc[qq];
        __syncthreads();
        if (grp == 0) {
            #pragma unroll
            for (int qq = 0; qq < QT; qq++) {
                float r = red[(0 * QT + qq) * DH + d] + red[(1 * QT + qq) * DH + d]
                        + red[(2 * QT + qq) * DH + d] + red[(3 * QT + qq) * DH + d];
                O[((size_t)(b * TT + q0 + qq)) * DM + h * DH + d] = tfr(r);
            }
        }
    }
}

// ---------------- add + layernorm (dual output: fp32 + tf32-rounded) ----------------
__global__ __launch_bounds__(256) void add_ln_kernel(
    const float* __restrict__ x, const float* __restrict__ r,
    const float* __restrict__ g, const float* __restrict__ be,
    float* __restrict__ out, float* __restrict__ out_t)
{
    __shared__ float red[32];
    __shared__ float s_mean, s_rstd;
    int row = blockIdx.x, tid = threadIdx.x;
    const float* xp = x + (size_t)row * DM;
    const float* rp = r + (size_t)row * DM;
    float v[4]; float sum = 0.0f;
    #pragma unroll
    for (int i = 0; i < 4; i++) { int idx = tid + i * 256; v[i] = xp[idx] + rp[idx]; sum += v[i]; }
    sum = block_reduce_sum(sum, red);
    if (tid == 0) s_mean = sum * (1.0f / DM);
    __syncthreads();
    float mean = s_mean, vs = 0.0f;
    #pragma unroll
    for (int i = 0; i < 4; i++) { float dv = v[i] - mean; vs += dv * dv; }
    vs = block_reduce_sum(vs, red);
    if (tid == 0) s_rstd = rsqrtf(vs * (1.0f / DM) + EPSL);
    __syncthreads();
    float rs = s_rstd;
    #pragma unroll
    for (int i = 0; i < 4; i++) {
        int idx = tid + i * 256;
        float o = (v[i] - mean) * rs * g[idx] + be[idx];
        out[(size_t)row * DM + idx] = o;
        if (out_t) out_t[(size_t)row * DM + idx] = tfr(o);
    }
}

// ---------------- final add + layernorm over expert slots ----------------
__global__ __launch_bounds__(256) void add_ln_moe_kernel(
    const float* __restrict__ r, const float* __restrict__ g,
    const float* __restrict__ be, float* __restrict__ out)
{
    __shared__ float red[32];
    __shared__ float s_mean, s_rstd;
    int row = blockIdx.x, tid = threadIdx.x;
    const float* y0 = g_ys + (size_t)(row * 2) * DM;
    const float* y1 = y0 + DM;
    const float* rp = r + (size_t)row * DM;
    float v[4]; float sum = 0.0f;
    #pragma unroll
    for (int i = 0; i < 4; i++) {
        int idx = tid + i * 256;
        v[i] = y0[idx] + y1[idx] + rp[idx];
        sum += v[i];
    }
    sum = block_reduce_sum(sum, red);
    if (tid == 0) s_mean = sum * (1.0f / DM);
    __syncthreads();
    float mean = s_mean, vs = 0.0f;
    #pragma unroll
    for (int i = 0; i < 4; i++) { float dv = v[i] - mean; vs += dv * dv; }
    vs = block_reduce_sum(vs, red);
    if (tid == 0) s_rstd = rsqrtf(vs * (1.0f / DM) + EPSL);
    __syncthreads();
    float rs = s_rstd;
    #pragma unroll
    for (int i = 0; i < 4; i++) {
        int idx = tid + i * 256;
        out[(size_t)row * DM + idx] = (v[i] - mean) * rs * g[idx] + be[idx];
    }
}

// ---------------- router ----------------
__global__ __launch_bounds__(256) void router_kernel(
    const float* __restrict__ x, const float* __restrict__ rw,
    const float* __restrict__ rb)
{
    int t = blockIdx.x;
    int tid = threadIdx.x, lane = tid & 31, w = tid >> 5;
    __shared__ float logits[EE];
    const float* xp = x + (size_t)t * DM;
    float acc = 0.0f;
    for (int d = lane; d < DM; d += 32) acc += xp[d] * rw[d * EE + w];
    #pragma unroll
    for (int o = 16; o; o >>= 1) acc += __shfl_xor_sync(0xFFFFFFFFu, acc, o);
    if (lane == 0) logits[w] = acc + rb[w];
    __syncthreads();
    if (tid == 0) {
        float m = logits[0];
        #pragma unroll
        for (int e = 1; e < EE; e++) m = fmaxf(m, logits[e]);
        float p[EE], sum = 0.0f;
        #pragma unroll
        for (int e = 0; e < EE; e++) { p[e] = __expf(logits[e] - m); sum += p[e]; }
        float inv = 1.0f / sum;
        #pragma unroll
        for (int e = 0; e < EE; e++) { p[e] *= inv; atomicAdd(&g_imp[e], p[e]); }
        int i0 = 0;
        #pragma unroll
        for (int e = 1; e < EE; e++) if (p[e] > p[i0]) i0 = e;
        int i1 = (i0 == 0) ? 1 : 0;
        #pragma unroll
        for (int e = 0; e < EE; e++) if (e != i0 && p[e] > p[i1]) i1 = e;
        float g0 = p[i0], g1 = p[i1], gs = 1.0f / (g0 + g1);
        g0 *= gs; g1 *= gs;
        int pos = atomicAdd(&g_ecnt[i0], 1);
        g_elist[i0 * NTOK + pos] = t; g_egate[i0 * NTOK + pos] = g0;
        g_slot[i0 * NTOK + pos] = 2 * t;
        pos = atomicAdd(&g_ecnt[i1], 1);
        g_elist[i1 * NTOK + pos] = t; g_egate[i1 * NTOK + pos] = g1;
        g_slot[i1 * NTOK + pos] = 2 * t + 1;
    }
}

// ---------------- load-balance loss ----------------
__global__ void lb_kernel(float* __restrict__ out) {
    float lb = 0.0f;
    #pragma unroll
    for (int e = 0; e < EE; e++)
        lb += ((float)g_ecnt[e] / (float)(NTOK * 2)) * (g_imp[e] / (float)NTOK);
    out[0] = (float)EE * lb;
}

// ---------------- host launcher ----------------
extern "C" void kernel_launch(void* const* d_in, const int* in_sizes, int n_in,
                              void* d_out, int out_size)
{
    const float* tgt = (const float*)d_in[0];
    const float* mem = (const float*)d_in[1];
    const float *sa_wq, *sa_wk, *sa_wv, *sa_wo, *ca_wq, *ca_wk, *ca_wv, *ca_wo;
    const float *sa_bq, *sa_bk, *sa_bv, *sa_bo, *ca_bq, *ca_bk, *ca_bv, *ca_bo;
    const float *ln1g, *ln1b, *ln2g, *ln2b, *ln3g, *ln3b, *rw, *rb, *w1, *b1, *w2, *b2;

    if (in_sizes[5] == DM * DM) {
        sa_wq = (const float*)d_in[2];  sa_wk = (const float*)d_in[3];
        sa_wv = (const float*)d_in[4];  sa_wo = (const float*)d_in[5];
        ca_wq = (const float*)d_in[6];  ca_wk = (const float*)d_in[7];
        ca_wv = (const float*)d_in[8];  ca_wo = (const float*)d_in[9];
        sa_bq = (const float*)d_in[10]; sa_bk = (const float*)d_in[11];
        sa_bv = (const float*)d_in[12]; sa_bo = (const float*)d_in[13];
        ca_bq = (const float*)d_in[14]; ca_bk = (const float*)d_in[15];
        ca_bv = (const float*)d_in[16]; ca_bo = (const float*)d_in[17];
        ln1g = (const float*)d_in[18]; ln2g = (const float*)d_in[19]; ln3g = (const float*)d_in[20];
        ln1b = (const float*)d_in[21]; ln2b = (const float*)d_in[22]; ln3b = (const float*)d_in[23];
    } else {
        sa_wq = (const float*)d_in[2];  sa_wk = (const float*)d_in[3];
        sa_wv = (const float*)d_in[4];
        sa_bq = (const float*)d_in[5];  sa_bk = (const float*)d_in[6];
        sa_bv = (const float*)d_in[7];
        sa_wo = (const float*)d_in[8];  sa_bo = (const float*)d_in[9];
        ca_wq = (const float*)d_in[10]; ca_wk = (const float*)d_in[11];
        ca_wv = (const float*)d_in[12];
        ca_bq = (const float*)d_in[13]; ca_bk = (const float*)d_in[14];
        ca_bv = (const float*)d_in[15];
        ca_wo = (const float*)d_in[16]; ca_bo = (const float*)d_in[17];
        ln1g = (const float*)d_in[18]; ln1b = (const float*)d_in[19];
        ln2g = (const float*)d_in[20]; ln2b = (const float*)d_in[21];
        ln3g = (const float*)d_in[22]; ln3b = (const float*)d_in[23];
    }
    rw = (const float*)d_in[24]; rb = (const float*)d_in[25];
    w1 = (const float*)d_in[26]; b1 = (const float*)d_in[27];
    w2 = (const float*)d_in[28]; b2 = (const float*)d_in[29];

    float *wt, *q, *k, *v, *ctx, *attn, *t1, *t1t, *t2, *t2t;
    cudaGetSymbolAddress((void**)&wt,   g_wt);
    cudaGetSymbolAddress((void**)&q,    g_q);
    cudaGetSymbolAddress((void**)&k,    g_k);
    cudaGetSymbolAddress((void**)&v,    g_v);
    cudaGetSymbolAddress((void**)&ctx,  g_ctx);
    cudaGetSymbolAddress((void**)&attn, g_attn);
    cudaGetSymbolAddress((void**)&t1,   g_t1);
    cudaGetSymbolAddress((void**)&t1t,  g_t1t);
    cudaGetSymbolAddress((void**)&t2,   g_t2);
    cudaGetSymbolAddress((void**)&t2t,  g_t2t);

    const float* wt_saq = wt + 0 * PQ;
    const float* wt_sak = wt + 1 * PQ;
    const float* wt_sav = wt + 2 * PQ;
    const float* wt_sao = wt + 3 * PQ;
    const float* wt_caq = wt + 4 * PQ;
    const float* wt_cak = wt + 5 * PQ;
    const float* wt_cav = wt + 6 * PQ;
    const float* wt_cao = wt + 7 * PQ;
    const float* wt_w1  = wt + 8 * PQ;
    const float* wt_w2  = wt + 24 * PQ;
    const float* tgt_t  = wt + 40 * PQ;
    const float* mem_t  = wt + 42 * PQ;

    float* out = (float*)d_out;

    cudaFuncSetAttribute(proj_qkv_kernel, cudaFuncAttributeMaxDynamicSharedMemorySize, GEMM_SMEM);
    cudaFuncSetAttribute(moe1_kernel,     cudaFuncAttributeMaxDynamicSharedMemorySize, GEMM_SMEM);
    cudaFuncSetAttribute(moe2_kernel,     cudaFuncAttributeMaxDynamicSharedMemorySize, GEMM_SMEM);
    cudaFuncSetAttribute(attn_kernel,     cudaFuncAttributeMaxDynamicSharedMemorySize, ATTN_SMEM);

    dim3 gQKV(DM / BN, NTOK / BM, 3);
    dim3 gO  (DM / BN, NTOK / BM, 1);
    dim3 gAttn(TT / QT, HH, BB);
    dim3 gMoe1(FF / BN, NTOK / BM, EE);
    dim3 gMoe2(DM / BN, NTOK / BM, EE);
    dim3 gPrep(256, 12);

    zero_small_kernel<<<1, 32>>>();
    prep_kernel<<<gPrep, 256>>>(sa_wq, sa_wk, sa_wv, sa_wo, ca_wq, ca_wk, ca_wv, ca_wo,
                                w1, w2, tgt, mem);

    // ---- self attention ----
    proj_qkv_kernel<<<gQKV, 256, GEMM_SMEM>>>(tgt_t, tgt_t, tgt_t, wt_saq, wt_sak, wt_sav,
                                              sa_bq, sa_bk, sa_bv, q, k, v, DM, DM);
    attn_kernel<<<gAttn, 256, ATTN_SMEM>>>(q, k, v, ctx);
    proj_qkv_kernel<<<gO, 256, GEMM_SMEM>>>(ctx, ctx, ctx, wt_sao, wt_sao, wt_sao,
                                            sa_bo, sa_bo, sa_bo, attn, attn, attn, DM, DM);
    add_ln_kernel<<<NTOK, 256>>>(attn, tgt, ln1g, ln1b, t1, t1t);

    // ---- cross attention ----
    proj_qkv_kernel<<<gQKV, 256, GEMM_SMEM>>>(t1t, mem_t, mem_t, wt_caq, wt_cak, wt_cav,
                                              ca_bq, ca_bk, ca_bv, q, k, v, DM, DM);
    attn_kernel<<<gAttn, 256, ATTN_SMEM>>>(q, k, v, ctx);
    proj_qkv_kernel<<<gO, 256, GEMM_SMEM>>>(ctx, ctx, ctx, wt_cao, wt_cao, wt_cao,
                                            ca_bo, ca_bo, ca_bo, attn, attn, attn, DM, DM);
    add_ln_kernel<<<NTOK, 256>>>(attn, t1, ln2g, ln2b, t2, t2t);

    // ---- MoE (sparse top-2, slot-based scatter) ----
    router_kernel<<<NTOK, 256>>>(t2, rw, rb);
    moe1_kernel<<<gMoe1, 256, GEMM_SMEM>>>(t2t, wt_w1, b1);
    moe2_kernel<<<gMoe2, 256, GEMM_SMEM>>>(wt_w2, b2);
    add_ln_moe_kernel<<<NTOK, 256>>>(t2, ln3g, ln3b, out);

    if (out_size > NTOK * DM)
        lb_kernel<<<1, 1>>>(out + (size_t)NTOK * DM);
}

// round 4
// speedup vs baseline: 3.4106x; 1.4186x over previous
#include <cuda_runtime.h>
#include <cuda_bf16.h>
#include <math.h>
#include <stdint.h>

// ---------------- problem constants ----------------
#define BB   4
#define TT   512
#define DM   1024
#define HH   16
#define DH   64
#define FF   2048
#define EE   8
#define NTOK 2048
#define EPSL 1e-5f

// GEMM tiling
#define BM 128
#define BN 128
#define BKT 16
#define AS_STRIDE 20     // conflict-free fragment loads (verified)
#define BS_STRIDE 136
#define NSTAGE 3
#define A_ELEMS (BM * AS_STRIDE)    // 2560
#define B_ELEMS (BKT * BS_STRIDE)   // 2176
#define GEMM_SMEM (NSTAGE * (A_ELEMS + B_ELEMS) * 4)   // 56832 B

// pre-converted (tf32-rounded) constant pool layout, units of floats
#define PQ 1048576ull
#define WT_TOTAL (44ull * PQ)

// ---------------- static scratch ----------------
__device__ float g_wt  [WT_TOTAL];          // rounded weights + tgt + mem
__device__ float g_q   [NTOK * DM];
__device__ float g_k   [NTOK * DM];
__device__ float g_v   [NTOK * DM];
__device__ float g_ctx [NTOK * DM];         // written tf32-rounded by attn
__device__ float g_attn[NTOK * DM];
__device__ float g_t1  [NTOK * DM];
__device__ float g_t1t [NTOK * DM];
__device__ float g_t2  [NTOK * DM];
__device__ float g_t2t [NTOK * DM];
__device__ float g_ys  [NTOK * 2 * DM];     // per-slot expert outputs
__device__ float g_h   [(size_t)EE * NTOK * FF];  // rounded by moe1 epilogue
__device__ int   g_elist[EE * NTOK];
__device__ int   g_slot [EE * NTOK];
__device__ float g_egate[EE * NTOK];
__device__ int   g_ecnt [EE];
__device__ float g_imp  [EE];

// ---------------- helpers ----------------
__device__ __forceinline__ uint32_t f2tf(float f) {
    uint32_t u;
    asm("cvt.rna.tf32.f32 %0, %1;" : "=r"(u) : "f"(f));
    return u;
}
__device__ __forceinline__ float tfr(float f) { return __uint_as_float(f2tf(f)); }

__device__ __forceinline__ void mma8(float* c, const uint32_t* a, const uint32_t* b) {
    asm volatile(
        "mma.sync.aligned.m16n8k8.row.col.f32.tf32.tf32.f32 "
        "{%0,%1,%2,%3}, {%4,%5,%6,%7}, {%8,%9}, {%0,%1,%2,%3};\n"
        : "+f"(c[0]), "+f"(c[1]), "+f"(c[2]), "+f"(c[3])
        : "r"(a[0]), "r"(a[1]), "r"(a[2]), "r"(a[3]), "r"(b[0]), "r"(b[1]));
}

__device__ __forceinline__ uint32_t smem_u32(const void* p) {
    return (uint32_t)__cvta_generic_to_shared(p);
}
__device__ __forceinline__ void cp16(uint32_t dst, const void* src, bool pred) {
    int sz = pred ? 16 : 0;
    asm volatile("cp.async.cg.shared.global [%0], [%1], 16, %2;\n"
                 :: "r"(dst), "l"(src), "r"(sz) : "memory");
}
#define CP_COMMIT  asm volatile("cp.async.commit_group;\n" ::: "memory")
#define CP_WAIT1   asm volatile("cp.async.wait_group 1;\n" ::: "memory")

__device__ __forceinline__ float block_reduce_sum(float v, float* red) {
    int lane = threadIdx.x & 31, w = threadIdx.x >> 5;
    #pragma unroll
    for (int o = 16; o; o >>= 1) v += __shfl_xor_sync(0xFFFFFFFFu, v, o);
    __syncthreads();
    if (lane == 0) red[w] = v;
    __syncthreads();
    if (w == 0) {
        v = (lane < ((int)blockDim.x >> 5)) ? red[lane] : 0.0f;
        #pragma unroll
        for (int o = 16; o; o >>= 1) v += __shfl_xor_sync(0xFFFFFFFFu, v, o);
        if (lane == 0) red[0] = v;
    }
    __syncthreads();
    return red[0];
}

// ---------------- tiny zero ----------------
__global__ void zero_small_kernel() {
    int i = threadIdx.x;
    if (i < EE) { g_ecnt[i] = 0; g_imp[i] = 0.0f; }
}

// ---------------- prep: tf32-round all static operands into g_wt ----------------
__global__ void prep_kernel(
    const float* s0, const float* s1, const float* s2, const float* s3,
    const float* s4, const float* s5, const float* s6, const float* s7,
    const float* s8, const float* s9, const float* s10, const float* s11)
{
    int r = blockIdx.y;
    const float* src; size_t off, cnt;
    switch (r) {
        case 0:  src = s0;  off = 0;       cnt = PQ;      break;
        case 1:  src = s1;  off = PQ;      cnt = PQ;      break;
        case 2:  src = s2;  off = 2 * PQ;  cnt = PQ;      break;
        case 3:  src = s3;  off = 3 * PQ;  cnt = PQ;      break;
        case 4:  src = s4;  off = 4 * PQ;  cnt = PQ;      break;
        case 5:  src = s5;  off = 5 * PQ;  cnt = PQ;      break;
        case 6:  src = s6;  off = 6 * PQ;  cnt = PQ;      break;
        case 7:  src = s7;  off = 7 * PQ;  cnt = PQ;      break;
        case 8:  src = s8;  off = 8 * PQ;  cnt = 16 * PQ; break;
        case 9:  src = s9;  off = 24 * PQ; cnt = 16 * PQ; break;
        case 10: src = s10; off = 40 * PQ; cnt = 2 * PQ;  break;
        default: src = s11; off = 42 * PQ; cnt = 2 * PQ;  break;
    }
    const float4* sp = (const float4*)src;
    float4* dp = (float4*)(g_wt + off);
    size_t n4 = cnt >> 2;
    for (size_t i = blockIdx.x * blockDim.x + threadIdx.x; i < n4;
         i += (size_t)gridDim.x * blockDim.x) {
        float4 v = sp[i];
        v.x = tfr(v.x); v.y = tfr(v.y); v.z = tfr(v.z); v.w = tfr(v.w);
        dp[i] = v;
    }
}

// ================= tf32 MMA GEMM core (cp.async pipelined) =================
template<int MODE>
__device__ __forceinline__ void gemm_core(
    const float* __restrict__ A, const float* __restrict__ W,
    const float* __restrict__ bias, float* __restrict__ C,
    int K, int N, int row0, int col0,
    const int* atoks, const int* slots, const float* gates)
{
    extern __shared__ uint32_t smp[];
    uint32_t* As = smp;
    uint32_t* Bs = smp + NSTAGE * A_ELEMS;

    const int tid  = threadIdx.x;
    const int lane = tid & 31;
    const int wid  = tid >> 5;
    const int wm   = wid >> 2;
    const int wn   = wid & 3;
    const int g    = lane >> 2;
    const int tig  = lane & 3;

    const int lr0 = tid >> 2;
    const int akq = (tid & 3) * 4;
    bool p0 = true, p1 = true;
    const float *a0p, *a1p;
    if (MODE == 1) {
        int t0 = atoks[lr0], t1 = atoks[lr0 + 64];
        p0 = (t0 >= 0); p1 = (t1 >= 0);
        a0p = A + (size_t)(p0 ? t0 : 0) * K + akq;
        a1p = A + (size_t)(p1 ? t1 : 0) * K + akq;
    } else {
        a0p = A + (size_t)(row0 + lr0) * K + akq;
        a1p = A + (size_t)(row0 + lr0 + 64) * K + akq;
    }

    const int kr = tid >> 4;
    const int nq = (tid & 15) * 8;
    const float* bp = W + (size_t)kr * N + col0 + nq;

    uint32_t sA0 = smem_u32(As) + (lr0 * AS_STRIDE + akq) * 4;
    uint32_t sA1 = sA0 + 64 * AS_STRIDE * 4;
    uint32_t sB0 = smem_u32(Bs) + (kr * BS_STRIDE + nq) * 4;

    const int nk = K / BKT;

#define ISSUE(b, kti) do {                                     \
        uint32_t ao = (uint32_t)(b) * (A_ELEMS * 4);           \
        cp16(sA0 + ao, a0p + (kti) * BKT, p0);                 \
        cp16(sA1 + ao, a1p + (kti) * BKT, p1);                 \
        const float* bs_ = bp + (size_t)(kti) * BKT * N;       \
        uint32_t bo = (uint32_t)(b) * (B_ELEMS * 4);           \
        cp16(sB0 + bo, bs_, true);                             \
        cp16(sB0 + bo + 16, bs_ + 4, true);                    \
    } while (0)

    ISSUE(0, 0); CP_COMMIT;
    ISSUE(1, 1); CP_COMMIT;

    float acc[4][4][4];
    #pragma unroll
    for (int i = 0; i < 4; i++)
        #pragma unroll
        for (int j = 0; j < 4; j++)
            #pragma unroll
            for (int r = 0; r < 4; r++) acc[i][j][r] = 0.0f;

    int buf = 0;
    for (int kt = 0; kt < nk; kt++) {
        CP_WAIT1;
        __syncthreads();
        if (kt + 2 < nk) {
            int nb = buf + 2; if (nb >= NSTAGE) nb -= NSTAGE;
            ISSUE(nb, kt + 2);
        }
        CP_COMMIT;

        const uint32_t* Ab = As + buf * A_ELEMS;
        const uint32_t* Bb = Bs + buf * B_ELEMS;
        #pragma unroll
        for (int k8 = 0; k8 < 2; k8++) {
            uint32_t af[4][4], bf[4][2];
            const uint32_t* abase = Ab + (wm * 64 + g) * AS_STRIDE + k8 * 8 + tig;
            #pragma unroll
            for (int mt = 0; mt < 4; mt++) {
                const uint32_t* p = abase + mt * 16 * AS_STRIDE;
                af[mt][0] = p[0];
                af[mt][1] = p[8 * AS_STRIDE];
                af[mt][2] = p[4];
                af[mt][3] = p[8 * AS_STRIDE + 4];
            }
            const uint32_t* bbase = Bb + (k8 * 8 + tig) * BS_STRIDE + wn * 32 + g;
            #pragma unroll
            for (int nt = 0; nt < 4; nt++) {
                bf[nt][0] = bbase[nt * 8];
                bf[nt][1] = bbase[4 * BS_STRIDE + nt * 8];
            }
            #pragma unroll
            for (int mt = 0; mt < 4; mt++)
                #pragma unroll
                for (int nt = 0; nt < 4; nt++)
                    mma8(acc[mt][nt], af[mt], bf[nt]);
        }
        buf = (buf == NSTAGE - 1) ? 0 : buf + 1;
    }
#undef ISSUE

    #pragma unroll
    for (int mt = 0; mt < 4; mt++) {
        const int lr = wm * 64 + mt * 16 + g;
        #pragma unroll
        for (int nt = 0; nt < 4; nt++) {
            float* ac = acc[mt][nt];
            const int c = col0 + wn * 32 + nt * 8 + 2 * tig;
            const float bc0 = bias[c], bc1 = bias[c + 1];
            if (MODE == 0) {
                *(float2*)&C[(size_t)(row0 + lr) * N + c]     = make_float2(ac[0] + bc0, ac[1] + bc1);
                *(float2*)&C[(size_t)(row0 + lr + 8) * N + c] = make_float2(ac[2] + bc0, ac[3] + bc1);
            } else if (MODE == 1) {
                if (atoks[lr] >= 0)
                    *(float2*)&C[(size_t)(row0 + lr) * N + c] = make_float2(
                        tfr(fmaxf(ac[0] + bc0, 0.f)), tfr(fmaxf(ac[1] + bc1, 0.f)));
                if (atoks[lr + 8] >= 0)
                    *(float2*)&C[(size_t)(row0 + lr + 8) * N + c] = make_float2(
                        tfr(fmaxf(ac[2] + bc0, 0.f)), tfr(fmaxf(ac[3] + bc1, 0.f)));
            } else {
                int sid = slots[lr]; float gt = gates[lr];
                if (sid >= 0)
                    *(float2*)&C[(size_t)sid * DM + c] =
                        make_float2(gt * (ac[0] + bc0), gt * (ac[1] + bc1));
                sid = slots[lr + 8]; gt = gates[lr + 8];
                if (sid >= 0)
                    *(float2*)&C[(size_t)sid * DM + c] =
                        make_float2(gt * (ac[2] + bc0), gt * (ac[3] + bc1));
            }
        }
    }
}

// ---------------- GEMM wrappers ----------------
__global__ __launch_bounds__(256, 2) void proj_qkv_kernel(
    const float* A0, const float* A1, const float* A2,
    const float* W0, const float* W1, const float* W2,
    const float* b0, const float* b1, const float* b2,
    float* C0, float* C1, float* C2, int K, int N)
{
    const int z = blockIdx.z;
    const float* A = (z == 0) ? A0 : (z == 1) ? A1 : A2;
    const float* W = (z == 0) ? W0 : (z == 1) ? W1 : W2;
    const float* b = (z == 0) ? b0 : (z == 1) ? b1 : b2;
    float*       C = (z == 0) ? C0 : (z == 1) ? C1 : C2;
    gemm_core<0>(A, W, b, C, K, N, blockIdx.y * BM, blockIdx.x * BN,
                 nullptr, nullptr, nullptr);
}

__global__ __launch_bounds__(256, 2) void moe1_kernel(
    const float* __restrict__ X, const float* __restrict__ w1,
    const float* __restrict__ b1)
{
    const int e = blockIdx.z;
    const int cnt = g_ecnt[e];
    const int row0 = blockIdx.y * BM;
    if (row0 >= cnt) return;
    __shared__ int toks[BM];
    if (threadIdx.x < BM) {
        int r = row0 + threadIdx.x;
        toks[threadIdx.x] = (r < cnt) ? g_elist[e * NTOK + r] : -1;
    }
    __syncthreads();
    gemm_core<1>(X, w1 + (size_t)e * DM * FF, b1 + e * FF,
                 g_h + (size_t)e * NTOK * FF,
                 DM, FF, row0, blockIdx.x * BN, toks, nullptr, nullptr);
}

__global__ __launch_bounds__(256, 2) void moe2_kernel(
    const float* __restrict__ w2, const float* __restrict__ b2)
{
    const int e = blockIdx.z;
    const int cnt = g_ecnt[e];
    const int row0 = blockIdx.y * BM;
    if (row0 >= cnt) return;
    __shared__ int slts[BM];
    __shared__ float gat[BM];
    if (threadIdx.x < BM) {
        int r = row0 + threadIdx.x;
        bool ok = (r < cnt);
        slts[threadIdx.x] = ok ? g_slot[e * NTOK + r] : -1;
        gat[threadIdx.x]  = ok ? g_egate[e * NTOK + r] : 0.0f;
    }
    __syncthreads();
    gemm_core<2>(g_h + (size_t)e * NTOK * FF, w2 + (size_t)e * FF * DM,
                 b2 + e * DM, g_ys,
                 FF, DM, row0, blockIdx.x * BN, nullptr, slts, gat);
}

// ---------------- attention (QT=16, vectorized smem access) ----------------
#define QT 16
#define ATTN_SMEM ((QT * DH + QT * TT + 4 * QT * DH) * 4)
__global__ __launch_bounds__(256) void attn_kernel(
    const float* __restrict__ Q, const float* __restrict__ Kk,
    const float* __restrict__ V, float* __restrict__ O)
{
    extern __shared__ float am[];
    float* qs  = am;                        // [QT][DH]
    float* s   = am + QT * DH;              // [QT][TT]
    float* red = s + QT * TT;               // [4][QT][DH]

    int q0 = blockIdx.x * QT;
    int h  = blockIdx.y;
    int b  = blockIdx.z;
    int tid = threadIdx.x;

    for (int i = tid; i < QT * DH; i += 256) {
        int qq = i / DH, d = i % DH;
        qs[qq * DH + d] = Q[((size_t)(b * TT + q0 + qq)) * DM + h * DH + d] * 0.125f;
    }
    __syncthreads();

    // ---- scores: float4 over d; qs LDS128 broadcast, K LDG128 ----
    #pragma unroll
    for (int jj = 0; jj < 2; jj++) {
        int j = tid + jj * 256;
        const float4* kp = (const float4*)(Kk + ((size_t)(b * TT + j)) * DM + h * DH);
        float acc[QT] = {};
        #pragma unroll 4
        for (int d4 = 0; d4 < DH / 4; d4++) {
            float4 kv = kp[d4];
            #pragma unroll
            for (int qq = 0; qq < QT; qq++) {
                float4 qv = *(const float4*)&qs[qq * DH + d4 * 4];
                acc[qq] = fmaf(qv.x, kv.x, acc[qq]);
                acc[qq] = fmaf(qv.y, kv.y, acc[qq]);
                acc[qq] = fmaf(qv.z, kv.z, acc[qq]);
                acc[qq] = fmaf(qv.w, kv.w, acc[qq]);
            }
        }
        #pragma unroll
        for (int qq = 0; qq < QT; qq++) s[qq * TT + j] = acc[qq];
    }
    __syncthreads();

    // ---- softmax: warp w owns rows [w*2, w*2+1] ----
    {
        int lane = tid & 31, w = tid >> 5;
        #pragma unroll
        for (int rr = 0; rr < QT / 8; rr++) {
            int row = w * (QT / 8) + rr;
            float* sr = s + row * TT;
            float m = -1e30f;
            for (int j = lane; j < TT; j += 32) m = fmaxf(m, sr[j]);
            #pragma unroll
            for (int o = 16; o; o >>= 1) m = fmaxf(m, __shfl_xor_sync(0xFFFFFFFFu, m, o));
            float sum = 0.0f;
            for (int j = lane; j < TT; j += 32) { float ev = __expf(sr[j] - m); sr[j] = ev; sum += ev; }
            #pragma unroll
            for (int o = 16; o; o >>= 1) sum += __shfl_xor_sync(0xFFFFFFFFu, sum, o);
            float inv = 1.0f / sum;
            for (int j = lane; j < TT; j += 32) sr[j] *= inv;
        }
    }
    __syncthreads();

    // ---- PV: float4 over j; s LDS128 broadcast, V coalesced ----
    {
        int d = tid & 63, grp = tid >> 6;
        const int j0 = grp * (TT / 4);
        float acc[QT] = {};
        #pragma unroll 2
        for (int j = j0; j < j0 + TT / 4; j += 4) {
            const float* vp = V + ((size_t)(b * TT + j)) * DM + h * DH + d;
            float v0 = vp[0];
            float v1 = vp[DM];
            float v2 = vp[2 * DM];
            float v3 = vp[3 * DM];
            #pragma unroll
            for (int qq = 0; qq < QT; qq++) {
                float4 s4 = *(const float4*)&s[qq * TT + j];
                acc[qq] = fmaf(s4.x, v0, acc[qq]);
                acc[qq] = fmaf(s4.y, v1, acc[qq]);
                acc[qq] = fmaf(s4.z, v2, acc[qq]);
                acc[qq] = fmaf(s4.w, v3, acc[qq]);
            }
        }
        #pragma unroll
        for (int qq = 0; qq < QT; qq++) red[(grp * QT + qq) * DH + d] = acc[qq];
        __syncthreads();
        if (grp == 0) {
            #pragma unroll
            for (int qq = 0; qq < QT; qq++) {
                float r = red[(0 * QT + qq) * DH + d] + red[(1 * QT + qq) * DH + d]
                        + red[(2 * QT + qq) * DH + d] + red[(3 * QT + qq) * DH + d];
                O[((size_t)(b * TT + q0 + qq)) * DM + h * DH + d] = tfr(r);
            }
        }
    }
}

// ---------------- add + layernorm (dual output: fp32 + tf32-rounded) ----------------
__global__ __launch_bounds__(256) void add_ln_kernel(
    const float* __restrict__ x, const float* __restrict__ r,
    const float* __restrict__ g, const float* __restrict__ be,
    float* __restrict__ out, float* __restrict__ out_t)
{
    __shared__ float red[32];
    __shared__ float s_mean, s_rstd;
    int row = blockIdx.x, tid = threadIdx.x;
    const float* xp = x + (size_t)row * DM;
    const float* rp = r + (size_t)row * DM;
    float v[4]; float sum = 0.0f;
    #pragma unroll
    for (int i = 0; i < 4; i++) { int idx = tid + i * 256; v[i] = xp[idx] + rp[idx]; sum += v[i]; }
    sum = block_reduce_sum(sum, red);
    if (tid == 0) s_mean = sum * (1.0f / DM);
    __syncthreads();
    float mean = s_mean, vs = 0.0f;
    #pragma unroll
    for (int i = 0; i < 4; i++) { float dv = v[i] - mean; vs += dv * dv; }
    vs = block_reduce_sum(vs, red);
    if (tid == 0) s_rstd = rsqrtf(vs * (1.0f / DM) + EPSL);
    __syncthreads();
    float rs = s_rstd;
    #pragma unroll
    for (int i = 0; i < 4; i++) {
        int idx = tid + i * 256;
        float o = (v[i] - mean) * rs * g[idx] + be[idx];
        out[(size_t)row * DM + idx] = o;
        if (out_t) out_t[(size_t)row * DM + idx] = tfr(o);
    }
}

// ---------------- final add + layernorm over expert slots ----------------
__global__ __launch_bounds__(256) void add_ln_moe_kernel(
    const float* __restrict__ r, const float* __restrict__ g,
    const float* __restrict__ be, float* __restrict__ out)
{
    __shared__ float red[32];
    __shared__ float s_mean, s_rstd;
    int row = blockIdx.x, tid = threadIdx.x;
    const float* y0 = g_ys + (size_t)(row * 2) * DM;
    const float* y1 = y0 + DM;
    const float* rp = r + (size_t)row * DM;
    float v[4]; float sum = 0.0f;
    #pragma unroll
    for (int i = 0; i < 4; i++) {
        int idx = tid + i * 256;
        v[i] = y0[idx] + y1[idx] + rp[idx];
        sum += v[i];
    }
    sum = block_reduce_sum(sum, red);
    if (tid == 0) s_mean = sum * (1.0f / DM);
    __syncthreads();
    float mean = s_mean, vs = 0.0f;
    #pragma unroll
    for (int i = 0; i < 4; i++) { float dv = v[i] - mean; vs += dv * dv; }
    vs = block_reduce_sum(vs, red);
    if (tid == 0) s_rstd = rsqrtf(vs * (1.0f / DM) + EPSL);
    __syncthreads();
    float rs = s_rstd;
    #pragma unroll
    for (int i = 0; i < 4; i++) {
        int idx = tid + i * 256;
        out[(size_t)row * DM + idx] = (v[i] - mean) * rs * g[idx] + be[idx];
    }
}

// ---------------- router ----------------
__global__ __launch_bounds__(256) void router_kernel(
    const float* __restrict__ x, const float* __restrict__ rw,
    const float* __restrict__ rb)
{
    int t = blockIdx.x;
    int tid = threadIdx.x, lane = tid & 31, w = tid >> 5;
    __shared__ float logits[EE];
    const float* xp = x + (size_t)t * DM;
    float acc = 0.0f;
    for (int d = lane; d < DM; d += 32) acc += xp[d] * rw[d * EE + w];
    #pragma unroll
    for (int o = 16; o; o >>= 1) acc += __shfl_xor_sync(0xFFFFFFFFu, acc, o);
    if (lane == 0) logits[w] = acc + rb[w];
    __syncthreads();
    if (tid == 0) {
        float m = logits[0];
        #pragma unroll
        for (int e = 1; e < EE; e++) m = fmaxf(m, logits[e]);
        float p[EE], sum = 0.0f;
        #pragma unroll
        for (int e = 0; e < EE; e++) { p[e] = __expf(logits[e] - m); sum += p[e]; }
        float inv = 1.0f / sum;
        #pragma unroll
        for (int e = 0; e < EE; e++) { p[e] *= inv; atomicAdd(&g_imp[e], p[e]); }
        int i0 = 0;
        #pragma unroll
        for (int e = 1; e < EE; e++) if (p[e] > p[i0]) i0 = e;
        int i1 = (i0 == 0) ? 1 : 0;
        #pragma unroll
        for (int e = 0; e < EE; e++) if (e != i0 && p[e] > p[i1]) i1 = e;
        float g0 = p[i0], g1 = p[i1], gs = 1.0f / (g0 + g1);
        g0 *= gs; g1 *= gs;
        int pos = atomicAdd(&g_ecnt[i0], 1);
        g_elist[i0 * NTOK + pos] = t; g_egate[i0 * NTOK + pos] = g0;
        g_slot[i0 * NTOK + pos] = 2 * t;
        pos = atomicAdd(&g_ecnt[i1], 1);
        g_elist[i1 * NTOK + pos] = t; g_egate[i1 * NTOK + pos] = g1;
        g_slot[i1 * NTOK + pos] = 2 * t + 1;
    }
}

// ---------------- load-balance loss ----------------
__global__ void lb_kernel(float* __restrict__ out) {
    float lb = 0.0f;
    #pragma unroll
    for (int e = 0; e < EE; e++)
        lb += ((float)g_ecnt[e] / (float)(NTOK * 2)) * (g_imp[e] / (float)NTOK);
    out[0] = (float)EE * lb;
}

// ---------------- host launcher ----------------
extern "C" void kernel_launch(void* const* d_in, const int* in_sizes, int n_in,
                              void* d_out, int out_size)
{
    const float* tgt = (const float*)d_in[0];
    const float* mem = (const float*)d_in[1];
    const float *sa_wq, *sa_wk, *sa_wv, *sa_wo, *ca_wq, *ca_wk, *ca_wv, *ca_wo;
    const float *sa_bq, *sa_bk, *sa_bv, *sa_bo, *ca_bq, *ca_bk, *ca_bv, *ca_bo;
    const float *ln1g, *ln1b, *ln2g, *ln2b, *ln3g, *ln3b, *rw, *rb, *w1, *b1, *w2, *b2;

    if (in_sizes[5] == DM * DM) {
        sa_wq = (const float*)d_in[2];  sa_wk = (const float*)d_in[3];
        sa_wv = (const float*)d_in[4];  sa_wo = (const float*)d_in[5];
        ca_wq = (const float*)d_in[6];  ca_wk = (const float*)d_in[7];
        ca_wv = (const float*)d_in[8];  ca_wo = (const float*)d_in[9];
        sa_bq = (const float*)d_in[10]; sa_bk = (const float*)d_in[11];
        sa_bv = (const float*)d_in[12]; sa_bo = (const float*)d_in[13];
        ca_bq = (const float*)d_in[14]; ca_bk = (const float*)d_in[15];
        ca_bv = (const float*)d_in[16]; ca_bo = (const float*)d_in[17];
        ln1g = (const float*)d_in[18]; ln2g = (const float*)d_in[19]; ln3g = (const float*)d_in[20];
        ln1b = (const float*)d_in[21]; ln2b = (const float*)d_in[22]; ln3b = (const float*)d_in[23];
    } else {
        sa_wq = (const float*)d_in[2];  sa_wk = (const float*)d_in[3];
        sa_wv = (const float*)d_in[4];
        sa_bq = (const float*)d_in[5];  sa_bk = (const float*)d_in[6];
        sa_bv = (const float*)d_in[7];
        sa_wo = (const float*)d_in[8];  sa_bo = (const float*)d_in[9];
        ca_wq = (const float*)d_in[10]; ca_wk = (const float*)d_in[11];
        ca_wv = (const float*)d_in[12];
        ca_bq = (const float*)d_in[13]; ca_bk = (const float*)d_in[14];
        ca_bv = (const float*)d_in[15];
        ca_wo = (const float*)d_in[16]; ca_bo = (const float*)d_in[17];
        ln1g = (const float*)d_in[18]; ln1b = (const float*)d_in[19];
        ln2g = (const float*)d_in[20]; ln2b = (const float*)d_in[21];
        ln3g = (const float*)d_in[22]; ln3b = (const float*)d_in[23];
    }
    rw = (const float*)d_in[24]; rb = (const float*)d_in[25];
    w1 = (const float*)d_in[26]; b1 = (const float*)d_in[27];
    w2 = (const float*)d_in[28]; b2 = (const float*)d_in[29];

    float *wt, *q, *k, *v, *ctx, *attn, *t1, *t1t, *t2, *t2t;
    cudaGetSymbolAddress((void**)&wt,   g_wt);
    cudaGetSymbolAddress((void**)&q,    g_q);
    cudaGetSymbolAddress((void**)&k,    g_k);
    cudaGetSymbolAddress((void**)&v,    g_v);
    cudaGetSymbolAddress((void**)&ctx,  g_ctx);
    cudaGetSymbolAddress((void**)&attn, g_attn);
    cudaGetSymbolAddress((void**)&t1,   g_t1);
    cudaGetSymbolAddress((void**)&t1t,  g_t1t);
    cudaGetSymbolAddress((void**)&t2,   g_t2);
    cudaGetSymbolAddress((void**)&t2t,  g_t2t);

    const float* wt_saq = wt + 0 * PQ;
    const float* wt_sak = wt + 1 * PQ;
    const float* wt_sav = wt + 2 * PQ;
    const float* wt_sao = wt + 3 * PQ;
    const float* wt_caq = wt + 4 * PQ;
    const float* wt_cak = wt + 5 * PQ;
    const float* wt_cav = wt + 6 * PQ;
    const float* wt_cao = wt + 7 * PQ;
    const float* wt_w1  = wt + 8 * PQ;
    const float* wt_w2  = wt + 24 * PQ;
    const float* tgt_t  = wt + 40 * PQ;
    const float* mem_t  = wt + 42 * PQ;

    float* out = (float*)d_out;

    cudaFuncSetAttribute(proj_qkv_kernel, cudaFuncAttributeMaxDynamicSharedMemorySize, GEMM_SMEM);
    cudaFuncSetAttribute(moe1_kernel,     cudaFuncAttributeMaxDynamicSharedMemorySize, GEMM_SMEM);
    cudaFuncSetAttribute(moe2_kernel,     cudaFuncAttributeMaxDynamicSharedMemorySize, GEMM_SMEM);
    cudaFuncSetAttribute(attn_kernel,     cudaFuncAttributeMaxDynamicSharedMemorySize, ATTN_SMEM);

    dim3 gQKV(DM / BN, NTOK / BM, 3);
    dim3 gO  (DM / BN, NTOK / BM, 1);
    dim3 gAttn(TT / QT, HH, BB);
    dim3 gMoe1(FF / BN, NTOK / BM, EE);
    dim3 gMoe2(DM / BN, NTOK / BM, EE);
    dim3 gPrep(256, 12);

    zero_small_kernel<<<1, 32>>>();
    prep_kernel<<<gPrep, 256>>>(sa_wq, sa_wk, sa_wv, sa_wo, ca_wq, ca_wk, ca_wv, ca_wo,
                                w1, w2, tgt, mem);

    // ---- self attention ----
    proj_qkv_kernel<<<gQKV, 256, GEMM_SMEM>>>(tgt_t, tgt_t, tgt_t, wt_saq, wt_sak, wt_sav,
                                              sa_bq, sa_bk, sa_bv, q, k, v, DM, DM);
    attn_kernel<<<gAttn, 256, ATTN_SMEM>>>(q, k, v, ctx);
    proj_qkv_kernel<<<gO, 256, GEMM_SMEM>>>(ctx, ctx, ctx, wt_sao, wt_sao, wt_sao,
                                            sa_bo, sa_bo, sa_bo, attn, attn, attn, DM, DM);
    add_ln_kernel<<<NTOK, 256>>>(attn, tgt, ln1g, ln1b, t1, t1t);

    // ---- cross attention ----
    proj_qkv_kernel<<<gQKV, 256, GEMM_SMEM>>>(t1t, mem_t, mem_t, wt_caq, wt_cak, wt_cav,
                                              ca_bq, ca_bk, ca_bv, q, k, v, DM, DM);
    attn_kernel<<<gAttn, 256, ATTN_SMEM>>>(q, k, v, ctx);
    proj_qkv_kernel<<<gO, 256, GEMM_SMEM>>>(ctx, ctx, ctx, wt_cao, wt_cao, wt_cao,
                                            ca_bo, ca_bo, ca_bo, attn, attn, attn, DM, DM);
    add_ln_kernel<<<NTOK, 256>>>(attn, t1, ln2g, ln2b, t2, t2t);

    // ---- MoE (sparse top-2, slot-based scatter) ----
    router_kernel<<<NTOK, 256>>>(t2, rw, rb);
    moe1_kernel<<<gMoe1, 256, GEMM_SMEM>>>(t2t, wt_w1, b1);
    moe2_kernel<<<gMoe2, 256, GEMM_SMEM>>>(wt_w2, b2);
    add_ln_moe_kernel<<<NTOK, 256>>>(t2, ln3g, ln3b, out);

    if (out_size > NTOK * DM)
        lb_kernel<<<1, 1>>>(out + (size_t)NTOK * DM);
}

// round 5
// speedup vs baseline: 4.1755x; 1.2243x over previous
#include <cuda_runtime.h>
#include <cuda_bf16.h>
#include <math.h>
#include <stdint.h>

// ---------------- problem constants ----------------
#define BB   4
#define TT   512
#define DM   1024
#define HH   16
#define DH   64
#define FF   2048
#define EE   8
#define NTOK 2048
#define EPSL 1e-5f

// GEMM tiling
#define BM 128
#define BN 128
#define BKT 16
#define AS_STRIDE 20
#define BS_STRIDE 136
#define NSTAGE 3
#define A_ELEMS (BM * AS_STRIDE)
#define B_ELEMS (BKT * BS_STRIDE)
#define GEMM_SMEM (NSTAGE * (A_ELEMS + B_ELEMS) * 4)

// pre-converted (tf32-rounded) constant pool layout, units of floats
#define PQ 1048576ull
#define WT_TOTAL (44ull * PQ)

// ---------------- static scratch ----------------
__device__ float g_wt  [WT_TOTAL];
__device__ float g_q   [NTOK * DM];
__device__ float g_k   [NTOK * DM];
__device__ float g_v   [NTOK * DM];
__device__ float g_ctx [NTOK * DM];
__device__ float g_attn[NTOK * DM];
__device__ float g_t1  [NTOK * DM];
__device__ float g_t1t [NTOK * DM];
__device__ float g_t2  [NTOK * DM];
__device__ float g_t2t [NTOK * DM];
__device__ float g_ys  [NTOK * 2 * DM];
__device__ float g_h   [(size_t)EE * NTOK * FF];
__device__ int   g_elist[EE * NTOK];
__device__ int   g_slot [EE * NTOK];
__device__ float g_egate[EE * NTOK];
__device__ int   g_ecnt [EE];
__device__ float g_imp  [EE];

// ---------------- helpers ----------------
__device__ __forceinline__ uint32_t f2tf(float f) {
    uint32_t u;
    asm("cvt.rna.tf32.f32 %0, %1;" : "=r"(u) : "f"(f));
    return u;
}
__device__ __forceinline__ float tfr(float f) { return __uint_as_float(f2tf(f)); }

__device__ __forceinline__ void mma8(float* c, const uint32_t* a, const uint32_t* b) {
    asm volatile(
        "mma.sync.aligned.m16n8k8.row.col.f32.tf32.tf32.f32 "
        "{%0,%1,%2,%3}, {%4,%5,%6,%7}, {%8,%9}, {%0,%1,%2,%3};\n"
        : "+f"(c[0]), "+f"(c[1]), "+f"(c[2]), "+f"(c[3])
        : "r"(a[0]), "r"(a[1]), "r"(a[2]), "r"(a[3]), "r"(b[0]), "r"(b[1]));
}

__device__ __forceinline__ uint32_t smem_u32(const void* p) {
    return (uint32_t)__cvta_generic_to_shared(p);
}
__device__ __forceinline__ void cp16(uint32_t dst, const void* src, bool pred) {
    int sz = pred ? 16 : 0;
    asm volatile("cp.async.cg.shared.global [%0], [%1], 16, %2;\n"
                 :: "r"(dst), "l"(src), "r"(sz) : "memory");
}
#define CP_COMMIT  asm volatile("cp.async.commit_group;\n" ::: "memory")
#define CP_WAIT1   asm volatile("cp.async.wait_group 1;\n" ::: "memory")

__device__ __forceinline__ float block_reduce_sum(float v, float* red) {
    int lane = threadIdx.x & 31, w = threadIdx.x >> 5;
    #pragma unroll
    for (int o = 16; o; o >>= 1) v += __shfl_xor_sync(0xFFFFFFFFu, v, o);
    __syncthreads();
    if (lane == 0) red[w] = v;
    __syncthreads();
    if (w == 0) {
        v = (lane < ((int)blockDim.x >> 5)) ? red[lane] : 0.0f;
        #pragma unroll
        for (int o = 16; o; o >>= 1) v += __shfl_xor_sync(0xFFFFFFFFu, v, o);
        if (lane == 0) red[0] = v;
    }
    __syncthreads();
    return red[0];
}

// ---------------- tiny zero ----------------
__global__ void zero_small_kernel() {
    int i = threadIdx.x;
    if (i < EE) { g_ecnt[i] = 0; g_imp[i] = 0.0f; }
}

// ---------------- prep: tf32-round all static operands into g_wt ----------------
__global__ void prep_kernel(
    const float* s0, const float* s1, const float* s2, const float* s3,
    const float* s4, const float* s5, const float* s6, const float* s7,
    const float* s8, const float* s9, const float* s10, const float* s11)
{
    int r = blockIdx.y;
    const float* src; size_t off, cnt;
    switch (r) {
        case 0:  src = s0;  off = 0;       cnt = PQ;      break;
        case 1:  src = s1;  off = PQ;      cnt = PQ;      break;
        case 2:  src = s2;  off = 2 * PQ;  cnt = PQ;      break;
        case 3:  src = s3;  off = 3 * PQ;  cnt = PQ;      break;
        case 4:  src = s4;  off = 4 * PQ;  cnt = PQ;      break;
        case 5:  src = s5;  off = 5 * PQ;  cnt = PQ;      break;
        case 6:  src = s6;  off = 6 * PQ;  cnt = PQ;      break;
        case 7:  src = s7;  off = 7 * PQ;  cnt = PQ;      break;
        case 8:  src = s8;  off = 8 * PQ;  cnt = 16 * PQ; break;
        case 9:  src = s9;  off = 24 * PQ; cnt = 16 * PQ; break;
        case 10: src = s10; off = 40 * PQ; cnt = 2 * PQ;  break;
        default: src = s11; off = 42 * PQ; cnt = 2 * PQ;  break;
    }
    const float4* sp = (const float4*)src;
    float4* dp = (float4*)(g_wt + off);
    size_t n4 = cnt >> 2;
    for (size_t i = blockIdx.x * blockDim.x + threadIdx.x; i < n4;
         i += (size_t)gridDim.x * blockDim.x) {
        float4 v = sp[i];
        v.x = tfr(v.x); v.y = tfr(v.y); v.z = tfr(v.z); v.w = tfr(v.w);
        dp[i] = v;
    }
}

// ================= tf32 MMA GEMM core (cp.async pipelined) =================
template<int MODE>
__device__ __forceinline__ void gemm_core(
    const float* __restrict__ A, const float* __restrict__ W,
    const float* __restrict__ bias, float* __restrict__ C,
    int K, int N, int row0, int col0,
    const int* atoks, const int* slots, const float* gates)
{
    extern __shared__ uint32_t smp[];
    uint32_t* As = smp;
    uint32_t* Bs = smp + NSTAGE * A_ELEMS;

    const int tid  = threadIdx.x;
    const int lane = tid & 31;
    const int wid  = tid >> 5;
    const int wm   = wid >> 2;
    const int wn   = wid & 3;
    const int g    = lane >> 2;
    const int tig  = lane & 3;

    const int lr0 = tid >> 2;
    const int akq = (tid & 3) * 4;
    bool p0 = true, p1 = true;
    const float *a0p, *a1p;
    if (MODE == 1) {
        int t0 = atoks[lr0], t1 = atoks[lr0 + 64];
        p0 = (t0 >= 0); p1 = (t1 >= 0);
        a0p = A + (size_t)(p0 ? t0 : 0) * K + akq;
        a1p = A + (size_t)(p1 ? t1 : 0) * K + akq;
    } else {
        a0p = A + (size_t)(row0 + lr0) * K + akq;
        a1p = A + (size_t)(row0 + lr0 + 64) * K + akq;
    }

    const int kr = tid >> 4;
    const int nq = (tid & 15) * 8;
    const float* bp = W + (size_t)kr * N + col0 + nq;

    uint32_t sA0 = smem_u32(As) + (lr0 * AS_STRIDE + akq) * 4;
    uint32_t sA1 = sA0 + 64 * AS_STRIDE * 4;
    uint32_t sB0 = smem_u32(Bs) + (kr * BS_STRIDE + nq) * 4;

    const int nk = K / BKT;

#define ISSUE(b, kti) do {                                     \
        uint32_t ao = (uint32_t)(b) * (A_ELEMS * 4);           \
        cp16(sA0 + ao, a0p + (kti) * BKT, p0);                 \
        cp16(sA1 + ao, a1p + (kti) * BKT, p1);                 \
        const float* bs_ = bp + (size_t)(kti) * BKT * N;       \
        uint32_t bo = (uint32_t)(b) * (B_ELEMS * 4);           \
        cp16(sB0 + bo, bs_, true);                             \
        cp16(sB0 + bo + 16, bs_ + 4, true);                    \
    } while (0)

    ISSUE(0, 0); CP_COMMIT;
    ISSUE(1, 1); CP_COMMIT;

    float acc[4][4][4];
    #pragma unroll
    for (int i = 0; i < 4; i++)
        #pragma unroll
        for (int j = 0; j < 4; j++)
            #pragma unroll
            for (int r = 0; r < 4; r++) acc[i][j][r] = 0.0f;

    int buf = 0;
    for (int kt = 0; kt < nk; kt++) {
        CP_WAIT1;
        __syncthreads();
        if (kt + 2 < nk) {
            int nb = buf + 2; if (nb >= NSTAGE) nb -= NSTAGE;
            ISSUE(nb, kt + 2);
        }
        CP_COMMIT;

        const uint32_t* Ab = As + buf * A_ELEMS;
        const uint32_t* Bb = Bs + buf * B_ELEMS;
        #pragma unroll
        for (int k8 = 0; k8 < 2; k8++) {
            uint32_t af[4][4], bf[4][2];
            const uint32_t* abase = Ab + (wm * 64 + g) * AS_STRIDE + k8 * 8 + tig;
            #pragma unroll
            for (int mt = 0; mt < 4; mt++) {
                const uint32_t* p = abase + mt * 16 * AS_STRIDE;
                af[mt][0] = p[0];
                af[mt][1] = p[8 * AS_STRIDE];
                af[mt][2] = p[4];
                af[mt][3] = p[8 * AS_STRIDE + 4];
            }
            const uint32_t* bbase = Bb + (k8 * 8 + tig) * BS_STRIDE + wn * 32 + g;
            #pragma unroll
            for (int nt = 0; nt < 4; nt++) {
                bf[nt][0] = bbase[nt * 8];
                bf[nt][1] = bbase[4 * BS_STRIDE + nt * 8];
            }
            #pragma unroll
            for (int mt = 0; mt < 4; mt++)
                #pragma unroll
                for (int nt = 0; nt < 4; nt++)
                    mma8(acc[mt][nt], af[mt], bf[nt]);
        }
        buf = (buf == NSTAGE - 1) ? 0 : buf + 1;
    }
#undef ISSUE

    #pragma unroll
    for (int mt = 0; mt < 4; mt++) {
        const int lr = wm * 64 + mt * 16 + g;
        #pragma unroll
        for (int nt = 0; nt < 4; nt++) {
            float* ac = acc[mt][nt];
            const int c = col0 + wn * 32 + nt * 8 + 2 * tig;
            const float bc0 = bias[c], bc1 = bias[c + 1];
            if (MODE == 0) {
                *(float2*)&C[(size_t)(row0 + lr) * N + c]     = make_float2(ac[0] + bc0, ac[1] + bc1);
                *(float2*)&C[(size_t)(row0 + lr + 8) * N + c] = make_float2(ac[2] + bc0, ac[3] + bc1);
            } else if (MODE == 1) {
                if (atoks[lr] >= 0)
                    *(float2*)&C[(size_t)(row0 + lr) * N + c] = make_float2(
                        tfr(fmaxf(ac[0] + bc0, 0.f)), tfr(fmaxf(ac[1] + bc1, 0.f)));
                if (atoks[lr + 8] >= 0)
                    *(float2*)&C[(size_t)(row0 + lr + 8) * N + c] = make_float2(
                        tfr(fmaxf(ac[2] + bc0, 0.f)), tfr(fmaxf(ac[3] + bc1, 0.f)));
            } else {
                int sid = slots[lr]; float gt = gates[lr];
                if (sid >= 0)
                    *(float2*)&C[(size_t)sid * DM + c] =
                        make_float2(gt * (ac[0] + bc0), gt * (ac[1] + bc1));
                sid = slots[lr + 8]; gt = gates[lr + 8];
                if (sid >= 0)
                    *(float2*)&C[(size_t)sid * DM + c] =
                        make_float2(gt * (ac[2] + bc0), gt * (ac[3] + bc1));
            }
        }
    }
}

// ---------------- GEMM wrappers ----------------
__global__ __launch_bounds__(256, 2) void proj_qkv_kernel(
    const float* A0, const float* A1, const float* A2,
    const float* W0, const float* W1, const float* W2,
    const float* b0, const float* b1, const float* b2,
    float* C0, float* C1, float* C2, int K, int N)
{
    const int z = blockIdx.z;
    const float* A = (z == 0) ? A0 : (z == 1) ? A1 : A2;
    const float* W = (z == 0) ? W0 : (z == 1) ? W1 : W2;
    const float* b = (z == 0) ? b0 : (z == 1) ? b1 : b2;
    float*       C = (z == 0) ? C0 : (z == 1) ? C1 : C2;
    gemm_core<0>(A, W, b, C, K, N, blockIdx.y * BM, blockIdx.x * BN,
                 nullptr, nullptr, nullptr);
}

__global__ __launch_bounds__(256, 2) void moe1_kernel(
    const float* __restrict__ X, const float* __restrict__ w1,
    const float* __restrict__ b1)
{
    const int e = blockIdx.z;
    const int cnt = g_ecnt[e];
    const int row0 = blockIdx.y * BM;
    if (row0 >= cnt) return;
    __shared__ int toks[BM];
    if (threadIdx.x < BM) {
        int r = row0 + threadIdx.x;
        toks[threadIdx.x] = (r < cnt) ? g_elist[e * NTOK + r] : -1;
    }
    __syncthreads();
    gemm_core<1>(X, w1 + (size_t)e * DM * FF, b1 + e * FF,
                 g_h + (size_t)e * NTOK * FF,
                 DM, FF, row0, blockIdx.x * BN, toks, nullptr, nullptr);
}

__global__ __launch_bounds__(256, 2) void moe2_kernel(
    const float* __restrict__ w2, const float* __restrict__ b2)
{
    const int e = blockIdx.z;
    const int cnt = g_ecnt[e];
    const int row0 = blockIdx.y * BM;
    if (row0 >= cnt) return;
    __shared__ int slts[BM];
    __shared__ float gat[BM];
    if (threadIdx.x < BM) {
        int r = row0 + threadIdx.x;
        bool ok = (r < cnt);
        slts[threadIdx.x] = ok ? g_slot[e * NTOK + r] : -1;
        gat[threadIdx.x]  = ok ? g_egate[e * NTOK + r] : 0.0f;
    }
    __syncthreads();
    gemm_core<2>(g_h + (size_t)e * NTOK * FF, w2 + (size_t)e * FF * DM,
                 b2 + e * DM, g_ys,
                 FF, DM, row0, blockIdx.x * BN, nullptr, slts, gat);
}

// ---------------- tensor-core attention ----------------
// One block per (b, h, 32-q tile). 256 threads = 8 warps.
// smem: Qs[32][QSTR] tf32, KVs[128][VSTR] (K uses KSTR), S[32][SSTR] fp32.
#define AQT   32
#define KTILE 128
#define QSTR  68     // 64+4: A-frag reads conflict-free (4g+tig)
#define KSTR  68     // K tile, B-frag reads stride-per-g: 4g+tig ok
#define VSTR  72     // V tile, B-frag reads stride-per-tig: 8tig+g ok
#define SSTR  516    // 512+4: A-frag reads 4g+tig ok
#define ATC_SMEM ((AQT * QSTR + KTILE * VSTR + AQT * SSTR) * 4)

__global__ __launch_bounds__(256) void attn_tc_kernel(
    const float* __restrict__ Q, const float* __restrict__ Kk,
    const float* __restrict__ V, float* __restrict__ O)
{
    extern __shared__ float am[];
    float* Qs  = am;                         // [AQT][QSTR]
    float* KVs = am + AQT * QSTR;            // [KTILE][KSTR/VSTR]
    float* S   = KVs + KTILE * VSTR;         // [AQT][SSTR]

    const int q0  = blockIdx.x * AQT;
    const int h   = blockIdx.y;
    const int b   = blockIdx.z;
    const int tid = threadIdx.x;
    const int lane = tid & 31;
    const int wid  = tid >> 5;
    const int wm   = wid >> 2;     // 0..1 (m half)
    const int wn   = wid & 3;      // 0..3
    const int g    = lane >> 2;    // 0..7
    const int tig  = lane & 3;     // 0..3

    // ---- load Q (scaled, tf32) ----
    for (int i = tid; i < AQT * (DH / 4); i += 256) {
        int row = i >> 4, c4 = (i & 15) * 4;
        float4 qv = *(const float4*)&Q[((size_t)(b * TT + q0 + row)) * DM + h * DH + c4];
        float* qp = Qs + row * QSTR + c4;
        qp[0] = tfr(qv.x * 0.125f); qp[1] = tfr(qv.y * 0.125f);
        qp[2] = tfr(qv.z * 0.125f); qp[3] = tfr(qv.w * 0.125f);
    }
    __syncthreads();

    // ---- scores: S[32][512] = Q @ K^T ----
    for (int kt = 0; kt < TT / KTILE; kt++) {
        for (int i = tid; i < KTILE * (DH / 4); i += 256) {
            int row = i >> 4, c4 = (i & 15) * 4;
            float4 kv = *(const float4*)&Kk[((size_t)(b * TT + kt * KTILE + row)) * DM + h * DH + c4];
            float* kp = KVs + row * KSTR + c4;
            kp[0] = tfr(kv.x); kp[1] = tfr(kv.y); kp[2] = tfr(kv.z); kp[3] = tfr(kv.w);
        }
        __syncthreads();

        float c[4][4];
        #pragma unroll
        for (int nt = 0; nt < 4; nt++)
            #pragma unroll
            for (int r = 0; r < 4; r++) c[nt][r] = 0.0f;

        #pragma unroll
        for (int k8 = 0; k8 < DH / 8; k8++) {
            uint32_t af[4];
            const uint32_t* ab = (const uint32_t*)(Qs + (wm * 16 + g) * QSTR + k8 * 8 + tig);
            af[0] = ab[0]; af[1] = ab[8 * QSTR]; af[2] = ab[4]; af[3] = ab[8 * QSTR + 4];
            #pragma unroll
            for (int nt = 0; nt < 4; nt++) {
                const uint32_t* bb = (const uint32_t*)(KVs + (wn * 32 + nt * 8 + g) * KSTR + k8 * 8 + tig);
                uint32_t bf[2] = { bb[0], bb[4] };
                mma8(c[nt], af, bf);
            }
        }
        #pragma unroll
        for (int nt = 0; nt < 4; nt++) {
            int col = kt * KTILE + wn * 32 + nt * 8 + 2 * tig;
            float* s0 = S + (wm * 16 + g) * SSTR + col;
            float* s1 = S + (wm * 16 + g + 8) * SSTR + col;
            s0[0] = c[nt][0]; s0[1] = c[nt][1];
            s1[0] = c[nt][2]; s1[1] = c[nt][3];
        }
        __syncthreads();
    }

    // ---- softmax: warp wid owns rows [wid*4, wid*4+4) ----
    #pragma unroll
    for (int rr = 0; rr < AQT / 8; rr++) {
        int row = wid * (AQT / 8) + rr;
        float* sr = S + row * SSTR;
        float m = -1e30f;
        for (int j = lane; j < TT; j += 32) m = fmaxf(m, sr[j]);
        #pragma unroll
        for (int o = 16; o; o >>= 1) m = fmaxf(m, __shfl_xor_sync(0xFFFFFFFFu, m, o));
        float sum = 0.0f;
        for (int j = lane; j < TT; j += 32) { float ev = __expf(sr[j] - m); sr[j] = ev; sum += ev; }
        #pragma unroll
        for (int o = 16; o; o >>= 1) sum += __shfl_xor_sync(0xFFFFFFFFu, sum, o);
        float inv = 1.0f / sum;
        for (int j = lane; j < TT; j += 32) sr[j] = tfr(sr[j] * inv);
    }
    __syncthreads();

    // ---- PV: O[32][64] = P @ V ----
    float acc[2][4];
    #pragma unroll
    for (int nt = 0; nt < 2; nt++)
        #pragma unroll
        for (int r = 0; r < 4; r++) acc[nt][r] = 0.0f;

    for (int vt = 0; vt < TT / KTILE; vt++) {
        for (int i = tid; i < KTILE * (DH / 4); i += 256) {
            int row = i >> 4, c4 = (i & 15) * 4;
            float4 vv = *(const float4*)&V[((size_t)(b * TT + vt * KTILE + row)) * DM + h * DH + c4];
            float* vp = KVs + row * VSTR + c4;
            vp[0] = tfr(vv.x); vp[1] = tfr(vv.y); vp[2] = tfr(vv.z); vp[3] = tfr(vv.w);
        }
        __syncthreads();

        #pragma unroll
        for (int k8 = 0; k8 < KTILE / 8; k8++) {
            uint32_t af[4];
            const uint32_t* ab = (const uint32_t*)(S + (wm * 16 + g) * SSTR + vt * KTILE + k8 * 8 + tig);
            af[0] = ab[0]; af[1] = ab[8 * SSTR]; af[2] = ab[4]; af[3] = ab[8 * SSTR + 4];
            #pragma unroll
            for (int nt = 0; nt < 2; nt++) {
                const uint32_t* bb = (const uint32_t*)(KVs + (k8 * 8 + tig) * VSTR + wn * 16 + nt * 8 + g);
                uint32_t bf[2] = { bb[0], bb[4 * VSTR] };
                mma8(acc[nt], af, bf);
            }
        }
        __syncthreads();
    }

    // epilogue: write ctx (tf32-rounded, feeds O-projection GEMM)
    #pragma unroll
    for (int nt = 0; nt < 2; nt++) {
        int col = h * DH + wn * 16 + nt * 8 + 2 * tig;
        size_t r0 = (size_t)(b * TT + q0 + wm * 16 + g) * DM + col;
        size_t r1 = (size_t)(b * TT + q0 + wm * 16 + g + 8) * DM + col;
        O[r0]     = tfr(acc[nt][0]); O[r0 + 1] = tfr(acc[nt][1]);
        O[r1]     = tfr(acc[nt][2]); O[r1 + 1] = tfr(acc[nt][3]);
    }
}

// ---------------- add + layernorm (dual output: fp32 + tf32-rounded) ----------------
__global__ __launch_bounds__(256) void add_ln_kernel(
    const float* __restrict__ x, const float* __restrict__ r,
    const float* __restrict__ g, const float* __restrict__ be,
    float* __restrict__ out, float* __restrict__ out_t)
{
    __shared__ float red[32];
    __shared__ float s_mean, s_rstd;
    int row = blockIdx.x, tid = threadIdx.x;
    const float* xp = x + (size_t)row * DM;
    const float* rp = r + (size_t)row * DM;
    float v[4]; float sum = 0.0f;
    #pragma unroll
    for (int i = 0; i < 4; i++) { int idx = tid + i * 256; v[i] = xp[idx] + rp[idx]; sum += v[i]; }
    sum = block_reduce_sum(sum, red);
    if (tid == 0) s_mean = sum * (1.0f / DM);
    __syncthreads();
    float mean = s_mean, vs = 0.0f;
    #pragma unroll
    for (int i = 0; i < 4; i++) { float dv = v[i] - mean; vs += dv * dv; }
    vs = block_reduce_sum(vs, red);
    if (tid == 0) s_rstd = rsqrtf(vs * (1.0f / DM) + EPSL);
    __syncthreads();
    float rs = s_rstd;
    #pragma unroll
    for (int i = 0; i < 4; i++) {
        int idx = tid + i * 256;
        float o = (v[i] - mean) * rs * g[idx] + be[idx];
        out[(size_t)row * DM + idx] = o;
        if (out_t) out_t[(size_t)row * DM + idx] = tfr(o);
    }
}

// ---------------- final add + layernorm over expert slots ----------------
__global__ __launch_bounds__(256) void add_ln_moe_kernel(
    const float* __restrict__ r, const float* __restrict__ g,
    const float* __restrict__ be, float* __restrict__ out)
{
    __shared__ float red[32];
    __shared__ float s_mean, s_rstd;
    int row = blockIdx.x, tid = threadIdx.x;
    const float* y0 = g_ys + (size_t)(row * 2) * DM;
    const float* y1 = y0 + DM;
    const float* rp = r + (size_t)row * DM;
    float v[4]; float sum = 0.0f;
    #pragma unroll
    for (int i = 0; i < 4; i++) {
        int idx = tid + i * 256;
        v[i] = y0[idx] + y1[idx] + rp[idx];
        sum += v[i];
    }
    sum = block_reduce_sum(sum, red);
    if (tid == 0) s_mean = sum * (1.0f / DM);
    __syncthreads();
    float mean = s_mean, vs = 0.0f;
    #pragma unroll
    for (int i = 0; i < 4; i++) { float dv = v[i] - mean; vs += dv * dv; }
    vs = block_reduce_sum(vs, red);
    if (tid == 0) s_rstd = rsqrtf(vs * (1.0f / DM) + EPSL);
    __syncthreads();
    float rs = s_rstd;
    #pragma unroll
    for (int i = 0; i < 4; i++) {
        int idx = tid + i * 256;
        out[(size_t)row * DM + idx] = (v[i] - mean) * rs * g[idx] + be[idx];
    }
}

// ---------------- router ----------------
__global__ __launch_bounds__(256) void router_kernel(
    const float* __restrict__ x, const float* __restrict__ rw,
    const float* __restrict__ rb)
{
    int t = blockIdx.x;
    int tid = threadIdx.x, lane = tid & 31, w = tid >> 5;
    __shared__ float logits[EE];
    const float* xp = x + (size_t)t * DM;
    float acc = 0.0f;
    for (int d = lane; d < DM; d += 32) acc += xp[d] * rw[d * EE + w];
    #pragma unroll
    for (int o = 16; o; o >>= 1) acc += __shfl_xor_sync(0xFFFFFFFFu, acc, o);
    if (lane == 0) logits[w] = acc + rb[w];
    __syncthreads();
    if (tid == 0) {
        float m = logits[0];
        #pragma unroll
        for (int e = 1; e < EE; e++) m = fmaxf(m, logits[e]);
        float p[EE], sum = 0.0f;
        #pragma unroll
        for (int e = 0; e < EE; e++) { p[e] = __expf(logits[e] - m); sum += p[e]; }
        float inv = 1.0f / sum;
        #pragma unroll
        for (int e = 0; e < EE; e++) { p[e] *= inv; atomicAdd(&g_imp[e], p[e]); }
        int i0 = 0;
        #pragma unroll
        for (int e = 1; e < EE; e++) if (p[e] > p[i0]) i0 = e;
        int i1 = (i0 == 0) ? 1 : 0;
        #pragma unroll
        for (int e = 0; e < EE; e++) if (e != i0 && p[e] > p[i1]) i1 = e;
        float g0 = p[i0], g1 = p[i1], gs = 1.0f / (g0 + g1);
        g0 *= gs; g1 *= gs;
        int pos = atomicAdd(&g_ecnt[i0], 1);
        g_elist[i0 * NTOK + pos] = t; g_egate[i0 * NTOK + pos] = g0;
        g_slot[i0 * NTOK + pos] = 2 * t;
        pos = atomicAdd(&g_ecnt[i1], 1);
        g_elist[i1 * NTOK + pos] = t; g_egate[i1 * NTOK + pos] = g1;
        g_slot[i1 * NTOK + pos] = 2 * t + 1;
    }
}

// ---------------- load-balance loss ----------------
__global__ void lb_kernel(float* __restrict__ out) {
    float lb = 0.0f;
    #pragma unroll
    for (int e = 0; e < EE; e++)
        lb += ((float)g_ecnt[e] / (float)(NTOK * 2)) * (g_imp[e] / (float)NTOK);
    out[0] = (float)EE * lb;
}

// ---------------- host launcher ----------------
extern "C" void kernel_launch(void* const* d_in, const int* in_sizes, int n_in,
                              void* d_out, int out_size)
{
    const float* tgt = (const float*)d_in[0];
    const float* mem = (const float*)d_in[1];
    const float *sa_wq, *sa_wk, *sa_wv, *sa_wo, *ca_wq, *ca_wk, *ca_wv, *ca_wo;
    const float *sa_bq, *sa_bk, *sa_bv, *sa_bo, *ca_bq, *ca_bk, *ca_bv, *ca_bo;
    const float *ln1g, *ln1b, *ln2g, *ln2b, *ln3g, *ln3b, *rw, *rb, *w1, *b1, *w2, *b2;

    if (in_sizes[5] == DM * DM) {
        sa_wq = (const float*)d_in[2];  sa_wk = (const float*)d_in[3];
        sa_wv = (const float*)d_in[4];  sa_wo = (const float*)d_in[5];
        ca_wq = (const float*)d_in[6];  ca_wk = (const float*)d_in[7];
        ca_wv = (const float*)d_in[8];  ca_wo = (const float*)d_in[9];
        sa_bq = (const float*)d_in[10]; sa_bk = (const float*)d_in[11];
        sa_bv = (const float*)d_in[12]; sa_bo = (const float*)d_in[13];
        ca_bq = (const float*)d_in[14]; ca_bk = (const float*)d_in[15];
        ca_bv = (const float*)d_in[16]; ca_bo = (const float*)d_in[17];
        ln1g = (const float*)d_in[18]; ln2g = (const float*)d_in[19]; ln3g = (const float*)d_in[20];
        ln1b = (const float*)d_in[21]; ln2b = (const float*)d_in[22]; ln3b = (const float*)d_in[23];
    } else {
        sa_wq = (const float*)d_in[2];  sa_wk = (const float*)d_in[3];
        sa_wv = (const float*)d_in[4];
        sa_bq = (const float*)d_in[5];  sa_bk = (const float*)d_in[6];
        sa_bv = (const float*)d_in[7];
        sa_wo = (const float*)d_in[8];  sa_bo = (const float*)d_in[9];
        ca_wq = (const float*)d_in[10]; ca_wk = (const float*)d_in[11];
        ca_wv = (const float*)d_in[12];
        ca_bq = (const float*)d_in[13]; ca_bk = (const float*)d_in[14];
        ca_bv = (const float*)d_in[15];
        ca_wo = (const float*)d_in[16]; ca_bo = (const float*)d_in[17];
        ln1g = (const float*)d_in[18]; ln1b = (const float*)d_in[19];
        ln2g = (const float*)d_in[20]; ln2b = (const float*)d_in[21];
        ln3g = (const float*)d_in[22]; ln3b = (const float*)d_in[23];
    }
    rw = (const float*)d_in[24]; rb = (const float*)d_in[25];
    w1 = (const float*)d_in[26]; b1 = (const float*)d_in[27];
    w2 = (const float*)d_in[28]; b2 = (const float*)d_in[29];

    float *wt, *q, *k, *v, *ctx, *attn, *t1, *t1t, *t2, *t2t;
    cudaGetSymbolAddress((void**)&wt,   g_wt);
    cudaGetSymbolAddress((void**)&q,    g_q);
    cudaGetSymbolAddress((void**)&k,    g_k);
    cudaGetSymbolAddress((void**)&v,    g_v);
    cudaGetSymbolAddress((void**)&ctx,  g_ctx);
    cudaGetSymbolAddress((void**)&attn, g_attn);
    cudaGetSymbolAddress((void**)&t1,   g_t1);
    cudaGetSymbolAddress((void**)&t1t,  g_t1t);
    cudaGetSymbolAddress((void**)&t2,   g_t2);
    cudaGetSymbolAddress((void**)&t2t,  g_t2t);

    const float* wt_saq = wt + 0 * PQ;
    const float* wt_sak = wt + 1 * PQ;
    const float* wt_sav = wt + 2 * PQ;
    const float* wt_sao = wt + 3 * PQ;
    const float* wt_caq = wt + 4 * PQ;
    const float* wt_cak = wt + 5 * PQ;
    const float* wt_cav = wt + 6 * PQ;
    const float* wt_cao = wt + 7 * PQ;
    const float* wt_w1  = wt + 8 * PQ;
    const float* wt_w2  = wt + 24 * PQ;
    const float* tgt_t  = wt + 40 * PQ;
    const float* mem_t  = wt + 42 * PQ;

    float* out = (float*)d_out;

    cudaFuncSetAttribute(proj_qkv_kernel, cudaFuncAttributeMaxDynamicSharedMemorySize, GEMM_SMEM);
    cudaFuncSetAttribute(moe1_kernel,     cudaFuncAttributeMaxDynamicSharedMemorySize, GEMM_SMEM);
    cudaFuncSetAttribute(moe2_kernel,     cudaFuncAttributeMaxDynamicSharedMemorySize, GEMM_SMEM);
    cudaFuncSetAttribute(attn_tc_kernel,  cudaFuncAttributeMaxDynamicSharedMemorySize, ATC_SMEM);

    dim3 gQKV(DM / BN, NTOK / BM, 3);
    dim3 gO  (DM / BN, NTOK / BM, 1);
    dim3 gAttn(TT / AQT, HH, BB);          // (16, 16, 4)
    dim3 gMoe1(FF / BN, NTOK / BM, EE);
    dim3 gMoe2(DM / BN, NTOK / BM, EE);
    dim3 gPrep(256, 12);

    zero_small_kernel<<<1, 32>>>();
    prep_kernel<<<gPrep, 256>>>(sa_wq, sa_wk, sa_wv, sa_wo, ca_wq, ca_wk, ca_wv, ca_wo,
                                w1, w2, tgt, mem);

    // ---- self attention ----
    proj_qkv_kernel<<<gQKV, 256, GEMM_SMEM>>>(tgt_t, tgt_t, tgt_t, wt_saq, wt_sak, wt_sav,
                                              sa_bq, sa_bk, sa_bv, q, k, v, DM, DM);
    attn_tc_kernel<<<gAttn, 256, ATC_SMEM>>>(q, k, v, ctx);
    proj_qkv_kernel<<<gO, 256, GEMM_SMEM>>>(ctx, ctx, ctx, wt_sao, wt_sao, wt_sao,
                                            sa_bo, sa_bo, sa_bo, attn, attn, attn, DM, DM);
    add_ln_kernel<<<NTOK, 256>>>(attn, tgt, ln1g, ln1b, t1, t1t);

    // ---- cross attention ----
    proj_qkv_kernel<<<gQKV, 256, GEMM_SMEM>>>(t1t, mem_t, mem_t, wt_caq, wt_cak, wt_cav,
                                              ca_bq, ca_bk, ca_bv, q, k, v, DM, DM);
    attn_tc_kernel<<<gAttn, 256, ATC_SMEM>>>(q, k, v, ctx);
    proj_qkv_kernel<<<gO, 256, GEMM_SMEM>>>(ctx, ctx, ctx, wt_cao, wt_cao, wt_cao,
                                            ca_bo, ca_bo, ca_bo, attn, attn, attn, DM, DM);
    add_ln_kernel<<<NTOK, 256>>>(attn, t1, ln2g, ln2b, t2, t2t);

    // ---- MoE (sparse top-2, slot-based scatter) ----
    router_kernel<<<NTOK, 256>>>(t2, rw, rb);
    moe1_kernel<<<gMoe1, 256, GEMM_SMEM>>>(t2t, wt_w1, b1);
    moe2_kernel<<<gMoe2, 256, GEMM_SMEM>>>(wt_w2, b2);
    add_ln_moe_kernel<<<NTOK, 256>>>(t2, ln3g, ln3b, out);

    if (out_size > NTOK * DM)
        lb_kernel<<<1, 1>>>(out + (size_t)NTOK * DM);
}

// round 7
// speedup vs baseline: 4.2612x; 1.0205x over previous
#include <cuda_runtime.h>
#include <cuda_bf16.h>
#include <math.h>
#include <stdint.h>

// ---------------- problem constants ----------------
#define BB   4
#define TT   512
#define DM   1024
#define HH   16
#define DH   64
#define FF   2048
#define EE   8
#define NTOK 2048
#define EPSL 1e-5f

// GEMM tiling
#define BM 128
#define BN 128
#define BKT 16
#define AS_STRIDE 20
#define BS_STRIDE 136
#define NSTAGE 3
#define A_ELEMS (BM * AS_STRIDE)
#define B_ELEMS (BKT * BS_STRIDE)
#define GEMM_SMEM (NSTAGE * (A_ELEMS + B_ELEMS) * 4)

// pre-converted (tf32-rounded) constant pool layout, units of floats
#define PQ 1048576ull
#define WT_TOTAL (44ull * PQ)

// ---------------- static scratch ----------------
__device__ float g_wt  [WT_TOTAL];
__device__ float g_q   [NTOK * DM];
__device__ float g_k   [NTOK * DM];
__device__ float g_v   [NTOK * DM];
__device__ float g_ctx [NTOK * DM];
__device__ float g_attn[NTOK * DM];
__device__ float g_t1  [NTOK * DM];
__device__ float g_t1t [NTOK * DM];
__device__ float g_t2  [NTOK * DM];
__device__ float g_t2t [NTOK * DM];
__device__ float g_ys  [NTOK * 2 * DM];
__device__ float g_h   [(size_t)EE * NTOK * FF];
__device__ int   g_elist[EE * NTOK];
__device__ int   g_slot [EE * NTOK];
__device__ float g_egate[EE * NTOK];
__device__ int   g_ecnt [EE];
__device__ float g_imp  [EE];

// ---------------- helpers ----------------
__device__ __forceinline__ uint32_t f2tf(float f) {
    uint32_t u;
    asm("cvt.rna.tf32.f32 %0, %1;" : "=r"(u) : "f"(f));
    return u;
}
__device__ __forceinline__ float tfr(float f) { return __uint_as_float(f2tf(f)); }

__device__ __forceinline__ void mma8(float* c, const uint32_t* a, const uint32_t* b) {
    asm volatile(
        "mma.sync.aligned.m16n8k8.row.col.f32.tf32.tf32.f32 "
        "{%0,%1,%2,%3}, {%4,%5,%6,%7}, {%8,%9}, {%0,%1,%2,%3};\n"
        : "+f"(c[0]), "+f"(c[1]), "+f"(c[2]), "+f"(c[3])
        : "r"(a[0]), "r"(a[1]), "r"(a[2]), "r"(a[3]), "r"(b[0]), "r"(b[1]));
}

__device__ __forceinline__ uint32_t smem_u32(const void* p) {
    return (uint32_t)__cvta_generic_to_shared(p);
}
__device__ __forceinline__ void cp16(uint32_t dst, const void* src, bool pred) {
    int sz = pred ? 16 : 0;
    asm volatile("cp.async.cg.shared.global [%0], [%1], 16, %2;\n"
                 :: "r"(dst), "l"(src), "r"(sz) : "memory");
}
#define CP_COMMIT  asm volatile("cp.async.commit_group;\n" ::: "memory")
#define CP_WAIT1   asm volatile("cp.async.wait_group 1;\n" ::: "memory")
#define CP_WAIT0   asm volatile("cp.async.wait_group 0;\n" ::: "memory")

__device__ __forceinline__ float block_reduce_sum(float v, float* red) {
    int lane = threadIdx.x & 31, w = threadIdx.x >> 5;
    #pragma unroll
    for (int o = 16; o; o >>= 1) v += __shfl_xor_sync(0xFFFFFFFFu, v, o);
    __syncthreads();
    if (lane == 0) red[w] = v;
    __syncthreads();
    if (w == 0) {
        v = (lane < ((int)blockDim.x >> 5)) ? red[lane] : 0.0f;
        #pragma unroll
        for (int o = 16; o; o >>= 1) v += __shfl_xor_sync(0xFFFFFFFFu, v, o);
        if (lane == 0) red[0] = v;
    }
    __syncthreads();
    return red[0];
}

// ---------------- tiny zero ----------------
__global__ void zero_small_kernel() {
    int i = threadIdx.x;
    if (i < EE) { g_ecnt[i] = 0; g_imp[i] = 0.0f; }
}

// ---------------- prep: tf32-round all static operands into g_wt ----------------
__global__ void prep_kernel(
    const float* s0, const float* s1, const float* s2, const float* s3,
    const float* s4, const float* s5, const float* s6, const float* s7,
    const float* s8, const float* s9, const float* s10, const float* s11)
{
    int r = blockIdx.y;
    const float* src; size_t off, cnt;
    switch (r) {
        case 0:  src = s0;  off = 0;       cnt = PQ;      break;
        case 1:  src = s1;  off = PQ;      cnt = PQ;      break;
        case 2:  src = s2;  off = 2 * PQ;  cnt = PQ;      break;
        case 3:  src = s3;  off = 3 * PQ;  cnt = PQ;      break;
        case 4:  src = s4;  off = 4 * PQ;  cnt = PQ;      break;
        case 5:  src = s5;  off = 5 * PQ;  cnt = PQ;      break;
        case 6:  src = s6;  off = 6 * PQ;  cnt = PQ;      break;
        case 7:  src = s7;  off = 7 * PQ;  cnt = PQ;      break;
        case 8:  src = s8;  off = 8 * PQ;  cnt = 16 * PQ; break;
        case 9:  src = s9;  off = 24 * PQ; cnt = 16 * PQ; break;
        case 10: src = s10; off = 40 * PQ; cnt = 2 * PQ;  break;
        default: src = s11; off = 42 * PQ; cnt = 2 * PQ;  break;
    }
    const float4* sp = (const float4*)src;
    float4* dp = (float4*)(g_wt + off);
    size_t n4 = cnt >> 2;
    for (size_t i = blockIdx.x * blockDim.x + threadIdx.x; i < n4;
         i += (size_t)gridDim.x * blockDim.x) {
        float4 v = sp[i];
        v.x = tfr(v.x); v.y = tfr(v.y); v.z = tfr(v.z); v.w = tfr(v.w);
        dp[i] = v;
    }
}

// ================= tf32 MMA GEMM core (cp.async pipelined) =================
// MODE 0: plain proj; MODE 1: moe gather+relu+round; MODE 2: moe slot-scatter;
// MODE 3: proj with tf32-rounded output
template<int MODE>
__device__ __forceinline__ void gemm_core(
    const float* __restrict__ A, const float* __restrict__ W,
    const float* __restrict__ bias, float* __restrict__ C,
    int K, int N, int row0, int col0,
    const int* atoks, const int* slots, const float* gates)
{
    extern __shared__ uint32_t smp[];
    uint32_t* As = smp;
    uint32_t* Bs = smp + NSTAGE * A_ELEMS;

    const int tid  = threadIdx.x;
    const int lane = tid & 31;
    const int wid  = tid >> 5;
    const int wm   = wid >> 2;
    const int wn   = wid & 3;
    const int g    = lane >> 2;
    const int tig  = lane & 3;

    const int lr0 = tid >> 2;
    const int akq = (tid & 3) * 4;
    bool p0 = true, p1 = true;
    const float *a0p, *a1p;
    if (MODE == 1) {
        int t0 = atoks[lr0], t1 = atoks[lr0 + 64];
        p0 = (t0 >= 0); p1 = (t1 >= 0);
        a0p = A + (size_t)(p0 ? t0 : 0) * K + akq;
        a1p = A + (size_t)(p1 ? t1 : 0) * K + akq;
    } else {
        a0p = A + (size_t)(row0 + lr0) * K + akq;
        a1p = A + (size_t)(row0 + lr0 + 64) * K + akq;
    }

    const int kr = tid >> 4;
    const int nq = (tid & 15) * 8;
    const float* bp = W + (size_t)kr * N + col0 + nq;

    uint32_t sA0 = smem_u32(As) + (lr0 * AS_STRIDE + akq) * 4;
    uint32_t sA1 = sA0 + 64 * AS_STRIDE * 4;
    uint32_t sB0 = smem_u32(Bs) + (kr * BS_STRIDE + nq) * 4;

    const int nk = K / BKT;

#define ISSUE(b, kti) do {                                     \
        uint32_t ao = (uint32_t)(b) * (A_ELEMS * 4);           \
        cp16(sA0 + ao, a0p + (kti) * BKT, p0);                 \
        cp16(sA1 + ao, a1p + (kti) * BKT, p1);                 \
        const float* bs_ = bp + (size_t)(kti) * BKT * N;       \
        uint32_t bo = (uint32_t)(b) * (B_ELEMS * 4);           \
        cp16(sB0 + bo, bs_, true);                             \
        cp16(sB0 + bo + 16, bs_ + 4, true);                    \
    } while (0)

    ISSUE(0, 0); CP_COMMIT;
    ISSUE(1, 1); CP_COMMIT;

    float acc[4][4][4];
    #pragma unroll
    for (int i = 0; i < 4; i++)
        #pragma unroll
        for (int j = 0; j < 4; j++)
            #pragma unroll
            for (int r = 0; r < 4; r++) acc[i][j][r] = 0.0f;

    int buf = 0;
    for (int kt = 0; kt < nk; kt++) {
        CP_WAIT1;
        __syncthreads();
        if (kt + 2 < nk) {
            int nb = buf + 2; if (nb >= NSTAGE) nb -= NSTAGE;
            ISSUE(nb, kt + 2);
        }
        CP_COMMIT;

        const uint32_t* Ab = As + buf * A_ELEMS;
        const uint32_t* Bb = Bs + buf * B_ELEMS;
        #pragma unroll
        for (int k8 = 0; k8 < 2; k8++) {
            uint32_t af[4][4], bf[4][2];
            const uint32_t* abase = Ab + (wm * 64 + g) * AS_STRIDE + k8 * 8 + tig;
            #pragma unroll
            for (int mt = 0; mt < 4; mt++) {
                const uint32_t* p = abase + mt * 16 * AS_STRIDE;
                af[mt][0] = p[0];
                af[mt][1] = p[8 * AS_STRIDE];
                af[mt][2] = p[4];
                af[mt][3] = p[8 * AS_STRIDE + 4];
            }
            const uint32_t* bbase = Bb + (k8 * 8 + tig) * BS_STRIDE + wn * 32 + g;
            #pragma unroll
            for (int nt = 0; nt < 4; nt++) {
                bf[nt][0] = bbase[nt * 8];
                bf[nt][1] = bbase[4 * BS_STRIDE + nt * 8];
            }
            #pragma unroll
            for (int mt = 0; mt < 4; mt++)
                #pragma unroll
                for (int nt = 0; nt < 4; nt++)
                    mma8(acc[mt][nt], af[mt], bf[nt]);
        }
        buf = (buf == NSTAGE - 1) ? 0 : buf + 1;
    }
#undef ISSUE

    #pragma unroll
    for (int mt = 0; mt < 4; mt++) {
        const int lr = wm * 64 + mt * 16 + g;
        #pragma unroll
        for (int nt = 0; nt < 4; nt++) {
            float* ac = acc[mt][nt];
            const int c = col0 + wn * 32 + nt * 8 + 2 * tig;
            const float bc0 = bias[c], bc1 = bias[c + 1];
            if (MODE == 0) {
                *(float2*)&C[(size_t)(row0 + lr) * N + c]     = make_float2(ac[0] + bc0, ac[1] + bc1);
                *(float2*)&C[(size_t)(row0 + lr + 8) * N + c] = make_float2(ac[2] + bc0, ac[3] + bc1);
            } else if (MODE == 3) {
                *(float2*)&C[(size_t)(row0 + lr) * N + c]     = make_float2(tfr(ac[0] + bc0), tfr(ac[1] + bc1));
                *(float2*)&C[(size_t)(row0 + lr + 8) * N + c] = make_float2(tfr(ac[2] + bc0), tfr(ac[3] + bc1));
            } else if (MODE == 1) {
                if (atoks[lr] >= 0)
                    *(float2*)&C[(size_t)(row0 + lr) * N + c] = make_float2(
                        tfr(fmaxf(ac[0] + bc0, 0.f)), tfr(fmaxf(ac[1] + bc1, 0.f)));
                if (atoks[lr + 8] >= 0)
                    *(float2*)&C[(size_t)(row0 + lr + 8) * N + c] = make_float2(
                        tfr(fmaxf(ac[2] + bc0, 0.f)), tfr(fmaxf(ac[3] + bc1, 0.f)));
            } else {
                int sid = slots[lr]; float gt = gates[lr];
                if (sid >= 0)
                    *(float2*)&C[(size_t)sid * DM + c] =
                        make_float2(gt * (ac[0] + bc0), gt * (ac[1] + bc1));
                sid = slots[lr + 8]; gt = gates[lr + 8];
                if (sid >= 0)
                    *(float2*)&C[(size_t)sid * DM + c] =
                        make_float2(gt * (ac[2] + bc0), gt * (ac[3] + bc1));
            }
        }
    }
}

// ---------------- GEMM wrappers ----------------
__global__ __launch_bounds__(256, 2) void proj_qkv_kernel(
    const float* A0, const float* A1, const float* A2,
    const float* W0, const float* W1, const float* W2,
    const float* b0, const float* b1, const float* b2,
    float* C0, float* C1, float* C2, int K, int N)
{
    const int z = blockIdx.z;
    const float* A = (z == 0) ? A0 : (z == 1) ? A1 : A2;
    const float* W = (z == 0) ? W0 : (z == 1) ? W1 : W2;
    const float* b = (z == 0) ? b0 : (z == 1) ? b1 : b2;
    float*       C = (z == 0) ? C0 : (z == 1) ? C1 : C2;
    gemm_core<0>(A, W, b, C, K, N, blockIdx.y * BM, blockIdx.x * BN,
                 nullptr, nullptr, nullptr);
}

__global__ __launch_bounds__(256, 2) void proj_qkvr_kernel(
    const float* A0, const float* A1, const float* A2,
    const float* W0, const float* W1, const float* W2,
    const float* b0, const float* b1, const float* b2,
    float* C0, float* C1, float* C2, int K, int N)
{
    const int z = blockIdx.z;
    const float* A = (z == 0) ? A0 : (z == 1) ? A1 : A2;
    const float* W = (z == 0) ? W0 : (z == 1) ? W1 : W2;
    const float* b = (z == 0) ? b0 : (z == 1) ? b1 : b2;
    float*       C = (z == 0) ? C0 : (z == 1) ? C1 : C2;
    gemm_core<3>(A, W, b, C, K, N, blockIdx.y * BM, blockIdx.x * BN,
                 nullptr, nullptr, nullptr);
}

__global__ __launch_bounds__(256, 2) void moe1_kernel(
    const float* __restrict__ X, const float* __restrict__ w1,
    const float* __restrict__ b1)
{
    const int e = blockIdx.z;
    const int cnt = g_ecnt[e];
    const int row0 = blockIdx.y * BM;
    if (row0 >= cnt) return;
    __shared__ int toks[BM];
    if (threadIdx.x < BM) {
        int r = row0 + threadIdx.x;
        toks[threadIdx.x] = (r < cnt) ? g_elist[e * NTOK + r] : -1;
    }
    __syncthreads();
    gemm_core<1>(X, w1 + (size_t)e * DM * FF, b1 + e * FF,
                 g_h + (size_t)e * NTOK * FF,
                 DM, FF, row0, blockIdx.x * BN, toks, nullptr, nullptr);
}

__global__ __launch_bounds__(256, 2) void moe2_kernel(
    const float* __restrict__ w2, const float* __restrict__ b2)
{
    const int e = blockIdx.z;
    const int cnt = g_ecnt[e];
    const int row0 = blockIdx.y * BM;
    if (row0 >= cnt) return;
    __shared__ int slts[BM];
    __shared__ float gat[BM];
    if (threadIdx.x < BM) {
        int r = row0 + threadIdx.x;
        bool ok = (r < cnt);
        slts[threadIdx.x] = ok ? g_slot[e * NTOK + r] : -1;
        gat[threadIdx.x]  = ok ? g_egate[e * NTOK + r] : 0.0f;
    }
    __syncthreads();
    gemm_core<2>(g_h + (size_t)e * NTOK * FF, w2 + (size_t)e * FF * DM,
                 b2 + e * DM, g_ys,
                 FF, DM, row0, blockIdx.x * BN, nullptr, slts, gat);
}

// ---------------- tensor-core attention (cp.async, double-buffered) ----------------
// One block per (b, h, 32-q tile). 256 threads = 8 warps (2m x 4n).
// Inputs Q/K/V pre-rounded to tf32 by proj_qkvr.
#define AQT   32
#define KT2   64
#define QSTR  68
#define KSTR  68
#define VSTR  72
#define KVBUF (KT2 * VSTR)     // 4608 floats per buffer
#define SSTR  516
#define ATC_SMEM ((AQT * QSTR + 2 * KVBUF + AQT * SSTR) * 4)   // 111616 B

__global__ __launch_bounds__(256, 2) void attn_tc_kernel(
    const float* __restrict__ Q, const float* __restrict__ Kk,
    const float* __restrict__ V, float* __restrict__ O)
{
    extern __shared__ float am[];
    float* Qs = am;                      // [AQT][QSTR]
    float* KV = am + AQT * QSTR;         // [2][KVBUF]
    float* S  = KV + 2 * KVBUF;          // [AQT][SSTR]

    const int q0  = blockIdx.x * AQT;
    const int h   = blockIdx.y;
    const int b   = blockIdx.z;
    const int tid = threadIdx.x;
    const int lane = tid & 31;
    const int wid  = tid >> 5;
    const int wm   = wid >> 2;     // 0..1
    const int wn   = wid & 3;      // 0..3
    const int g    = lane >> 2;    // 0..7
    const int tig  = lane & 3;     // 0..3

    // loader mapping: 4 x cp16 (16 floats) per thread per tile
    const int lrow = tid >> 2;             // 0..63 (key row in tile)
    const int lc   = (tid & 3) * 16;       // float offset in row
    const float* ksrc = Kk + ((size_t)(b * TT) + lrow) * DM + h * DH + lc;
    const float* vsrc = V  + ((size_t)(b * TT) + lrow) * DM + h * DH + lc;
    uint32_t kdst = smem_u32(KV) + (lrow * KSTR + lc) * 4;
    uint32_t vdst = smem_u32(KV) + (lrow * VSTR + lc) * 4;

#define ISSUE_K(bf_, kt_) do {                                         \
        const float* s_ = ksrc + (size_t)(kt_) * KT2 * DM;             \
        uint32_t d_ = kdst + (uint32_t)(bf_) * (KVBUF * 4);            \
        cp16(d_,      s_,      true); cp16(d_ + 16, s_ + 4,  true);    \
        cp16(d_ + 32, s_ + 8,  true); cp16(d_ + 48, s_ + 12, true);    \
    } while (0)
#define ISSUE_V(bf_, kt_) do {                                         \
        const float* s_ = vsrc + (size_t)(kt_) * KT2 * DM;             \
        uint32_t d_ = vdst + (uint32_t)(bf_) * (KVBUF * 4);            \
        cp16(d_,      s_,      true); cp16(d_ + 16, s_ + 4,  true);    \
        cp16(d_ + 32, s_ + 8,  true); cp16(d_ + 48, s_ + 12, true);    \
    } while (0)

    // prefetch K tile 0 while loading Q
    ISSUE_K(0, 0); CP_COMMIT;

    // ---- load Q (scaled; inputs already tf32-rounded, x0.125 exact) ----
    for (int i = tid; i < AQT * (DH / 4); i += 256) {
        int row = i >> 4, c4 = (i & 15) * 4;
        float4 qv = *(const float4*)&Q[((size_t)(b * TT + q0 + row)) * DM + h * DH + c4];
        float* qp = Qs + row * QSTR + c4;
        qp[0] = qv.x * 0.125f; qp[1] = qv.y * 0.125f;
        qp[2] = qv.z * 0.125f; qp[3] = qv.w * 0.125f;
    }

    // ---- scores: S[32][512] = Q @ K^T, streaming 64-key tiles ----
    int buf = 0;
    for (int kt = 0; kt < TT / KT2; kt++) {
        const bool more = (kt + 1 < TT / KT2);
        if (more) { ISSUE_K(buf ^ 1, kt + 1); CP_COMMIT; }
        if (more) { CP_WAIT1; } else { CP_WAIT0; }
        __syncthreads();

        const float* Kb = KV + buf * KVBUF;
        float c[2][4];
        #pragma unroll
        for (int nt = 0; nt < 2; nt++)
            #pragma unroll
            for (int r = 0; r < 4; r++) c[nt][r] = 0.0f;

        #pragma unroll
        for (int k8 = 0; k8 < DH / 8; k8++) {
            uint32_t af[4];
            const uint32_t* ab = (const uint32_t*)(Qs + (wm * 16 + g) * QSTR + k8 * 8 + tig);
            af[0] = ab[0]; af[1] = ab[8 * QSTR]; af[2] = ab[4]; af[3] = ab[8 * QSTR + 4];
            #pragma unroll
            for (int nt = 0; nt < 2; nt++) {
                const uint32_t* bb = (const uint32_t*)(Kb + (wn * 16 + nt * 8 + g) * KSTR + k8 * 8 + tig);
                uint32_t bf[2] = { bb[0], bb[4] };
                mma8(c[nt], af, bf);
            }
        }
        #pragma unroll
        for (int nt = 0; nt < 2; nt++) {
            int col = kt * KT2 + wn * 16 + nt * 8 + 2 * tig;
            float* s0 = S + (wm * 16 + g) * SSTR + col;
            float* s1 = S + (wm * 16 + g + 8) * SSTR + col;
            s0[0] = c[nt][0]; s0[1] = c[nt][1];
            s1[0] = c[nt][2]; s1[1] = c[nt][3];
        }
        __syncthreads();
        buf ^= 1;
    }

    // prefetch V tile 0 (overlaps softmax)
    ISSUE_V(0, 0); CP_COMMIT;

    // ---- softmax: warp wid owns rows [wid*4, wid*4+4) ----
    #pragma unroll
    for (int rr = 0; rr < AQT / 8; rr++) {
        int row = wid * (AQT / 8) + rr;
        float* sr = S + row * SSTR;
        float m = -1e30f;
        for (int j = lane; j < TT; j += 32) m = fmaxf(m, sr[j]);
        #pragma unroll
        for (int o = 16; o; o >>= 1) m = fmaxf(m, __shfl_xor_sync(0xFFFFFFFFu, m, o));
        float sum = 0.0f;
        for (int j = lane; j < TT; j += 32) { float ev = __expf(sr[j] - m); sr[j] = ev; sum += ev; }
        #pragma unroll
        for (int o = 16; o; o >>= 1) sum += __shfl_xor_sync(0xFFFFFFFFu, sum, o);
        float inv = 1.0f / sum;
        for (int j = lane; j < TT; j += 32) sr[j] = tfr(sr[j] * inv);
    }

    // ---- PV: O[32][64] = P @ V, streaming 64-key tiles ----
    float acc[2][4];
    #pragma unroll
    for (int nt = 0; nt < 2; nt++)
        #pragma unroll
        for (int r = 0; r < 4; r++) acc[nt][r] = 0.0f;

    buf = 0;
    for (int vt = 0; vt < TT / KT2; vt++) {
        const bool more = (vt + 1 < TT / KT2);
        if (more) { ISSUE_V(buf ^ 1, vt + 1); CP_COMMIT; }
        if (more) { CP_WAIT1; } else { CP_WAIT0; }
        __syncthreads();

        const float* Vb = KV + buf * KVBUF;
        #pragma unroll
        for (int k8 = 0; k8 < KT2 / 8; k8++) {
            uint32_t af[4];
            const uint32_t* ab = (const uint32_t*)(S + (wm * 16 + g) * SSTR + vt * KT2 + k8 * 8 + tig);
            af[0] = ab[0]; af[1] = ab[8 * SSTR]; af[2] = ab[4]; af[3] = ab[8 * SSTR + 4];
            #pragma unroll
            for (int nt = 0; nt < 2; nt++) {
                const uint32_t* bb = (const uint32_t*)(Vb + (k8 * 8 + tig) * VSTR + wn * 16 + nt * 8 + g);
                uint32_t bf[2] = { bb[0], bb[4 * VSTR] };
                mma8(acc[nt], af, bf);
            }
        }
        __syncthreads();
        buf ^= 1;
    }
#undef ISSUE_K
#undef ISSUE_V

    // epilogue: write ctx (tf32-rounded, feeds O-projection GEMM)
    #pragma unroll
    for (int nt = 0; nt < 2; nt++) {
        int col = h * DH + wn * 16 + nt * 8 + 2 * tig;
        size_t r0 = (size_t)(b * TT + q0 + wm * 16 + g) * DM + col;
        size_t r1 = (size_t)(b * TT + q0 + wm * 16 + g + 8) * DM + col;
        O[r0]     = tfr(acc[nt][0]); O[r0 + 1] = tfr(acc[nt][1]);
        O[r1]     = tfr(acc[nt][2]); O[r1 + 1] = tfr(acc[nt][3]);
    }
}

// ---------------- add + layernorm (dual output: fp32 + tf32-rounded) ----------------
__global__ __launch_bounds__(256) void add_ln_kernel(
    const float* __restrict__ x, const float* __restrict__ r,
    const float* __restrict__ g, const float* __restrict__ be,
    float* __restrict__ out, float* __restrict__ out_t)
{
    __shared__ float red[32];
    __shared__ float s_mean, s_rstd;
    int row = blockIdx.x, tid = threadIdx.x;
    const float* xp = x + (size_t)row * DM;
    const float* rp = r + (size_t)row * DM;
    float v[4]; float sum = 0.0f;
    #pragma unroll
    for (int i = 0; i < 4; i++) { int idx = tid + i * 256; v[i] = xp[idx] + rp[idx]; sum += v[i]; }
    sum = block_reduce_sum(sum, red);
    if (tid == 0) s_mean = sum * (1.0f / DM);
    __syncthreads();
    float mean = s_mean, vs = 0.0f;
    #pragma unroll
    for (int i = 0; i < 4; i++) { float dv = v[i] - mean; vs += dv * dv; }
    vs = block_reduce_sum(vs, red);
    if (tid == 0) s_rstd = rsqrtf(vs * (1.0f / DM) + EPSL);
    __syncthreads();
    float rs = s_rstd;
    #pragma unroll
    for (int i = 0; i < 4; i++) {
        int idx = tid + i * 256;
        float o = (v[i] - mean) * rs * g[idx] + be[idx];
        out[(size_t)row * DM + idx] = o;
        if (out_t) out_t[(size_t)row * DM + idx] = tfr(o);
    }
}

// ---------------- final add + layernorm over expert slots ----------------
__global__ __launch_bounds__(256) void add_ln_moe_kernel(
    const float* __restrict__ r, const float* __restrict__ g,
    const float* __restrict__ be, float* __restrict__ out)
{
    __shared__ float red[32];
    __shared__ float s_mean, s_rstd;
    int row = blockIdx.x, tid = threadIdx.x;
    const float* y0 = g_ys + (size_t)(row * 2) * DM;
    const float* y1 = y0 + DM;
    const float* rp = r + (size_t)row * DM;
    float v[4]; float sum = 0.0f;
    #pragma unroll
    for (int i = 0; i < 4; i++) {
        int idx = tid + i * 256;
        v[i] = y0[idx] + y1[idx] + rp[idx];
        sum += v[i];
    }
    sum = block_reduce_sum(sum, red);
    if (tid == 0) s_mean = sum * (1.0f / DM);
    __syncthreads();
    float mean = s_mean, vs = 0.0f;
    #pragma unroll
    for (int i = 0; i < 4; i++) { float dv = v[i] - mean; vs += dv * dv; }
    vs = block_reduce_sum(vs, red);
    if (tid == 0) s_rstd = rsqrtf(vs * (1.0f / DM) + EPSL);
    __syncthreads();
    float rs = s_rstd;
    #pragma unroll
    for (int i = 0; i < 4; i++) {
        int idx = tid + i * 256;
        out[(size_t)row * DM + idx] = (v[i] - mean) * rs * g[idx] + be[idx];
    }
}

// ---------------- router ----------------
__global__ __launch_bounds__(256) void router_kernel(
    const float* __restrict__ x, const float* __restrict__ rw,
    const float* __restrict__ rb)
{
    int t = blockIdx.x;
    int tid = threadIdx.x, lane = tid & 31, w = tid >> 5;
    __shared__ float logits[EE];
    const float* xp = x + (size_t)t * DM;
    float acc = 0.0f;
    for (int d = lane; d < DM; d += 32) acc += xp[d] * rw[d * EE + w];
    #pragma unroll
    for (int o = 16; o; o >>= 1) acc += __shfl_xor_sync(0xFFFFFFFFu, acc, o);
    if (lane == 0) logits[w] = acc + rb[w];
    __syncthreads();
    if (tid == 0) {
        float m = logits[0];
        #pragma unroll
        for (int e = 1; e < EE; e++) m = fmaxf(m, logits[e]);
        float p[EE], sum = 0.0f;
        #pragma unroll
        for (int e = 0; e < EE; e++) { p[e] = __expf(logits[e] - m); sum += p[e]; }
        float inv = 1.0f / sum;
        #pragma unroll
        for (int e = 0; e < EE; e++) { p[e] *= inv; atomicAdd(&g_imp[e], p[e]); }
        int i0 = 0;
        #pragma unroll
        for (int e = 1; e < EE; e++) if (p[e] > p[i0]) i0 = e;
        int i1 = (i0 == 0) ? 1 : 0;
        #pragma unroll
        for (int e = 0; e < EE; e++) if (e != i0 && p[e] > p[i1]) i1 = e;
        float g0 = p[i0], g1 = p[i1], gs = 1.0f / (g0 + g1);
        g0 *= gs; g1 *= gs;
        int pos = atomicAdd(&g_ecnt[i0], 1);
        g_elist[i0 * NTOK + pos] = t; g_egate[i0 * NTOK + pos] = g0;
        g_slot[i0 * NTOK + pos] = 2 * t;
        pos = atomicAdd(&g_ecnt[i1], 1);
        g_elist[i1 * NTOK + pos] = t; g_egate[i1 * NTOK + pos] = g1;
        g_slot[i1 * NTOK + pos] = 2 * t + 1;
    }
}

// ---------------- load-balance loss ----------------
__global__ void lb_kernel(float* __restrict__ out) {
    float lb = 0.0f;
    #pragma unroll
    for (int e = 0; e < EE; e++)
        lb += ((float)g_ecnt[e] / (float)(NTOK * 2)) * (g_imp[e] / (float)NTOK);
    out[0] = (float)EE * lb;
}

// ---------------- host launcher ----------------
extern "C" void kernel_launch(void* const* d_in, const int* in_sizes, int n_in,
                              void* d_out, int out_size)
{
    const float* tgt = (const float*)d_in[0];
    const float* mem = (const float*)d_in[1];
    const float *sa_wq, *sa_wk, *sa_wv, *sa_wo, *ca_wq, *ca_wk, *ca_wv, *ca_wo;
    const float *sa_bq, *sa_bk, *sa_bv, *sa_bo, *ca_bq, *ca_bk, *ca_bv, *ca_bo;
    const float *ln1g, *ln1b, *ln2g, *ln2b, *ln3g, *ln3b, *rw, *rb, *w1, *b1, *w2, *b2;

    if (in_sizes[5] == DM * DM) {
        sa_wq = (const float*)d_in[2];  sa_wk = (const float*)d_in[3];
        sa_wv = (const float*)d_in[4];  sa_wo = (const float*)d_in[5];
        ca_wq = (const float*)d_in[6];  ca_wk = (const float*)d_in[7];
        ca_wv = (const float*)d_in[8];  ca_wo = (const float*)d_in[9];
        sa_bq = (const float*)d_in[10]; sa_bk = (const float*)d_in[11];
        sa_bv = (const float*)d_in[12]; sa_bo = (const float*)d_in[13];
        ca_bq = (const float*)d_in[14]; ca_bk = (const float*)d_in[15];
        ca_bv = (const float*)d_in[16]; ca_bo = (const float*)d_in[17];
        ln1g = (const float*)d_in[18]; ln2g = (const float*)d_in[19]; ln3g = (const float*)d_in[20];
        ln1b = (const float*)d_in[21]; ln2b = (const float*)d_in[22]; ln3b = (const float*)d_in[23];
    } else {
        sa_wq = (const float*)d_in[2];  sa_wk = (const float*)d_in[3];
        sa_wv = (const float*)d_in[4];
        sa_bq = (const float*)d_in[5];  sa_bk = (const float*)d_in[6];
        sa_bv = (const float*)d_in[7];
        sa_wo = (const float*)d_in[8];  sa_bo = (const float*)d_in[9];
        ca_wq = (const float*)d_in[10]; ca_wk = (const float*)d_in[11];
        ca_wv = (const float*)d_in[12];
        ca_bq = (const float*)d_in[13]; ca_bk = (const float*)d_in[14];
        ca_bv = (const float*)d_in[15];
        ca_wo = (const float*)d_in[16]; ca_bo = (const float*)d_in[17];
        ln1g = (const float*)d_in[18]; ln1b = (const float*)d_in[19];
        ln2g = (const float*)d_in[20]; ln2b = (const float*)d_in[21];
        ln3g = (const float*)d_in[22]; ln3b = (const float*)d_in[23];
    }
    rw = (const float*)d_in[24]; rb = (const float*)d_in[25];
    w1 = (const float*)d_in[26]; b1 = (const float*)d_in[27];
    w2 = (const float*)d_in[28]; b2 = (const float*)d_in[29];

    float *wt, *q, *k, *v, *ctx, *attn, *t1, *t1t, *t2, *t2t;
    cudaGetSymbolAddress((void**)&wt,   g_wt);
    cudaGetSymbolAddress((void**)&q,    g_q);
    cudaGetSymbolAddress((void**)&k,    g_k);
    cudaGetSymbolAddress((void**)&v,    g_v);
    cudaGetSymbolAddress((void**)&ctx,  g_ctx);
    cudaGetSymbolAddress((void**)&attn, g_attn);
    cudaGetSymbolAddress((void**)&t1,   g_t1);
    cudaGetSymbolAddress((void**)&t1t,  g_t1t);
    cudaGetSymbolAddress((void**)&t2,   g_t2);
    cudaGetSymbolAddress((void**)&t2t,  g_t2t);

    const float* wt_saq = wt + 0 * PQ;
    const float* wt_sak = wt + 1 * PQ;
    const float* wt_sav = wt + 2 * PQ;
    const float* wt_sao = wt + 3 * PQ;
    const float* wt_caq = wt + 4 * PQ;
    const float* wt_cak = wt + 5 * PQ;
    const float* wt_cav = wt + 6 * PQ;
    const float* wt_cao = wt + 7 * PQ;
    const float* wt_w1  = wt + 8 * PQ;
    const float* wt_w2  = wt + 24 * PQ;
    const float* tgt_t  = wt + 40 * PQ;
    const float* mem_t  = wt + 42 * PQ;

    float* out = (float*)d_out;

    cudaFuncSetAttribute(proj_qkv_kernel,  cudaFuncAttributeMaxDynamicSharedMemorySize, GEMM_SMEM);
    cudaFuncSetAttribute(proj_qkvr_kernel, cudaFuncAttributeMaxDynamicSharedMemorySize, GEMM_SMEM);
    cudaFuncSetAttribute(moe1_kernel,      cudaFuncAttributeMaxDynamicSharedMemorySize, GEMM_SMEM);
    cudaFuncSetAttribute(moe2_kernel,      cudaFuncAttributeMaxDynamicSharedMemorySize, GEMM_SMEM);
    cudaFuncSetAttribute(attn_tc_kernel,   cudaFuncAttributeMaxDynamicSharedMemorySize, ATC_SMEM);

    dim3 gQKV(DM / BN, NTOK / BM, 3);
    dim3 gO  (DM / BN, NTOK / BM, 1);
    dim3 gAttn(TT / AQT, HH, BB);          // (16, 16, 4)
    dim3 gMoe1(FF / BN, NTOK / BM, EE);
    dim3 gMoe2(DM / BN, NTOK / BM, EE);
    dim3 gPrep(256, 12);

    zero_small_kernel<<<1, 32>>>();
    prep_kernel<<<gPrep, 256>>>(sa_wq, sa_wk, sa_wv, sa_wo, ca_wq, ca_wk, ca_wv, ca_wo,
                                w1, w2, tgt, mem);

    // ---- self attention ----
    proj_qkvr_kernel<<<gQKV, 256, GEMM_SMEM>>>(tgt_t, tgt_t, tgt_t, wt_saq, wt_sak, wt_sav,
                                               sa_bq, sa_bk, sa_bv, q, k, v, DM, DM);
    attn_tc_kernel<<<gAttn, 256, ATC_SMEM>>>(q, k, v, ctx);
    proj_qkv_kernel<<<gO, 256, GEMM_SMEM>>>(ctx, ctx, ctx, wt_sao, wt_sao, wt_sao,
                                            sa_bo, sa_bo, sa_bo, attn, attn, attn, DM, DM);
    add_ln_kernel<<<NTOK, 256>>>(attn, tgt, ln1g, ln1b, t1, t1t);

    // ---- cross attention ----
    proj_qkvr_kernel<<<gQKV, 256, GEMM_SMEM>>>(t1t, mem_t, mem_t, wt_caq, wt_cak, wt_cav,
                                               ca_bq, ca_bk, ca_bv, q, k, v, DM, DM);
    attn_tc_kernel<<<gAttn, 256, ATC_SMEM>>>(q, k, v, ctx);
    proj_qkv_kernel<<<gO, 256, GEMM_SMEM>>>(ctx, ctx, ctx, wt_cao, wt_cao, wt_cao,
                                            ca_bo, ca_bo, ca_bo, attn, attn, attn, DM, DM);
    add_ln_kernel<<<NTOK, 256>>>(attn, t1, ln2g, ln2b, t2, t2t);

    // ---- MoE (sparse top-2, slot-based scatter) ----
    router_kernel<<<NTOK, 256>>>(t2, rw, rb);
    moe1_kernel<<<gMoe1, 256, GEMM_SMEM>>>(t2t, wt_w1, b1);
    moe2_kernel<<<gMoe2, 256, GEMM_SMEM>>>(wt_w2, b2);
    add_ln_moe_kernel<<<NTOK, 256>>>(t2, ln3g, ln3b, out);

    if (out_size > NTOK * DM)
        lb_kernel<<<1, 1>>>(out + (size_t)NTOK * DM);
}

// round 8
// speedup vs baseline: 4.3114x; 1.0118x over previous
#include <cuda_runtime.h>
#include <cuda_bf16.h>
#include <math.h>
#include <stdint.h>

// ---------------- problem constants ----------------
#define BB   4
#define TT   512
#define DM   1024
#define HH   16
#define DH   64
#define FF   2048
#define EE   8
#define NTOK 2048
#define EPSL 1e-5f

// GEMM tiling
#define BM 128
#define BN 128
#define BKT 16
#define AS_STRIDE 20
#define BS_STRIDE 136
#define NSTAGE 3
#define A_ELEMS (BM * AS_STRIDE)
#define B_ELEMS (BKT * BS_STRIDE)
#define GEMM_SMEM (NSTAGE * (A_ELEMS + B_ELEMS) * 4)

// pre-converted (tf32-rounded) constant pool layout, units of floats
#define PQ 1048576ull
#define WT_TOTAL (44ull * PQ)

// ---------------- static scratch ----------------
__device__ float g_wt  [WT_TOTAL];
__device__ float g_q   [NTOK * DM];
__device__ float g_k   [NTOK * DM];
__device__ float g_v   [NTOK * DM];
__device__ float g_k2  [NTOK * DM];
__device__ float g_v2  [NTOK * DM];
__device__ float g_ctx [NTOK * DM];
__device__ float g_attn[NTOK * DM];
__device__ float g_t1  [NTOK * DM];
__device__ float g_t1t [NTOK * DM];
__device__ float g_t2  [NTOK * DM];
__device__ float g_t2t [NTOK * DM];
__device__ float g_ys  [NTOK * 2 * DM];
__device__ float g_h   [(size_t)EE * NTOK * FF];
__device__ int   g_elist[EE * NTOK];
__device__ int   g_slot [EE * NTOK];
__device__ float g_egate[EE * NTOK];
__device__ int   g_ecnt [EE];
__device__ float g_imp  [EE];

// ---------------- helpers ----------------
__device__ __forceinline__ uint32_t f2tf(float f) {
    uint32_t u;
    asm("cvt.rna.tf32.f32 %0, %1;" : "=r"(u) : "f"(f));
    return u;
}
__device__ __forceinline__ float tfr(float f) { return __uint_as_float(f2tf(f)); }

__device__ __forceinline__ void mma8(float* c, const uint32_t* a, const uint32_t* b) {
    asm volatile(
        "mma.sync.aligned.m16n8k8.row.col.f32.tf32.tf32.f32 "
        "{%0,%1,%2,%3}, {%4,%5,%6,%7}, {%8,%9}, {%0,%1,%2,%3};\n"
        : "+f"(c[0]), "+f"(c[1]), "+f"(c[2]), "+f"(c[3])
        : "r"(a[0]), "r"(a[1]), "r"(a[2]), "r"(a[3]), "r"(b[0]), "r"(b[1]));
}

__device__ __forceinline__ uint32_t smem_u32(const void* p) {
    return (uint32_t)__cvta_generic_to_shared(p);
}
__device__ __forceinline__ void cp16(uint32_t dst, const void* src, bool pred) {
    int sz = pred ? 16 : 0;
    asm volatile("cp.async.cg.shared.global [%0], [%1], 16, %2;\n"
                 :: "r"(dst), "l"(src), "r"(sz) : "memory");
}
#define CP_COMMIT  asm volatile("cp.async.commit_group;\n" ::: "memory")
#define CP_WAIT1   asm volatile("cp.async.wait_group 1;\n" ::: "memory")
#define CP_WAIT0   asm volatile("cp.async.wait_group 0;\n" ::: "memory")

__device__ __forceinline__ float block_reduce_sum(float v, float* red) {
    int lane = threadIdx.x & 31, w = threadIdx.x >> 5;
    #pragma unroll
    for (int o = 16; o; o >>= 1) v += __shfl_xor_sync(0xFFFFFFFFu, v, o);
    __syncthreads();
    if (lane == 0) red[w] = v;
    __syncthreads();
    if (w == 0) {
        v = (lane < ((int)blockDim.x >> 5)) ? red[lane] : 0.0f;
        #pragma unroll
        for (int o = 16; o; o >>= 1) v += __shfl_xor_sync(0xFFFFFFFFu, v, o);
        if (lane == 0) red[0] = v;
    }
    __syncthreads();
    return red[0];
}

// ---------------- prep: tf32-round all static operands into g_wt (+ zero init) ----------------
__global__ void prep_kernel(
    const float* s0, const float* s1, const float* s2, const float* s3,
    const float* s4, const float* s5, const float* s6, const float* s7,
    const float* s8, const float* s9, const float* s10, const float* s11)
{
    if (blockIdx.x == 0 && blockIdx.y == 0 && threadIdx.x < EE) {
        g_ecnt[threadIdx.x] = 0; g_imp[threadIdx.x] = 0.0f;
    }
    int r = blockIdx.y;
    const float* src; size_t off, cnt;
    switch (r) {
        case 0:  src = s0;  off = 0;       cnt = PQ;      break;
        case 1:  src = s1;  off = PQ;      cnt = PQ;      break;
        case 2:  src = s2;  off = 2 * PQ;  cnt = PQ;      break;
        case 3:  src = s3;  off = 3 * PQ;  cnt = PQ;      break;
        case 4:  src = s4;  off = 4 * PQ;  cnt = PQ;      break;
        case 5:  src = s5;  off = 5 * PQ;  cnt = PQ;      break;
        case 6:  src = s6;  off = 6 * PQ;  cnt = PQ;      break;
        case 7:  src = s7;  off = 7 * PQ;  cnt = PQ;      break;
        case 8:  src = s8;  off = 8 * PQ;  cnt = 16 * PQ; break;
        case 9:  src = s9;  off = 24 * PQ; cnt = 16 * PQ; break;
        case 10: src = s10; off = 40 * PQ; cnt = 2 * PQ;  break;
        default: src = s11; off = 42 * PQ; cnt = 2 * PQ;  break;
    }
    const float4* sp = (const float4*)src;
    float4* dp = (float4*)(g_wt + off);
    size_t n4 = cnt >> 2;
    for (size_t i = blockIdx.x * blockDim.x + threadIdx.x; i < n4;
         i += (size_t)gridDim.x * blockDim.x) {
        float4 v = sp[i];
        v.x = tfr(v.x); v.y = tfr(v.y); v.z = tfr(v.z); v.w = tfr(v.w);
        dp[i] = v;
    }
}

// ================= tf32 MMA GEMM core (cp.async pipelined) =================
// MODE 0: plain proj; MODE 1: moe gather+relu+round; MODE 2: moe slot-scatter;
// MODE 3: proj with tf32-rounded output
template<int MODE>
__device__ __forceinline__ void gemm_core(
    const float* __restrict__ A, const float* __restrict__ W,
    const float* __restrict__ bias, float* __restrict__ C,
    int K, int N, int row0, int col0,
    const int* atoks, const int* slots, const float* gates)
{
    extern __shared__ uint32_t smp[];
    uint32_t* As = smp;
    uint32_t* Bs = smp + NSTAGE * A_ELEMS;

    const int tid  = threadIdx.x;
    const int lane = tid & 31;
    const int wid  = tid >> 5;
    const int wm   = wid >> 2;
    const int wn   = wid & 3;
    const int g    = lane >> 2;
    const int tig  = lane & 3;

    const int lr0 = tid >> 2;
    const int akq = (tid & 3) * 4;
    bool p0 = true, p1 = true;
    const float *a0p, *a1p;
    if (MODE == 1) {
        int t0 = atoks[lr0], t1 = atoks[lr0 + 64];
        p0 = (t0 >= 0); p1 = (t1 >= 0);
        a0p = A + (size_t)(p0 ? t0 : 0) * K + akq;
        a1p = A + (size_t)(p1 ? t1 : 0) * K + akq;
    } else {
        a0p = A + (size_t)(row0 + lr0) * K + akq;
        a1p = A + (size_t)(row0 + lr0 + 64) * K + akq;
    }

    const int kr = tid >> 4;
    const int nq = (tid & 15) * 8;
    const float* bp = W + (size_t)kr * N + col0 + nq;

    uint32_t sA0 = smem_u32(As) + (lr0 * AS_STRIDE + akq) * 4;
    uint32_t sA1 = sA0 + 64 * AS_STRIDE * 4;
    uint32_t sB0 = smem_u32(Bs) + (kr * BS_STRIDE + nq) * 4;

    const int nk = K / BKT;

#define ISSUE(b, kti) do {                                     \
        uint32_t ao = (uint32_t)(b) * (A_ELEMS * 4);           \
        cp16(sA0 + ao, a0p + (kti) * BKT, p0);                 \
        cp16(sA1 + ao, a1p + (kti) * BKT, p1);                 \
        const float* bs_ = bp + (size_t)(kti) * BKT * N;       \
        uint32_t bo = (uint32_t)(b) * (B_ELEMS * 4);           \
        cp16(sB0 + bo, bs_, true);                             \
        cp16(sB0 + bo + 16, bs_ + 4, true);                    \
    } while (0)

    ISSUE(0, 0); CP_COMMIT;
    ISSUE(1, 1); CP_COMMIT;

    float acc[4][4][4];
    #pragma unroll
    for (int i = 0; i < 4; i++)
        #pragma unroll
        for (int j = 0; j < 4; j++)
            #pragma unroll
            for (int r = 0; r < 4; r++) acc[i][j][r] = 0.0f;

    int buf = 0;
    for (int kt = 0; kt < nk; kt++) {
        CP_WAIT1;
        __syncthreads();
        if (kt + 2 < nk) {
            int nb = buf + 2; if (nb >= NSTAGE) nb -= NSTAGE;
            ISSUE(nb, kt + 2);
        }
        CP_COMMIT;

        const uint32_t* Ab = As + buf * A_ELEMS;
        const uint32_t* Bb = Bs + buf * B_ELEMS;
        #pragma unroll
        for (int k8 = 0; k8 < 2; k8++) {
            uint32_t af[4][4], bf[4][2];
            const uint32_t* abase = Ab + (wm * 64 + g) * AS_STRIDE + k8 * 8 + tig;
            #pragma unroll
            for (int mt = 0; mt < 4; mt++) {
                const uint32_t* p = abase + mt * 16 * AS_STRIDE;
                af[mt][0] = p[0];
                af[mt][1] = p[8 * AS_STRIDE];
                af[mt][2] = p[4];
                af[mt][3] = p[8 * AS_STRIDE + 4];
            }
            const uint32_t* bbase = Bb + (k8 * 8 + tig) * BS_STRIDE + wn * 32 + g;
            #pragma unroll
            for (int nt = 0; nt < 4; nt++) {
                bf[nt][0] = bbase[nt * 8];
                bf[nt][1] = bbase[4 * BS_STRIDE + nt * 8];
            }
            #pragma unroll
            for (int mt = 0; mt < 4; mt++)
                #pragma unroll
                for (int nt = 0; nt < 4; nt++)
                    mma8(acc[mt][nt], af[mt], bf[nt]);
        }
        buf = (buf == NSTAGE - 1) ? 0 : buf + 1;
    }
#undef ISSUE

    #pragma unroll
    for (int mt = 0; mt < 4; mt++) {
        const int lr = wm * 64 + mt * 16 + g;
        #pragma unroll
        for (int nt = 0; nt < 4; nt++) {
            float* ac = acc[mt][nt];
            const int c = col0 + wn * 32 + nt * 8 + 2 * tig;
            const float bc0 = bias[c], bc1 = bias[c + 1];
            if (MODE == 0) {
                *(float2*)&C[(size_t)(row0 + lr) * N + c]     = make_float2(ac[0] + bc0, ac[1] + bc1);
                *(float2*)&C[(size_t)(row0 + lr + 8) * N + c] = make_float2(ac[2] + bc0, ac[3] + bc1);
            } else if (MODE == 3) {
                *(float2*)&C[(size_t)(row0 + lr) * N + c]     = make_float2(tfr(ac[0] + bc0), tfr(ac[1] + bc1));
                *(float2*)&C[(size_t)(row0 + lr + 8) * N + c] = make_float2(tfr(ac[2] + bc0), tfr(ac[3] + bc1));
            } else if (MODE == 1) {
                if (atoks[lr] >= 0)
                    *(float2*)&C[(size_t)(row0 + lr) * N + c] = make_float2(
                        tfr(fmaxf(ac[0] + bc0, 0.f)), tfr(fmaxf(ac[1] + bc1, 0.f)));
                if (atoks[lr + 8] >= 0)
                    *(float2*)&C[(size_t)(row0 + lr + 8) * N + c] = make_float2(
                        tfr(fmaxf(ac[2] + bc0, 0.f)), tfr(fmaxf(ac[3] + bc1, 0.f)));
            } else {
                int sid = slots[lr]; float gt = gates[lr];
                if (sid >= 0)
                    *(float2*)&C[(size_t)sid * DM + c] =
                        make_float2(gt * (ac[0] + bc0), gt * (ac[1] + bc1));
                sid = slots[lr + 8]; gt = gates[lr + 8];
                if (sid >= 0)
                    *(float2*)&C[(size_t)sid * DM + c] =
                        make_float2(gt * (ac[2] + bc0), gt * (ac[3] + bc1));
            }
        }
    }
}

// ---------------- GEMM wrappers ----------------
__global__ __launch_bounds__(256, 2) void proj_qkv_kernel(
    const float* A0, const float* A1, const float* A2,
    const float* W0, const float* W1, const float* W2,
    const float* b0, const float* b1, const float* b2,
    float* C0, float* C1, float* C2, int K, int N)
{
    const int z = blockIdx.z;
    const float* A = (z == 0) ? A0 : (z == 1) ? A1 : A2;
    const float* W = (z == 0) ? W0 : (z == 1) ? W1 : W2;
    const float* b = (z == 0) ? b0 : (z == 1) ? b1 : b2;
    float*       C = (z == 0) ? C0 : (z == 1) ? C1 : C2;
    gemm_core<0>(A, W, b, C, K, N, blockIdx.y * BM, blockIdx.x * BN,
                 nullptr, nullptr, nullptr);
}

__global__ __launch_bounds__(256, 2) void proj_qkvr_kernel(
    const float* A0, const float* A1, const float* A2,
    const float* W0, const float* W1, const float* W2,
    const float* b0, const float* b1, const float* b2,
    float* C0, float* C1, float* C2, int K, int N)
{
    const int z = blockIdx.z;
    const float* A = (z == 0) ? A0 : (z == 1) ? A1 : A2;
    const float* W = (z == 0) ? W0 : (z == 1) ? W1 : W2;
    const float* b = (z == 0) ? b0 : (z == 1) ? b1 : b2;
    float*       C = (z == 0) ? C0 : (z == 1) ? C1 : C2;
    gemm_core<3>(A, W, b, C, K, N, blockIdx.y * BM, blockIdx.x * BN,
                 nullptr, nullptr, nullptr);
}

// 5-way packed rounded projections (sa_q, sa_k, sa_v, ca_k, ca_v)
__global__ __launch_bounds__(256, 2) void proj_qkv5_kernel(
    const float* A0, const float* A1, const float* A2, const float* A3, const float* A4,
    const float* W0, const float* W1, const float* W2, const float* W3, const float* W4,
    const float* b0, const float* b1, const float* b2, const float* b3, const float* b4,
    float* C0, float* C1, float* C2, float* C3, float* C4, int K, int N)
{
    const int z = blockIdx.z;
    const float* A = (z == 0) ? A0 : (z == 1) ? A1 : (z == 2) ? A2 : (z == 3) ? A3 : A4;
    const float* W = (z == 0) ? W0 : (z == 1) ? W1 : (z == 2) ? W2 : (z == 3) ? W3 : W4;
    const float* b = (z == 0) ? b0 : (z == 1) ? b1 : (z == 2) ? b2 : (z == 3) ? b3 : b4;
    float*       C = (z == 0) ? C0 : (z == 1) ? C1 : (z == 2) ? C2 : (z == 3) ? C3 : C4;
    gemm_core<3>(A, W, b, C, K, N, blockIdx.y * BM, blockIdx.x * BN,
                 nullptr, nullptr, nullptr);
}

__global__ __launch_bounds__(256, 2) void moe1_kernel(
    const float* __restrict__ X, const float* __restrict__ w1,
    const float* __restrict__ b1)
{
    const int e = blockIdx.z;
    const int cnt = g_ecnt[e];
    const int row0 = blockIdx.y * BM;
    if (row0 >= cnt) return;
    __shared__ int toks[BM];
    if (threadIdx.x < BM) {
        int r = row0 + threadIdx.x;
        toks[threadIdx.x] = (r < cnt) ? g_elist[e * NTOK + r] : -1;
    }
    __syncthreads();
    gemm_core<1>(X, w1 + (size_t)e * DM * FF, b1 + e * FF,
                 g_h + (size_t)e * NTOK * FF,
                 DM, FF, row0, blockIdx.x * BN, toks, nullptr, nullptr);
}

__global__ __launch_bounds__(256, 2) void moe2_kernel(
    const float* __restrict__ w2, const float* __restrict__ b2)
{
    const int e = blockIdx.z;
    const int cnt = g_ecnt[e];
    const int row0 = blockIdx.y * BM;
    if (row0 >= cnt) return;
    __shared__ int slts[BM];
    __shared__ float gat[BM];
    if (threadIdx.x < BM) {
        int r = row0 + threadIdx.x;
        bool ok = (r < cnt);
        slts[threadIdx.x] = ok ? g_slot[e * NTOK + r] : -1;
        gat[threadIdx.x]  = ok ? g_egate[e * NTOK + r] : 0.0f;
    }
    __syncthreads();
    gemm_core<2>(g_h + (size_t)e * NTOK * FF, w2 + (size_t)e * FF * DM,
                 b2 + e * DM, g_ys,
                 FF, DM, row0, blockIdx.x * BN, nullptr, slts, gat);
}

// ---------------- tensor-core attention (512 threads, cp.async double-buffered) ----------------
// One block per (b, h, 32-q tile). 512 threads = 16 warps (2m x 8n).
// Q stored fragment-major (LDS128 per A-frag). Inputs pre-rounded to tf32.
#define AQT   32
#define KT2   64
#define KSTR  68
#define VSTR  72
#define KVBUF (KT2 * VSTR)                 // 4608 floats per buffer
#define SSTR  516
#define QF_ELEMS (2 * 8 * 32 * 4)          // 2048 u32
#define ATC_SMEM ((QF_ELEMS + 2 * KVBUF + AQT * SSTR) * 4)   // 111104 B

__global__ __launch_bounds__(512, 2) void attn_tc_kernel(
    const float* __restrict__ Q, const float* __restrict__ Kk,
    const float* __restrict__ V, float* __restrict__ O)
{
    extern __shared__ float am[];
    uint32_t* Qf = (uint32_t*)am;        // [2][8][32][4] fragment-major
    float* KV = am + QF_ELEMS;           // [2][KVBUF]
    float* S  = KV + 2 * KVBUF;          // [AQT][SSTR]

    const int q0  = blockIdx.x * AQT;
    const int h   = blockIdx.y;
    const int b   = blockIdx.z;
    const int tid = threadIdx.x;
    const int lane = tid & 31;
    const int wid  = tid >> 5;          // 0..15
    const int wm   = wid >> 3;          // 0..1
    const int wn   = wid & 7;           // 0..7
    const int g    = lane >> 2;         // 0..7
    const int tig  = lane & 3;          // 0..3

    // loader mapping: 2 cp16 (8 floats) per thread per tile
    const int lrow = tid >> 3;             // 0..63
    const int lc   = (tid & 7) * 8;        // 0..56
    const float* ksrc = Kk + ((size_t)(b * TT) + lrow) * DM + h * DH + lc;
    const float* vsrc = V  + ((size_t)(b * TT) + lrow) * DM + h * DH + lc;
    uint32_t kdst = smem_u32(KV) + (lrow * KSTR + lc) * 4;
    uint32_t vdst = smem_u32(KV) + (lrow * VSTR + lc) * 4;

#define ISSUE_K(bf_, kt_) do {                                         \
        const float* s_ = ksrc + (size_t)(kt_) * KT2 * DM;             \
        uint32_t d_ = kdst + (uint32_t)(bf_) * (KVBUF * 4);            \
        cp16(d_, s_, true); cp16(d_ + 16, s_ + 4, true);               \
    } while (0)
#define ISSUE_V(bf_, kt_) do {                                         \
        const float* s_ = vsrc + (size_t)(kt_) * KT2 * DM;             \
        uint32_t d_ = vdst + (uint32_t)(bf_) * (KVBUF * 4);            \
        cp16(d_, s_, true); cp16(d_ + 16, s_ + 4, true);               \
    } while (0)

    // prefetch K tile 0 while building Q fragments
    ISSUE_K(0, 0); CP_COMMIT;

    // ---- load Q into fragment-major layout (scaled; inputs tf32-rounded, x0.125 exact) ----
    for (int i = tid; i < QF_ELEMS; i += 512) {
        int r     = i & 3;
        int lane_ = (i >> 2) & 31;
        int k8    = (i >> 7) & 7;
        int wmf   = i >> 10;
        int gg = lane_ >> 2, tt = lane_ & 3;
        int row = q0 + wmf * 16 + gg + (r & 1) * 8;
        int col = k8 * 8 + tt + (r >> 1) * 4;
        float v = Q[((size_t)(b * TT + row)) * DM + h * DH + col] * 0.125f;
        Qf[i] = __float_as_uint(v);
    }

    // ---- scores: S[32][512] = Q @ K^T, streaming 64-key tiles ----
    int buf = 0;
    for (int kt = 0; kt < TT / KT2; kt++) {
        const bool more = (kt + 1 < TT / KT2);
        if (more) { ISSUE_K(buf ^ 1, kt + 1); CP_COMMIT; }
        if (more) { CP_WAIT1; } else { CP_WAIT0; }
        __syncthreads();

        const float* Kb = KV + buf * KVBUF;
        float c[4] = {0.f, 0.f, 0.f, 0.f};
        #pragma unroll
        for (int k8 = 0; k8 < DH / 8; k8++) {
            uint32_t af[4];
            *(uint4*)af = *(const uint4*)(Qf + ((wm * 8 + k8) * 32 + lane) * 4);
            const uint32_t* bb = (const uint32_t*)(Kb + (wn * 8 + g) * KSTR + k8 * 8 + tig);
            uint32_t bf2[2] = { bb[0], bb[4] };
            mma8(c, af, bf2);
        }
        int col = kt * KT2 + wn * 8 + 2 * tig;
        float* s0 = S + (wm * 16 + g) * SSTR + col;
        float* s1 = S + (wm * 16 + g + 8) * SSTR + col;
        s0[0] = c[0]; s0[1] = c[1];
        s1[0] = c[2]; s1[1] = c[3];
        __syncthreads();
        buf ^= 1;
    }

    // prefetch V tile 0 (overlaps softmax)
    ISSUE_V(0, 0); CP_COMMIT;

    // ---- softmax: warp wid owns rows [wid*2, wid*2+2) ----
    #pragma unroll
    for (int rr = 0; rr < 2; rr++) {
        int row = wid * 2 + rr;
        float* sr = S + row * SSTR;
        float m = -1e30f;
        for (int j = lane; j < TT; j += 32) m = fmaxf(m, sr[j]);
        #pragma unroll
        for (int o = 16; o; o >>= 1) m = fmaxf(m, __shfl_xor_sync(0xFFFFFFFFu, m, o));
        float sum = 0.0f;
        for (int j = lane; j < TT; j += 32) { float ev = __expf(sr[j] - m); sr[j] = ev; sum += ev; }
        #pragma unroll
        for (int o = 16; o; o >>= 1) sum += __shfl_xor_sync(0xFFFFFFFFu, sum, o);
        float inv = 1.0f / sum;
        for (int j = lane; j < TT; j += 32) sr[j] = tfr(sr[j] * inv);
    }

    // ---- PV: O[32][64] = P @ V, streaming 64-key tiles ----
    float acc[4] = {0.f, 0.f, 0.f, 0.f};
    buf = 0;
    for (int vt = 0; vt < TT / KT2; vt++) {
        const bool more = (vt + 1 < TT / KT2);
        if (more) { ISSUE_V(buf ^ 1, vt + 1); CP_COMMIT; }
        if (more) { CP_WAIT1; } else { CP_WAIT0; }
        __syncthreads();

        const float* Vb = KV + buf * KVBUF;
        #pragma unroll
        for (int k8 = 0; k8 < KT2 / 8; k8++) {
            uint32_t af[4];
            const uint32_t* ab = (const uint32_t*)(S + (wm * 16 + g) * SSTR + vt * KT2 + k8 * 8 + tig);
            af[0] = ab[0]; af[1] = ab[8 * SSTR]; af[2] = ab[4]; af[3] = ab[8 * SSTR + 4];
            const uint32_t* bb = (const uint32_t*)(Vb + (k8 * 8 + tig) * VSTR + wn * 8 + g);
            uint32_t bf2[2] = { bb[0], bb[4 * VSTR] };
            mma8(acc, af, bf2);
        }
        __syncthreads();
        buf ^= 1;
    }
#undef ISSUE_K
#undef ISSUE_V

    // epilogue: write ctx (tf32-rounded, feeds O-projection GEMM)
    {
        int col = h * DH + wn * 8 + 2 * tig;
        size_t r0 = (size_t)(b * TT + q0 + wm * 16 + g) * DM + col;
        size_t r1 = (size_t)(b * TT + q0 + wm * 16 + g + 8) * DM + col;
        O[r0]     = tfr(acc[0]); O[r0 + 1] = tfr(acc[1]);
        O[r1]     = tfr(acc[2]); O[r1 + 1] = tfr(acc[3]);
    }
}

// ---------------- add + layernorm (dual output: fp32 + tf32-rounded) ----------------
__global__ __launch_bounds__(256) void add_ln_kernel(
    const float* __restrict__ x, const float* __restrict__ r,
    const float* __restrict__ g, const float* __restrict__ be,
    float* __restrict__ out, float* __restrict__ out_t)
{
    __shared__ float red[32];
    __shared__ float s_mean, s_rstd;
    int row = blockIdx.x, tid = threadIdx.x;
    const float* xp = x + (size_t)row * DM;
    const float* rp = r + (size_t)row * DM;
    float v[4]; float sum = 0.0f;
    #pragma unroll
    for (int i = 0; i < 4; i++) { int idx = tid + i * 256; v[i] = xp[idx] + rp[idx]; sum += v[i]; }
    sum = block_reduce_sum(sum, red);
    if (tid == 0) s_mean = sum * (1.0f / DM);
    __syncthreads();
    float mean = s_mean, vs = 0.0f;
    #pragma unroll
    for (int i = 0; i < 4; i++) { float dv = v[i] - mean; vs += dv * dv; }
    vs = block_reduce_sum(vs, red);
    if (tid == 0) s_rstd = rsqrtf(vs * (1.0f / DM) + EPSL);
    __syncthreads();
    float rs = s_rstd;
    #pragma unroll
    for (int i = 0; i < 4; i++) {
        int idx = tid + i * 256;
        float o = (v[i] - mean) * rs * g[idx] + be[idx];
        out[(size_t)row * DM + idx] = o;
        if (out_t) out_t[(size_t)row * DM + idx] = tfr(o);
    }
}

// ---------------- final add + layernorm over expert slots ----------------
__global__ __launch_bounds__(256) void add_ln_moe_kernel(
    const float* __restrict__ r, const float* __restrict__ g,
    const float* __restrict__ be, float* __restrict__ out)
{
    __shared__ float red[32];
    __shared__ float s_mean, s_rstd;
    int row = blockIdx.x, tid = threadIdx.x;
    const float* y0 = g_ys + (size_t)(row * 2) * DM;
    const float* y1 = y0 + DM;
    const float* rp = r + (size_t)row * DM;
    float v[4]; float sum = 0.0f;
    #pragma unroll
    for (int i = 0; i < 4; i++) {
        int idx = tid + i * 256;
        v[i] = y0[idx] + y1[idx] + rp[idx];
        sum += v[i];
    }
    sum = block_reduce_sum(sum, red);
    if (tid == 0) s_mean = sum * (1.0f / DM);
    __syncthreads();
    float mean = s_mean, vs = 0.0f;
    #pragma unroll
    for (int i = 0; i < 4; i++) { float dv = v[i] - mean; vs += dv * dv; }
    vs = block_reduce_sum(vs, red);
    if (tid == 0) s_rstd = rsqrtf(vs * (1.0f / DM) + EPSL);
    __syncthreads();
    float rs = s_rstd;
    #pragma unroll
    for (int i = 0; i < 4; i++) {
        int idx = tid + i * 256;
        out[(size_t)row * DM + idx] = (v[i] - mean) * rs * g[idx] + be[idx];
    }
}

// ---------------- router ----------------
__global__ __launch_bounds__(256) void router_kernel(
    const float* __restrict__ x, const float* __restrict__ rw,
    const float* __restrict__ rb)
{
    int t = blockIdx.x;
    int tid = threadIdx.x, lane = tid & 31, w = tid >> 5;
    __shared__ float logits[EE];
    const float* xp = x + (size_t)t * DM;
    float acc = 0.0f;
    for (int d = lane; d < DM; d += 32) acc += xp[d] * rw[d * EE + w];
    #pragma unroll
    for (int o = 16; o; o >>= 1) acc += __shfl_xor_sync(0xFFFFFFFFu, acc, o);
    if (lane == 0) logits[w] = acc + rb[w];
    __syncthreads();
    if (tid == 0) {
        float m = logits[0];
        #pragma unroll
        for (int e = 1; e < EE; e++) m = fmaxf(m, logits[e]);
        float p[EE], sum = 0.0f;
        #pragma unroll
        for (int e = 0; e < EE; e++) { p[e] = __expf(logits[e] - m); sum += p[e]; }
        float inv = 1.0f / sum;
        #pragma unroll
        for (int e = 0; e < EE; e++) { p[e] *= inv; atomicAdd(&g_imp[e], p[e]); }
        int i0 = 0;
        #pragma unroll
        for (int e = 1; e < EE; e++) if (p[e] > p[i0]) i0 = e;
        int i1 = (i0 == 0) ? 1 : 0;
        #pragma unroll
        for (int e = 0; e < EE; e++) if (e != i0 && p[e] > p[i1]) i1 = e;
        float g0 = p[i0], g1 = p[i1], gs = 1.0f / (g0 + g1);
        g0 *= gs; g1 *= gs;
        int pos = atomicAdd(&g_ecnt[i0], 1);
        g_elist[i0 * NTOK + pos] = t; g_egate[i0 * NTOK + pos] = g0;
        g_slot[i0 * NTOK + pos] = 2 * t;
        pos = atomicAdd(&g_ecnt[i1], 1);
        g_elist[i1 * NTOK + pos] = t; g_egate[i1 * NTOK + pos] = g1;
        g_slot[i1 * NTOK + pos] = 2 * t + 1;
    }
}

// ---------------- load-balance loss ----------------
__global__ void lb_kernel(float* __restrict__ out) {
    float lb = 0.0f;
    #pragma unroll
    for (int e = 0; e < EE; e++)
        lb += ((float)g_ecnt[e] / (float)(NTOK * 2)) * (g_imp[e] / (float)NTOK);
    out[0] = (float)EE * lb;
}

// ---------------- host launcher ----------------
extern "C" void kernel_launch(void* const* d_in, const int* in_sizes, int n_in,
                              void* d_out, int out_size)
{
    const float* tgt = (const float*)d_in[0];
    const float* mem = (const float*)d_in[1];
    const float *sa_wq, *sa_wk, *sa_wv, *sa_wo, *ca_wq, *ca_wk, *ca_wv, *ca_wo;
    const float *sa_bq, *sa_bk, *sa_bv, *sa_bo, *ca_bq, *ca_bk, *ca_bv, *ca_bo;
    const float *ln1g, *ln1b, *ln2g, *ln2b, *ln3g, *ln3b, *rw, *rb, *w1, *b1, *w2, *b2;

    if (in_sizes[5] == DM * DM) {
        sa_wq = (const float*)d_in[2];  sa_wk = (const float*)d_in[3];
        sa_wv = (const float*)d_in[4];  sa_wo = (const float*)d_in[5];
        ca_wq = (const float*)d_in[6];  ca_wk = (const float*)d_in[7];
        ca_wv = (const float*)d_in[8];  ca_wo = (const float*)d_in[9];
        sa_bq = (const float*)d_in[10]; sa_bk = (const float*)d_in[11];
        sa_bv = (const float*)d_in[12]; sa_bo = (const float*)d_in[13];
        ca_bq = (const float*)d_in[14]; ca_bk = (const float*)d_in[15];
        ca_bv = (const float*)d_in[16]; ca_bo = (const float*)d_in[17];
        ln1g = (const float*)d_in[18]; ln2g = (const float*)d_in[19]; ln3g = (const float*)d_in[20];
        ln1b = (const float*)d_in[21]; ln2b = (const float*)d_in[22]; ln3b = (const float*)d_in[23];
    } else {
        sa_wq = (const float*)d_in[2];  sa_wk = (const float*)d_in[3];
        sa_wv = (const float*)d_in[4];
        sa_bq = (const float*)d_in[5];  sa_bk = (const float*)d_in[6];
        sa_bv = (const float*)d_in[7];
        sa_wo = (const float*)d_in[8];  sa_bo = (const float*)d_in[9];
        ca_wq = (const float*)d_in[10]; ca_wk = (const float*)d_in[11];
        ca_wv = (const float*)d_in[12];
        ca_bq = (const float*)d_in[13]; ca_bk = (const float*)d_in[14];
        ca_bv = (const float*)d_in[15];
        ca_wo = (const float*)d_in[16]; ca_bo = (const float*)d_in[17];
        ln1g = (const float*)d_in[18]; ln1b = (const float*)d_in[19];
        ln2g = (const float*)d_in[20]; ln2b = (const float*)d_in[21];
        ln3g = (const float*)d_in[22]; ln3b = (const float*)d_in[23];
    }
    rw = (const float*)d_in[24]; rb = (const float*)d_in[25];
    w1 = (const float*)d_in[26]; b1 = (const float*)d_in[27];
    w2 = (const float*)d_in[28]; b2 = (const float*)d_in[29];

    float *wt, *q, *k, *v, *k2, *v2, *ctx, *attn, *t1, *t1t, *t2, *t2t;
    cudaGetSymbolAddress((void**)&wt,   g_wt);
    cudaGetSymbolAddress((void**)&q,    g_q);
    cudaGetSymbolAddress((void**)&k,    g_k);
    cudaGetSymbolAddress((void**)&v,    g_v);
    cudaGetSymbolAddress((void**)&k2,   g_k2);
    cudaGetSymbolAddress((void**)&v2,   g_v2);
    cudaGetSymbolAddress((void**)&ctx,  g_ctx);
    cudaGetSymbolAddress((void**)&attn, g_attn);
    cudaGetSymbolAddress((void**)&t1,   g_t1);
    cudaGetSymbolAddress((void**)&t1t,  g_t1t);
    cudaGetSymbolAddress((void**)&t2,   g_t2);
    cudaGetSymbolAddress((void**)&t2t,  g_t2t);

    const float* wt_saq = wt + 0 * PQ;
    const float* wt_sak = wt + 1 * PQ;
    const float* wt_sav = wt + 2 * PQ;
    const float* wt_sao = wt + 3 * PQ;
    const float* wt_caq = wt + 4 * PQ;
    const float* wt_cak = wt + 5 * PQ;
    const float* wt_cav = wt + 6 * PQ;
    const float* wt_cao = wt + 7 * PQ;
    const float* wt_w1  = wt + 8 * PQ;
    const float* wt_w2  = wt + 24 * PQ;
    const float* tgt_t  = wt + 40 * PQ;
    const float* mem_t  = wt + 42 * PQ;

    float* out = (float*)d_out;

    cudaFuncSetAttribute(proj_qkv_kernel,  cudaFuncAttributeMaxDynamicSharedMemorySize, GEMM_SMEM);
    cudaFuncSetAttribute(proj_qkvr_kernel, cudaFuncAttributeMaxDynamicSharedMemorySize, GEMM_SMEM);
    cudaFuncSetAttribute(proj_qkv5_kernel, cudaFuncAttributeMaxDynamicSharedMemorySize, GEMM_SMEM);
    cudaFuncSetAttribute(moe1_kernel,      cudaFuncAttributeMaxDynamicSharedMemorySize, GEMM_SMEM);
    cudaFuncSetAttribute(moe2_kernel,      cudaFuncAttributeMaxDynamicSharedMemorySize, GEMM_SMEM);
    cudaFuncSetAttribute(attn_tc_kernel,   cudaFuncAttributeMaxDynamicSharedMemorySize, ATC_SMEM);

    dim3 gQKV5(DM / BN, NTOK / BM, 5);     // (8, 16, 5)
    dim3 gQ1  (DM / BN, NTOK / BM, 1);     // (8, 16, 1)
    dim3 gAttn(TT / AQT, HH, BB);          // (16, 16, 4)
    dim3 gMoe1(FF / BN, NTOK / BM, EE);
    dim3 gMoe2(DM / BN, NTOK / BM, EE);
    dim3 gPrep(256, 12);

    prep_kernel<<<gPrep, 256>>>(sa_wq, sa_wk, sa_wv, sa_wo, ca_wq, ca_wk, ca_wv, ca_wo,
                                w1, w2, tgt, mem);

    // ---- all projections that depend only on inputs: sa QKV + ca KV ----
    proj_qkv5_kernel<<<gQKV5, 256, GEMM_SMEM>>>(
        tgt_t, tgt_t, tgt_t, mem_t, mem_t,
        wt_saq, wt_sak, wt_sav, wt_cak, wt_cav,
        sa_bq, sa_bk, sa_bv, ca_bk, ca_bv,
        q, k, v, k2, v2, DM, DM);

    // ---- self attention ----
    attn_tc_kernel<<<gAttn, 512, ATC_SMEM>>>(q, k, v, ctx);
    proj_qkv_kernel<<<gQ1, 256, GEMM_SMEM>>>(ctx, ctx, ctx, wt_sao, wt_sao, wt_sao,
                                             sa_bo, sa_bo, sa_bo, attn, attn, attn, DM, DM);
    add_ln_kernel<<<NTOK, 256>>>(attn, tgt, ln1g, ln1b, t1, t1t);

    // ---- cross attention ----
    proj_qkvr_kernel<<<gQ1, 256, GEMM_SMEM>>>(t1t, t1t, t1t, wt_caq, wt_caq, wt_caq,
                                              ca_bq, ca_bq, ca_bq, q, q, q, DM, DM);
    attn_tc_kernel<<<gAttn, 512, ATC_SMEM>>>(q, k2, v2, ctx);
    proj_qkv_kernel<<<gQ1, 256, GEMM_SMEM>>>(ctx, ctx, ctx, wt_cao, wt_cao, wt_cao,
                                             ca_bo, ca_bo, ca_bo, attn, attn, attn, DM, DM);
    add_ln_kernel<<<NTOK, 256>>>(attn, t1, ln2g, ln2b, t2, t2t);

    // ---- MoE (sparse top-2, slot-based scatter) ----
    router_kernel<<<NTOK, 256>>>(t2, rw, rb);
    moe1_kernel<<<gMoe1, 256, GEMM_SMEM>>>(t2t, wt_w1, b1);
    moe2_kernel<<<gMoe2, 256, GEMM_SMEM>>>(wt_w2, b2);
    add_ln_moe_kernel<<<NTOK, 256>>>(t2, ln3g, ln3b, out);

    if (out_size > NTOK * DM)
        lb_kernel<<<1, 1>>>(out + (size_t)NTOK * DM);
}